// round 1
// baseline (speedup 1.0000x reference)
#include <cuda_runtime.h>
#include <math.h>

#define BB   4
#define N0   6000
#define HW   78
#define NPIX (HW*HW)        // 6084
#define ADDW (NPIX - N0)    // 84
#define NT   (NPIX + 1)     // 6085
#define NP   6144
#define PADT (NP - NT)      // 59
#define EMBD 512
#define NH   8
#define DH   64
#define ML   256
#define LWIN (NP/ML)        // 24
#define BH   (BB*NH)        // 32

// -------------------- scratch (device globals, no allocation) --------------------
__device__ float d_h   [(size_t)BB*NT*EMBD];
__device__ float d_xn  [(size_t)BB*NP*EMBD];
__device__ float d_qkv [(size_t)BB*NP*3*EMBD];
__device__ float d_attn[(size_t)BB*NP*EMBD];
__device__ float d_ql  [BH*ML*DH];
__device__ float d_kl  [BH*ML*DH];
__device__ float d_a2  [BH*ML*ML];
__device__ float d_z0  [BH*ML*ML];
__device__ float d_z1  [BH*ML*ML];
__device__ float d_t0  [BH*ML*ML];
__device__ float d_t1  [BH*ML*ML];
__device__ float d_t2  [BH*ML*ML];
__device__ float d_a3v [BH*ML*DH];
__device__ float d_w2  [BH*ML*DH];
__device__ float d_m3  [BH*ML];
__device__ float d_s3  [BH*ML];
__device__ float d_mx  [2];

__device__ __forceinline__ float dot64(const float* __restrict__ a, const float* __restrict__ kp) {
    float s = 0.f;
#pragma unroll
    for (int i = 0; i < 16; i++) {
        float4 x = *(const float4*)(kp + 4*i);
        s += a[4*i]*x.x + a[4*i+1]*x.y + a[4*i+2]*x.z + a[4*i+3]*x.w;
    }
    return s;
}

// -------------------- generic GEMM: C = act(A@W + bias), batched --------------------
__global__ __launch_bounds__(256) void gemm_bias_act(
    const float* __restrict__ A, const float* __restrict__ W,
    const float* __restrict__ bias, float* __restrict__ C,
    int Mrows, int N, int K, size_t strideA, size_t strideC, int act)
{
    __shared__ float As[16][64];
    __shared__ float Bs[16][64];
    A += (size_t)blockIdx.z * strideA;
    C += (size_t)blockIdx.z * strideC;
    int bm = blockIdx.y * 64, bn = blockIdx.x * 64;
    int tid = threadIdx.x;
    int la_r = tid >> 2, la_c = (tid & 3) << 2;
    int lb_r = tid >> 4, lb_c = (tid & 15) << 2;
    int ty = tid >> 4, tx = tid & 15;
    float acc[4][4];
#pragma unroll
    for (int i = 0; i < 4; i++)
#pragma unroll
        for (int j = 0; j < 4; j++) acc[i][j] = 0.f;

    for (int k0 = 0; k0 < K; k0 += 16) {
        int ar = bm + la_r;
        float4 av = make_float4(0.f, 0.f, 0.f, 0.f);
        if (ar < Mrows) av = *(const float4*)(A + (size_t)ar*K + k0 + la_c);
        As[la_c  ][la_r] = av.x;
        As[la_c+1][la_r] = av.y;
        As[la_c+2][la_r] = av.z;
        As[la_c+3][la_r] = av.w;
        float4 bv = *(const float4*)(W + (size_t)(k0+lb_r)*N + bn + lb_c);
        Bs[lb_r][lb_c  ] = bv.x;
        Bs[lb_r][lb_c+1] = bv.y;
        Bs[lb_r][lb_c+2] = bv.z;
        Bs[lb_r][lb_c+3] = bv.w;
        __syncthreads();
#pragma unroll
        for (int kk = 0; kk < 16; kk++) {
            float a0 = As[kk][ty*4+0], a1 = As[kk][ty*4+1], a2 = As[kk][ty*4+2], a3 = As[kk][ty*4+3];
            float b0 = Bs[kk][tx*4+0], b1 = Bs[kk][tx*4+1], b2 = Bs[kk][tx*4+2], b3 = Bs[kk][tx*4+3];
            acc[0][0]+=a0*b0; acc[0][1]+=a0*b1; acc[0][2]+=a0*b2; acc[0][3]+=a0*b3;
            acc[1][0]+=a1*b0; acc[1][1]+=a1*b1; acc[1][2]+=a1*b2; acc[1][3]+=a1*b3;
            acc[2][0]+=a2*b0; acc[2][1]+=a2*b1; acc[2][2]+=a2*b2; acc[2][3]+=a2*b3;
            acc[3][0]+=a3*b0; acc[3][1]+=a3*b1; acc[3][2]+=a3*b2; acc[3][3]+=a3*b3;
        }
        __syncthreads();
    }
#pragma unroll
    for (int i = 0; i < 4; i++) {
        int r = bm + ty*4 + i;
        if (r >= Mrows) continue;
#pragma unroll
        for (int j = 0; j < 4; j++) {
            int c = bn + tx*4 + j;
            float v = acc[i][j] + (bias ? bias[c] : 0.f);
            if (act == 1) v = fmaxf(v, 0.f);
            C[(size_t)r*N + c] = v;
        }
    }
}

// -------------------- batched GEMM with epilogue: C = s*(A @ (cI + e*B)) --------------------
__global__ __launch_bounds__(256) void bgemm_epi(
    const float* __restrict__ A, const float* __restrict__ Bm, float* __restrict__ C,
    int Md, int Nd, int Kd, float cI, float eB, float s)
{
    __shared__ float As[16][64];
    __shared__ float Bs[16][64];
    A  += (size_t)blockIdx.z * Md * Kd;
    Bm += (size_t)blockIdx.z * Kd * Nd;
    C  += (size_t)blockIdx.z * Md * Nd;
    int bm = blockIdx.y * 64, bn = blockIdx.x * 64;
    int tid = threadIdx.x;
    int la_r = tid >> 2, la_c = (tid & 3) << 2;
    int lb_r = tid >> 4, lb_c = (tid & 15) << 2;
    int ty = tid >> 4, tx = tid & 15;
    float acc[4][4];
#pragma unroll
    for (int i = 0; i < 4; i++)
#pragma unroll
        for (int j = 0; j < 4; j++) acc[i][j] = 0.f;

    for (int k0 = 0; k0 < Kd; k0 += 16) {
        float4 av = *(const float4*)(A + (size_t)(bm + la_r)*Kd + k0 + la_c);
        As[la_c  ][la_r] = av.x;
        As[la_c+1][la_r] = av.y;
        As[la_c+2][la_r] = av.z;
        As[la_c+3][la_r] = av.w;
        int kr = k0 + lb_r;
        float4 bv = *(const float4*)(Bm + (size_t)kr*Nd + bn + lb_c);
        float e0 = eB*bv.x, e1 = eB*bv.y, e2 = eB*bv.z, e3 = eB*bv.w;
        int col0 = bn + lb_c;
        if (kr == col0    ) e0 += cI;
        if (kr == col0 + 1) e1 += cI;
        if (kr == col0 + 2) e2 += cI;
        if (kr == col0 + 3) e3 += cI;
        Bs[lb_r][lb_c  ] = e0;
        Bs[lb_r][lb_c+1] = e1;
        Bs[lb_r][lb_c+2] = e2;
        Bs[lb_r][lb_c+3] = e3;
        __syncthreads();
#pragma unroll
        for (int kk = 0; kk < 16; kk++) {
            float a0 = As[kk][ty*4+0], a1 = As[kk][ty*4+1], a2 = As[kk][ty*4+2], a3 = As[kk][ty*4+3];
            float b0 = Bs[kk][tx*4+0], b1 = Bs[kk][tx*4+1], b2 = Bs[kk][tx*4+2], b3 = Bs[kk][tx*4+3];
            acc[0][0]+=a0*b0; acc[0][1]+=a0*b1; acc[0][2]+=a0*b2; acc[0][3]+=a0*b3;
            acc[1][0]+=a1*b0; acc[1][1]+=a1*b1; acc[1][2]+=a1*b2; acc[1][3]+=a1*b3;
            acc[2][0]+=a2*b0; acc[2][1]+=a2*b1; acc[2][2]+=a2*b2; acc[2][3]+=a2*b3;
            acc[3][0]+=a3*b0; acc[3][1]+=a3*b1; acc[3][2]+=a3*b2; acc[3][3]+=a3*b3;
        }
        __syncthreads();
    }
#pragma unroll
    for (int i = 0; i < 4; i++) {
        int r = bm + ty*4 + i;
#pragma unroll
        for (int j = 0; j < 4; j++) {
            int c = bn + tx*4 + j;
            C[(size_t)r*Nd + c] = s * acc[i][j];
        }
    }
}

// -------------------- misc small kernels --------------------
__global__ void fill_cls_k(const float* __restrict__ cls) {
    int i = blockIdx.x*256 + threadIdx.x;
    if (i < BB*EMBD) d_h[(size_t)(i/EMBD)*NT*EMBD + (i % EMBD)] = cls[i % EMBD];
}

__global__ void fill_wrap_k() {
    int i = blockIdx.x*256 + threadIdx.x;
    if (i >= BB*ADDW*EMBD) return;
    int c = i % EMBD; int r = i / EMBD; int j = r % ADDW; int b = r / ADDW;
    d_h[((size_t)(b*NT + 1 + N0 + j))*EMBD + c] = d_h[((size_t)(b*NT + 1 + j))*EMBD + c];
}

__global__ __launch_bounds__(256) void ln_pad_k(const float* __restrict__ g, const float* __restrict__ bp) {
    int row = blockIdx.x; int b = row / NP; int t = row % NP;
    int tid = threadIdx.x;
    float* out = d_xn + (size_t)row*EMBD;
    if (t < PADT) { out[tid] = 0.f; out[tid+256] = 0.f; return; }
    const float* x = d_h + ((size_t)b*NT + (t - PADT))*EMBD;
    float v0 = x[tid], v1 = x[tid+256];
    __shared__ float red[256];
    red[tid] = v0 + v1; __syncthreads();
    for (int o = 128; o > 0; o >>= 1) { if (tid < o) red[tid] += red[tid+o]; __syncthreads(); }
    float mean = red[0] * (1.f/512.f); __syncthreads();
    float e0 = v0 - mean, e1 = v1 - mean;
    red[tid] = e0*e0 + e1*e1; __syncthreads();
    for (int o = 128; o > 0; o >>= 1) { if (tid < o) red[tid] += red[tid+o]; __syncthreads(); }
    float inv = rsqrtf(red[0] * (1.f/512.f) + 1e-5f);
    out[tid]     = e0*inv*g[tid]     + bp[tid];
    out[tid+256] = e1*inv*g[tid+256] + bp[tid+256];
}

__global__ void landmarks_k() {
    int blk = blockIdx.x; int bh = blk >> 8; int i = blk & 255;
    int d = threadIdx.x;  // 64 threads
    int b = bh / NH, h = bh % NH;
    const float* base = d_qkv + ((size_t)(b*NP) + (size_t)i*LWIN)*1536 + h*64 + d;
    float sq = 0.f, sk = 0.f;
#pragma unroll
    for (int j = 0; j < LWIN; j++) { sq += base[(size_t)j*1536]; sk += base[(size_t)j*1536 + 512]; }
    d_ql[((size_t)(bh*ML + i))*DH + d] = sq * (0.125f / LWIN);   // q pre-scaled by d^-1/2
    d_kl[((size_t)(bh*ML + i))*DH + d] = sk * (1.f   / LWIN);
}

__global__ __launch_bounds__(256) void a2_k() {
    int blk = blockIdx.x; int bh = blk >> 8; int i = blk & 255;
    int tid = threadIdx.x;
    __shared__ float sq[64];
    __shared__ float red[256];
    if (tid < 64) sq[tid] = d_ql[((size_t)(bh*ML + i))*DH + tid];
    __syncthreads();
    float s = dot64(sq, d_kl + ((size_t)(bh*ML + tid))*DH);
    red[tid] = s; __syncthreads();
    for (int o = 128; o > 0; o >>= 1) { if (tid < o) red[tid] = fmaxf(red[tid], red[tid+o]); __syncthreads(); }
    float m = red[0]; __syncthreads();
    float p = expf(s - m);
    red[tid] = p; __syncthreads();
    for (int o = 128; o > 0; o >>= 1) { if (tid < o) red[tid] += red[tid+o]; __syncthreads(); }
    float Z = red[0];
    d_a2[((size_t)bh << 16) + ((size_t)i << 8) + tid] = p / Z;
}

__global__ void reset_mx_k() { d_mx[0] = 0.f; d_mx[1] = 0.f; }

__global__ __launch_bounds__(256) void a2_stats_k() {
    int bh = blockIdx.x; int tid = threadIdx.x;
    const float* a = d_a2 + ((size_t)bh << 16);
    float cs = 0.f, rs = 0.f;
    for (int i = 0; i < ML; i++) cs += a[(size_t)i*ML + tid];
    for (int j = 0; j < ML; j++) rs += a[(size_t)tid*ML + j];
    __shared__ float red[256];
    red[tid] = cs; __syncthreads();
    for (int o = 128; o > 0; o >>= 1) { if (tid < o) red[tid] = fmaxf(red[tid], red[tid+o]); __syncthreads(); }
    if (tid == 0) atomicMax((int*)&d_mx[1], __float_as_int(red[0]));
    __syncthreads();
    red[tid] = rs; __syncthreads();
    for (int o = 128; o > 0; o >>= 1) { if (tid < o) red[tid] = fmaxf(red[tid], red[tid+o]); __syncthreads(); }
    if (tid == 0) atomicMax((int*)&d_mx[0], __float_as_int(red[0]));
}

__global__ void z_init_k() {
    size_t idx = (size_t)blockIdx.x*256 + threadIdx.x;
    if (idx >= (size_t)BH*ML*ML) return;
    size_t bh = idx >> 16; size_t r = (idx >> 8) & 255; size_t c = idx & 255;
    float denom = d_mx[0] * d_mx[1];
    d_z0[idx] = d_a2[(bh << 16) + (c << 8) + r] / denom;
}

__global__ __launch_bounds__(256) void a3_stats_k() {
    int blk = blockIdx.x; int bh = blk >> 8; int i = blk & 255;
    int tid = threadIdx.x; int b = bh / NH, h = bh % NH;
    __shared__ float sq[64];
    if (tid < 64) sq[tid] = d_ql[((size_t)(bh*ML + i))*DH + tid];
    __syncthreads();
    float m = -1e30f, s = 0.f;
    for (int t = tid; t < NP; t += 256) {
        const float* kp = d_qkv + ((size_t)(b*NP + t))*1536 + 512 + h*64;
        float sc = dot64(sq, kp);
        if (sc > m) { s = s*expf(m - sc) + 1.f; m = sc; } else s += expf(sc - m);
    }
    __shared__ float sm[256], ss[256];
    sm[tid] = m; ss[tid] = s; __syncthreads();
    for (int o = 128; o > 0; o >>= 1) {
        if (tid < o) {
            float m1 = sm[tid], s1 = ss[tid], m2 = sm[tid+o], s2 = ss[tid+o];
            float M = fmaxf(m1, m2);
            sm[tid] = M; ss[tid] = s1*expf(m1 - M) + s2*expf(m2 - M);
        }
        __syncthreads();
    }
    if (tid == 0) { d_m3[bh*ML + i] = sm[0]; d_s3[bh*ML + i] = ss[0]; }
}

__global__ __launch_bounds__(256) void a3v_k() {
    int blk = blockIdx.x; int bh = blk >> 8; int i = blk & 255;
    int tid = threadIdx.x; int b = bh / NH, h = bh % NH;
    __shared__ float sq[64];
    __shared__ float pbuf[256];
    if (tid < 64) sq[tid] = d_ql[((size_t)(bh*ML + i))*DH + tid];
    float m = d_m3[bh*ML + i];
    float Zi = 1.f / d_s3[bh*ML + i];
    __syncthreads();
    int g = tid >> 6, dd = tid & 63;
    float acc = 0.f;
    for (int c0 = 0; c0 < NP; c0 += 256) {
        int t = c0 + tid;
        const float* kp = d_qkv + ((size_t)(b*NP + t))*1536 + 512 + h*64;
        pbuf[tid] = expf(dot64(sq, kp) - m);
        __syncthreads();
        const float* vb = d_qkv + ((size_t)(b*NP + c0 + (g << 6)))*1536 + 1024 + h*64 + dd;
        const float* pb = pbuf + (g << 6);
#pragma unroll 8
        for (int j = 0; j < 64; j++) acc += pb[j] * vb[(size_t)j*1536];
        __syncthreads();
    }
    pbuf[tid] = acc; __syncthreads();
    if (tid < 64)
        d_a3v[((size_t)(bh*ML + i))*DH + tid] =
            (pbuf[tid] + pbuf[tid+64] + pbuf[tid+128] + pbuf[tid+192]) * Zi;
}

#define TT 16
__global__ __launch_bounds__(256) void a1_out_k() {
    int blk = blockIdx.x;
    int bh = blk / (NP/TT);
    int t0 = (blk % (NP/TT)) * TT;
    int tid = threadIdx.x; int b = bh / NH, h = bh % NH;
    __shared__ float sq[64];
    __shared__ float pbuf[256];
    __shared__ float red[256];
    const float* klr = d_kl + ((size_t)(bh*ML + tid))*DH;
    int g = tid >> 6, dd = tid & 63;
    for (int tt = 0; tt < TT; tt++) {
        int t = t0 + tt;
        if (tid < 64) sq[tid] = d_qkv[((size_t)(b*NP + t))*1536 + h*64 + tid] * 0.125f;
        __syncthreads();
        float s = dot64(sq, klr);
        red[tid] = s; __syncthreads();
        for (int o = 128; o > 0; o >>= 1) { if (tid < o) red[tid] = fmaxf(red[tid], red[tid+o]); __syncthreads(); }
        float m = red[0]; __syncthreads();
        float p = expf(s - m);
        pbuf[tid] = p; red[tid] = p; __syncthreads();
        for (int o = 128; o > 0; o >>= 1) { if (tid < o) red[tid] += red[tid+o]; __syncthreads(); }
        float Zi = 1.f / red[0]; __syncthreads();
        const float* wb = d_w2 + ((size_t)(bh*ML + (g << 6)))*DH + dd;
        const float* pb = pbuf + (g << 6);
        float acc = 0.f;
#pragma unroll 8
        for (int j = 0; j < 64; j++) acc += pb[j] * wb[(size_t)j*DH];
        red[tid] = acc; __syncthreads();
        if (tid < 64)
            d_attn[((size_t)(b*NP + t))*EMBD + h*64 + tid] =
                (red[tid] + red[tid+64] + red[tid+128] + red[tid+192]) * Zi;
        __syncthreads();
    }
}

__global__ void conv_res_k(const float* __restrict__ w) {
    size_t idx = (size_t)blockIdx.x*256 + threadIdx.x;
    if (idx >= (size_t)BB*NH*NP*DH) return;
    int dd = idx & 63; size_t r = idx >> 6;
    int t = r % NP; r /= NP; int h = r % NH; int b = (int)(r / NH);
    float s = 0.f;
#pragma unroll
    for (int k = 0; k < 33; k++) {
        int tt = t + k - 16;
        if (tt >= 0 && tt < NP)
            s += d_qkv[((size_t)(b*NP + tt))*1536 + 1024 + h*64 + dd] * w[h*33 + k];
    }
    d_attn[((size_t)(b*NP + t))*EMBD + h*64 + dd] += s;
}

__global__ void add_res_k() {
    size_t idx = (size_t)blockIdx.x*256 + threadIdx.x;
    if (idx >= (size_t)BB*NT*EMBD) return;
    int c = idx % EMBD; size_t r = idx / EMBD; int t = r % NT; int b = (int)(r / NT);
    d_h[idx] += d_xn[((size_t)(b*NP + t + PADT))*EMBD + c];
}

__global__ __launch_bounds__(256) void ppeg_k(
    const float* __restrict__ w7, const float* __restrict__ b7,
    const float* __restrict__ w5, const float* __restrict__ b5,
    const float* __restrict__ w3, const float* __restrict__ b3)
{
    int blk = blockIdx.x; int b = blk / NPIX; int pix = blk % NPIX;
    int i = pix / HW, j = pix % HW;
    int tid = threadIdx.x;
    for (int c = tid; c < EMBD; c += 256) {
        float s = d_h[((size_t)(b*NT + 1 + pix))*EMBD + c] + b7[c] + b5[c] + b3[c];
#pragma unroll
        for (int a = 0; a < 7; a++) {
            int ii = i - 3 + a; if (ii < 0 || ii >= HW) continue;
#pragma unroll
            for (int q = 0; q < 7; q++) {
                int jj = j - 3 + q; if (jj < 0 || jj >= HW) continue;
                s += d_h[((size_t)(b*NT + 1 + ii*HW + jj))*EMBD + c] * w7[c*49 + a*7 + q];
            }
        }
#pragma unroll
        for (int a = 0; a < 5; a++) {
            int ii = i - 2 + a; if (ii < 0 || ii >= HW) continue;
#pragma unroll
            for (int q = 0; q < 5; q++) {
                int jj = j - 2 + q; if (jj < 0 || jj >= HW) continue;
                s += d_h[((size_t)(b*NT + 1 + ii*HW + jj))*EMBD + c] * w5[c*25 + a*5 + q];
            }
        }
#pragma unroll
        for (int a = 0; a < 3; a++) {
            int ii = i - 1 + a; if (ii < 0 || ii >= HW) continue;
#pragma unroll
            for (int q = 0; q < 3; q++) {
                int jj = j - 1 + q; if (jj < 0 || jj >= HW) continue;
                s += d_h[((size_t)(b*NT + 1 + ii*HW + jj))*EMBD + c] * w3[c*9 + a*3 + q];
            }
        }
        d_xn[((size_t)(b*NPIX + pix))*EMBD + c] = s;
    }
}

__global__ void ppeg_copy_k() {
    size_t idx = (size_t)blockIdx.x*256 + threadIdx.x;
    if (idx >= (size_t)BB*NPIX*EMBD) return;
    int c = idx % EMBD; size_t r = idx / EMBD; int pix = r % NPIX; int b = (int)(r / NPIX);
    d_h[((size_t)(b*NT + 1 + pix))*EMBD + c] = d_xn[idx];
}

__global__ __launch_bounds__(256) void head_k(
    const float* __restrict__ g, const float* __restrict__ bp,
    const float* __restrict__ w, const float* __restrict__ bias, float* __restrict__ out)
{
    int b = blockIdx.x; int tid = threadIdx.x;
    __shared__ float xs[512];
    __shared__ float red[256];
    __shared__ float lg[4];
    const float* x = d_h + (size_t)b*NT*EMBD;
    float v0 = x[tid], v1 = x[tid+256];
    red[tid] = v0 + v1; __syncthreads();
    for (int o = 128; o > 0; o >>= 1) { if (tid < o) red[tid] += red[tid+o]; __syncthreads(); }
    float mean = red[0] * (1.f/512.f); __syncthreads();
    float e0 = v0 - mean, e1 = v1 - mean;
    red[tid] = e0*e0 + e1*e1; __syncthreads();
    for (int o = 128; o > 0; o >>= 1) { if (tid < o) red[tid] += red[tid+o]; __syncthreads(); }
    float inv = rsqrtf(red[0] * (1.f/512.f) + 1e-5f);
    xs[tid]     = e0*inv*g[tid]     + bp[tid];
    xs[tid+256] = e1*inv*g[tid+256] + bp[tid+256];
    __syncthreads();
    if (tid < 4) {
        float s = bias[tid];
        for (int k = 0; k < 512; k++) s += xs[k]*w[k*4 + tid];
        lg[tid] = s;
    }
    __syncthreads();
    if (tid == 0) {
        int best = 0; float bv = lg[0];
        for (int k = 1; k < 4; k++) if (lg[k] > bv) { bv = lg[k]; best = k; }
        float S = 1.f;
        for (int k = 0; k < 4; k++) {
            float hz = 1.f / (1.f + expf(-lg[k]));
            out[b*4 + k] = hz;
            S *= (1.f - hz);
            out[16 + b*4 + k] = S;
        }
        out[32 + b] = (float)best;
    }
}

// -------------------- host orchestration --------------------
static float* symaddr(const void* sym) { void* p = nullptr; cudaGetSymbolAddress(&p, sym); return (float*)p; }

static void attn_layer(const float* lng, const float* lnb, const float* qkvw,
                       const float* outw, const float* outb, const float* resw)
{
    float* hp    = symaddr(d_h);
    float* xnp   = symaddr(d_xn);
    float* qkvp  = symaddr(d_qkv);
    float* attnp = symaddr(d_attn);
    float* a2p   = symaddr(d_a2);
    float* z0p   = symaddr(d_z0);
    float* z1p   = symaddr(d_z1);
    float* t0p   = symaddr(d_t0);
    float* t1p   = symaddr(d_t1);
    float* t2p   = symaddr(d_t2);
    float* a3vp  = symaddr(d_a3v);
    float* w2p   = symaddr(d_w2);
    (void)hp;

    ln_pad_k<<<BB*NP, 256>>>(lng, lnb);
    gemm_bias_act<<<dim3(1536/64, NP/64, BB), 256>>>(
        xnp, qkvw, nullptr, qkvp, NP, 1536, EMBD, (size_t)NP*EMBD, (size_t)NP*1536, 0);
    landmarks_k<<<BH*ML, 64>>>();
    a2_k<<<BH*ML, 256>>>();
    reset_mx_k<<<1, 1>>>();
    a2_stats_k<<<BH, 256>>>();
    z_init_k<<<(BH*ML*ML + 255)/256, 256>>>();

    float* zin = z0p; float* zout = z1p;
    for (int it = 0; it < 6; it++) {
        bgemm_epi<<<dim3(4, 4, BH), 256>>>(a2p, zin, t0p, 256, 256, 256, 0.f,  1.f, 1.f);
        bgemm_epi<<<dim3(4, 4, BH), 256>>>(t0p, t0p, t1p, 256, 256, 256, 7.f, -1.f, 1.f);
        bgemm_epi<<<dim3(4, 4, BH), 256>>>(t0p, t1p, t2p, 256, 256, 256, 15.f,-1.f, 1.f);
        bgemm_epi<<<dim3(4, 4, BH), 256>>>(zin, t2p, zout,256, 256, 256, 13.f,-1.f, 0.25f);
        float* tmp = zin; zin = zout; zout = tmp;
    }
    // zin now holds a2_inv (6 swaps -> back to d_z0)

    a3_stats_k<<<BH*ML, 256>>>();
    a3v_k<<<BH*ML, 256>>>();
    bgemm_epi<<<dim3(1, 4, BH), 256>>>(zin, a3vp, w2p, 256, 64, 256, 0.f, 1.f, 1.f);
    a1_out_k<<<BH*(NP/TT), 256>>>();
    conv_res_k<<<(int)(((size_t)BB*NH*NP*DH + 255)/256), 256>>>(resw);
    gemm_bias_act<<<dim3(EMBD/64, NP/64, BB), 256>>>(
        attnp, outw, outb, xnp, NP, EMBD, EMBD, (size_t)NP*EMBD, (size_t)NP*EMBD, 0);
    add_res_k<<<(int)(((size_t)BB*NT*EMBD + 255)/256), 256>>>();
}

extern "C" void kernel_launch(void* const* d_in, const int* in_sizes, int n_in,
                              void* d_out, int out_size)
{
    (void)in_sizes; (void)n_in; (void)out_size;
    const float* x_path = (const float*)d_in[0];
    const float* fc1_w  = (const float*)d_in[1];
    const float* fc1_b  = (const float*)d_in[2];
    const float* cls    = (const float*)d_in[3];
    const float* ln1g   = (const float*)d_in[4];
    const float* ln1b   = (const float*)d_in[5];
    const float* qkv1w  = (const float*)d_in[6];
    const float* out1w  = (const float*)d_in[7];
    const float* out1b  = (const float*)d_in[8];
    const float* res1w  = (const float*)d_in[9];
    const float* ln2g   = (const float*)d_in[10];
    const float* ln2b   = (const float*)d_in[11];
    const float* qkv2w  = (const float*)d_in[12];
    const float* out2w  = (const float*)d_in[13];
    const float* out2b  = (const float*)d_in[14];
    const float* res2w  = (const float*)d_in[15];
    const float* c7w    = (const float*)d_in[16];
    const float* c7b    = (const float*)d_in[17];
    const float* c5w    = (const float*)d_in[18];
    const float* c5b    = (const float*)d_in[19];
    const float* c3w    = (const float*)d_in[20];
    const float* c3b    = (const float*)d_in[21];
    const float* ng     = (const float*)d_in[22];
    const float* nb     = (const float*)d_in[23];
    const float* fc2w   = (const float*)d_in[24];
    const float* fc2b   = (const float*)d_in[25];
    float* out = (float*)d_out;

    float* hp = symaddr(d_h);

    // fc1 + relu -> tokens 1..6000 of d_h (per batch)
    gemm_bias_act<<<dim3(EMBD/64, (N0 + 63)/64, BB), 256>>>(
        x_path, fc1_w, fc1_b, hp + EMBD, N0, EMBD, 1024,
        (size_t)N0*1024, (size_t)NT*EMBD, 1);
    fill_cls_k<<<(BB*EMBD + 255)/256, 256>>>(cls);
    fill_wrap_k<<<(BB*ADDW*EMBD + 255)/256, 256>>>();

    // layer 1 attention
    attn_layer(ln1g, ln1b, qkv1w, out1w, out1b, res1w);

    // PPEG
    ppeg_k<<<BB*NPIX, 256>>>(c7w, c7b, c5w, c5b, c3w, c3b);
    ppeg_copy_k<<<(int)(((size_t)BB*NPIX*EMBD + 255)/256), 256>>>();

    // layer 2 attention
    attn_layer(ln2g, ln2b, qkv2w, out2w, out2b, res2w);

    // head: layernorm(token0) @ fc2 -> hazards, S, Y_hat
    head_k<<<BB, 256>>>(ng, nb, fc2w, fc2b, out);
}

// round 2
// speedup vs baseline: 1.2930x; 1.2930x over previous
#include <cuda_runtime.h>
#include <math.h>

#define BB   4
#define N0   6000
#define HW   78
#define NPIX (HW*HW)        // 6084
#define ADDW (NPIX - N0)    // 84
#define NT   (NPIX + 1)     // 6085
#define NP   6144
#define PADT (NP - NT)      // 59
#define EMBD 512
#define NH   8
#define DH   64
#define ML   256
#define LWIN (NP/ML)        // 24
#define BH   (BB*NH)        // 32

// -------------------- scratch (device globals, no allocation) --------------------
__device__ float d_h   [(size_t)BB*NT*EMBD];
__device__ float d_xn  [(size_t)BB*NP*EMBD];
__device__ float d_qkv [(size_t)BB*NP*3*EMBD];
__device__ float d_attn[(size_t)BB*NP*EMBD];
__device__ float d_ql  [BH*ML*DH];
__device__ float d_kl  [BH*ML*DH];
__device__ float d_a2  [BH*ML*ML];
__device__ float d_z0  [BH*ML*ML];
__device__ float d_z1  [BH*ML*ML];
__device__ float d_t0  [BH*ML*ML];
__device__ float d_t1  [BH*ML*ML];
__device__ float d_t2  [BH*ML*ML];
__device__ float d_a3v [BH*ML*DH];
__device__ float d_w2  [BH*ML*DH];
__device__ float d_mx  [2];

__device__ __forceinline__ float dot64(const float* __restrict__ a, const float* __restrict__ kp) {
    float s = 0.f;
#pragma unroll
    for (int i = 0; i < 16; i++) {
        float4 x = *(const float4*)(kp + 4*i);
        s += a[4*i]*x.x + a[4*i+1]*x.y + a[4*i+2]*x.z + a[4*i+3]*x.w;
    }
    return s;
}

// ==================== 128x128x8 double-buffered SGEMM ====================
// C = sc * ( A @ (cI*I + eB*B) ) + bias, optional relu.
// Requires: N multiple of 128, K multiple of 8. M arbitrary (row guards).
__global__ __launch_bounds__(256) void sgemm_k(
    const float* __restrict__ A, const float* __restrict__ B,
    const float* __restrict__ bias, float* __restrict__ C,
    int M, int N, int K, size_t sA, size_t sB, size_t sC,
    float cI, float eB, float sc, int act)
{
    __shared__ float As[2][8][132];
    __shared__ float Bs[2][8][132];
    A += (size_t)blockIdx.z * sA;
    B += (size_t)blockIdx.z * sB;
    C += (size_t)blockIdx.z * sC;
    int bm = blockIdx.y * 128, bn = blockIdx.x * 128;
    int tid = threadIdx.x;
    int arow = tid >> 1, acol = (tid & 1) << 2;     // A tile: 128 x 8
    int brow = tid >> 5, bcol = (tid & 31) << 2;    // B tile: 8 x 128
    int ty = tid >> 4, tx = tid & 15;

    float acc[8][8];
#pragma unroll
    for (int i = 0; i < 8; i++)
#pragma unroll
        for (int j = 0; j < 8; j++) acc[i][j] = 0.f;

    int nk = K >> 3;
    int col0 = bn + bcol;

    // prologue: tile 0 -> buf 0
    {
        int r = bm + arow;
        float4 va = make_float4(0.f,0.f,0.f,0.f);
        if (r < M) va = *(const float4*)(A + (size_t)r*K + acol);
        As[0][acol+0][arow] = va.x;
        As[0][acol+1][arow] = va.y;
        As[0][acol+2][arow] = va.z;
        As[0][acol+3][arow] = va.w;
        float4 vb = *(const float4*)(B + (size_t)brow*N + col0);
        float e0 = eB*vb.x, e1 = eB*vb.y, e2 = eB*vb.z, e3 = eB*vb.w;
        if (brow == col0    ) e0 += cI;
        if (brow == col0 + 1) e1 += cI;
        if (brow == col0 + 2) e2 += cI;
        if (brow == col0 + 3) e3 += cI;
        Bs[0][brow][bcol  ] = e0;
        Bs[0][brow][bcol+1] = e1;
        Bs[0][brow][bcol+2] = e2;
        Bs[0][brow][bcol+3] = e3;
    }
    __syncthreads();

    int buf = 0;
    for (int kt = 0; kt < nk; kt++) {
        float4 va, vb;
        bool pf = (kt + 1 < nk);
        if (pf) {
            int k0 = (kt + 1) << 3;
            int r = bm + arow;
            va = make_float4(0.f,0.f,0.f,0.f);
            if (r < M) va = *(const float4*)(A + (size_t)r*K + k0 + acol);
            vb = *(const float4*)(B + (size_t)(k0 + brow)*N + col0);
        }
#pragma unroll
        for (int kk = 0; kk < 8; kk++) {
            float4 a0 = *(const float4*)&As[buf][kk][ty*8];
            float4 a1 = *(const float4*)&As[buf][kk][ty*8 + 4];
            float4 b0 = *(const float4*)&Bs[buf][kk][tx*8];
            float4 b1 = *(const float4*)&Bs[buf][kk][tx*8 + 4];
            float ar[8] = {a0.x,a0.y,a0.z,a0.w,a1.x,a1.y,a1.z,a1.w};
            float br[8] = {b0.x,b0.y,b0.z,b0.w,b1.x,b1.y,b1.z,b1.w};
#pragma unroll
            for (int i = 0; i < 8; i++)
#pragma unroll
                for (int j = 0; j < 8; j++) acc[i][j] += ar[i]*br[j];
        }
        if (pf) {
            int nb = buf ^ 1;
            int kr = ((kt + 1) << 3) + brow;
            As[nb][acol+0][arow] = va.x;
            As[nb][acol+1][arow] = va.y;
            As[nb][acol+2][arow] = va.z;
            As[nb][acol+3][arow] = va.w;
            float e0 = eB*vb.x, e1 = eB*vb.y, e2 = eB*vb.z, e3 = eB*vb.w;
            if (kr == col0    ) e0 += cI;
            if (kr == col0 + 1) e1 += cI;
            if (kr == col0 + 2) e2 += cI;
            if (kr == col0 + 3) e3 += cI;
            Bs[nb][brow][bcol  ] = e0;
            Bs[nb][brow][bcol+1] = e1;
            Bs[nb][brow][bcol+2] = e2;
            Bs[nb][brow][bcol+3] = e3;
        }
        __syncthreads();
        buf ^= 1;
    }

    float bj[8];
#pragma unroll
    for (int j = 0; j < 8; j++) bj[j] = bias ? bias[bn + tx*8 + j] : 0.f;
#pragma unroll
    for (int i = 0; i < 8; i++) {
        int r = bm + ty*8 + i;
        if (r >= M) continue;
        float* Crow = C + (size_t)r*N + bn + tx*8;
#pragma unroll
        for (int j0 = 0; j0 < 8; j0 += 4) {
            float4 v;
            v.x = sc*acc[i][j0+0] + bj[j0+0];
            v.y = sc*acc[i][j0+1] + bj[j0+1];
            v.z = sc*acc[i][j0+2] + bj[j0+2];
            v.w = sc*acc[i][j0+3] + bj[j0+3];
            if (act == 1) {
                v.x = fmaxf(v.x, 0.f); v.y = fmaxf(v.y, 0.f);
                v.z = fmaxf(v.z, 0.f); v.w = fmaxf(v.w, 0.f);
            }
            *(float4*)(Crow + j0) = v;
        }
    }
}

// -------------------- small 64-tile batched GEMM (for N=64 case) --------------------
__global__ __launch_bounds__(256) void bgemm_epi(
    const float* __restrict__ A, const float* __restrict__ Bm, float* __restrict__ C,
    int Md, int Nd, int Kd, float cI, float eB, float s)
{
    __shared__ float As[16][64];
    __shared__ float Bs[16][64];
    A  += (size_t)blockIdx.z * Md * Kd;
    Bm += (size_t)blockIdx.z * Kd * Nd;
    C  += (size_t)blockIdx.z * Md * Nd;
    int bm = blockIdx.y * 64, bn = blockIdx.x * 64;
    int tid = threadIdx.x;
    int la_r = tid >> 2, la_c = (tid & 3) << 2;
    int lb_r = tid >> 4, lb_c = (tid & 15) << 2;
    int ty = tid >> 4, tx = tid & 15;
    float acc[4][4];
#pragma unroll
    for (int i = 0; i < 4; i++)
#pragma unroll
        for (int j = 0; j < 4; j++) acc[i][j] = 0.f;

    for (int k0 = 0; k0 < Kd; k0 += 16) {
        float4 av = *(const float4*)(A + (size_t)(bm + la_r)*Kd + k0 + la_c);
        As[la_c  ][la_r] = av.x;
        As[la_c+1][la_r] = av.y;
        As[la_c+2][la_r] = av.z;
        As[la_c+3][la_r] = av.w;
        int kr = k0 + lb_r;
        float4 bv = *(const float4*)(Bm + (size_t)kr*Nd + bn + lb_c);
        float e0 = eB*bv.x, e1 = eB*bv.y, e2 = eB*bv.z, e3 = eB*bv.w;
        int c0 = bn + lb_c;
        if (kr == c0    ) e0 += cI;
        if (kr == c0 + 1) e1 += cI;
        if (kr == c0 + 2) e2 += cI;
        if (kr == c0 + 3) e3 += cI;
        Bs[lb_r][lb_c  ] = e0;
        Bs[lb_r][lb_c+1] = e1;
        Bs[lb_r][lb_c+2] = e2;
        Bs[lb_r][lb_c+3] = e3;
        __syncthreads();
#pragma unroll
        for (int kk = 0; kk < 16; kk++) {
            float a0 = As[kk][ty*4+0], a1 = As[kk][ty*4+1], a2 = As[kk][ty*4+2], a3 = As[kk][ty*4+3];
            float b0 = Bs[kk][tx*4+0], b1 = Bs[kk][tx*4+1], b2 = Bs[kk][tx*4+2], b3 = Bs[kk][tx*4+3];
            acc[0][0]+=a0*b0; acc[0][1]+=a0*b1; acc[0][2]+=a0*b2; acc[0][3]+=a0*b3;
            acc[1][0]+=a1*b0; acc[1][1]+=a1*b1; acc[1][2]+=a1*b2; acc[1][3]+=a1*b3;
            acc[2][0]+=a2*b0; acc[2][1]+=a2*b1; acc[2][2]+=a2*b2; acc[2][3]+=a2*b3;
            acc[3][0]+=a3*b0; acc[3][1]+=a3*b1; acc[3][2]+=a3*b2; acc[3][3]+=a3*b3;
        }
        __syncthreads();
    }
#pragma unroll
    for (int i = 0; i < 4; i++) {
        int r = bm + ty*4 + i;
#pragma unroll
        for (int j = 0; j < 4; j++) {
            int c = bn + tx*4 + j;
            C[(size_t)r*Nd + c] = s * acc[i][j];
        }
    }
}

// -------------------- misc small kernels --------------------
__global__ void fill_cls_k(const float* __restrict__ cls) {
    int i = blockIdx.x*256 + threadIdx.x;
    if (i < BB*EMBD) d_h[(size_t)(i/EMBD)*NT*EMBD + (i % EMBD)] = cls[i % EMBD];
}

__global__ void fill_wrap_k() {
    int i = blockIdx.x*256 + threadIdx.x;
    if (i >= BB*ADDW*EMBD) return;
    int c = i % EMBD; int r = i / EMBD; int j = r % ADDW; int b = r / ADDW;
    d_h[((size_t)(b*NT + 1 + N0 + j))*EMBD + c] = d_h[((size_t)(b*NT + 1 + j))*EMBD + c];
}

__global__ __launch_bounds__(256) void ln_pad_k(const float* __restrict__ g, const float* __restrict__ bp) {
    int row = blockIdx.x; int b = row / NP; int t = row % NP;
    int tid = threadIdx.x;
    float* out = d_xn + (size_t)row*EMBD;
    if (t < PADT) { out[tid] = 0.f; out[tid+256] = 0.f; return; }
    const float* x = d_h + ((size_t)b*NT + (t - PADT))*EMBD;
    float v0 = x[tid], v1 = x[tid+256];
    __shared__ float red[256];
    red[tid] = v0 + v1; __syncthreads();
    for (int o = 128; o > 0; o >>= 1) { if (tid < o) red[tid] += red[tid+o]; __syncthreads(); }
    float mean = red[0] * (1.f/512.f); __syncthreads();
    float e0 = v0 - mean, e1 = v1 - mean;
    red[tid] = e0*e0 + e1*e1; __syncthreads();
    for (int o = 128; o > 0; o >>= 1) { if (tid < o) red[tid] += red[tid+o]; __syncthreads(); }
    float inv = rsqrtf(red[0] * (1.f/512.f) + 1e-5f);
    out[tid]     = e0*inv*g[tid]     + bp[tid];
    out[tid+256] = e1*inv*g[tid+256] + bp[tid+256];
}

__global__ void landmarks_k() {
    int blk = blockIdx.x; int bh = blk >> 8; int i = blk & 255;
    int d = threadIdx.x;  // 64 threads
    int b = bh / NH, h = bh % NH;
    const float* base = d_qkv + ((size_t)(b*NP) + (size_t)i*LWIN)*1536 + h*64 + d;
    float sq = 0.f, sk = 0.f;
#pragma unroll
    for (int j = 0; j < LWIN; j++) { sq += base[(size_t)j*1536]; sk += base[(size_t)j*1536 + 512]; }
    d_ql[((size_t)(bh*ML + i))*DH + d] = sq * (0.125f / LWIN);   // q pre-scaled by d^-1/2
    d_kl[((size_t)(bh*ML + i))*DH + d] = sk * (1.f   / LWIN);
}

__global__ __launch_bounds__(256) void a2_k() {
    int blk = blockIdx.x; int bh = blk >> 8; int i = blk & 255;
    int tid = threadIdx.x;
    __shared__ float sq[64];
    __shared__ float red[256];
    if (tid < 64) sq[tid] = d_ql[((size_t)(bh*ML + i))*DH + tid];
    __syncthreads();
    float s = dot64(sq, d_kl + ((size_t)(bh*ML + tid))*DH);
    red[tid] = s; __syncthreads();
    for (int o = 128; o > 0; o >>= 1) { if (tid < o) red[tid] = fmaxf(red[tid], red[tid+o]); __syncthreads(); }
    float m = red[0]; __syncthreads();
    float p = expf(s - m);
    red[tid] = p; __syncthreads();
    for (int o = 128; o > 0; o >>= 1) { if (tid < o) red[tid] += red[tid+o]; __syncthreads(); }
    float Z = red[0];
    d_a2[((size_t)bh << 16) + ((size_t)i << 8) + tid] = p / Z;
}

__global__ void reset_mx_k() { d_mx[0] = 0.f; d_mx[1] = 0.f; }

__global__ __launch_bounds__(256) void a2_stats_k() {
    int bh = blockIdx.x; int tid = threadIdx.x;
    const float* a = d_a2 + ((size_t)bh << 16);
    float cs = 0.f, rs = 0.f;
    for (int i = 0; i < ML; i++) cs += a[(size_t)i*ML + tid];
    for (int j = 0; j < ML; j++) rs += a[(size_t)tid*ML + j];
    __shared__ float red[256];
    red[tid] = cs; __syncthreads();
    for (int o = 128; o > 0; o >>= 1) { if (tid < o) red[tid] = fmaxf(red[tid], red[tid+o]); __syncthreads(); }
    if (tid == 0) atomicMax((int*)&d_mx[1], __float_as_int(red[0]));
    __syncthreads();
    red[tid] = rs; __syncthreads();
    for (int o = 128; o > 0; o >>= 1) { if (tid < o) red[tid] = fmaxf(red[tid], red[tid+o]); __syncthreads(); }
    if (tid == 0) atomicMax((int*)&d_mx[0], __float_as_int(red[0]));
}

__global__ void z_init_k() {
    size_t idx = (size_t)blockIdx.x*256 + threadIdx.x;
    if (idx >= (size_t)BH*ML*ML) return;
    size_t bh = idx >> 16; size_t r = (idx >> 8) & 255; size_t c = idx & 255;
    float denom = d_mx[0] * d_mx[1];
    d_z0[idx] = d_a2[(bh << 16) + (c << 8) + r] / denom;
}

// -------------------- fused a3 @ v with online softmax (flash-style) --------------------
__global__ __launch_bounds__(256) void a3v_flash_k() {
    int blk = blockIdx.x; int bh = blk >> 8; int i = blk & 255;
    int tid = threadIdx.x; int b = bh / NH, h = bh % NH;
    __shared__ float sq[64];
    __shared__ float pbuf[256];
    __shared__ float red[256];
    if (tid < 64) sq[tid] = d_ql[((size_t)(bh*ML + i))*DH + tid];
    __syncthreads();
    int g = tid >> 6, dd = tid & 63;
    float m = -1e30f, s = 0.f, acc = 0.f;
    for (int c0 = 0; c0 < NP; c0 += 256) {
        const float* kp = d_qkv + ((size_t)(b*NP + c0 + tid))*1536 + 512 + h*64;
        float scv = dot64(sq, kp);
        red[tid] = scv; __syncthreads();
        for (int o = 128; o > 0; o >>= 1) { if (tid < o) red[tid] = fmaxf(red[tid], red[tid+o]); __syncthreads(); }
        float cm = red[0]; __syncthreads();
        float newm = fmaxf(m, cm);
        float f = expf(m - newm);
        float p = expf(scv - newm);
        pbuf[tid] = p; red[tid] = p; __syncthreads();
        for (int o = 128; o > 0; o >>= 1) { if (tid < o) red[tid] += red[tid+o]; __syncthreads(); }
        float ps = red[0]; __syncthreads();
        s = s*f + ps; m = newm;
        acc *= f;
        const float* vb = d_qkv + ((size_t)(b*NP + c0 + (g << 6)))*1536 + 1024 + h*64 + dd;
        const float* pb = pbuf + (g << 6);
#pragma unroll 8
        for (int j = 0; j < 64; j++) acc += pb[j] * vb[(size_t)j*1536];
    }
    __syncthreads();
    pbuf[tid] = acc; __syncthreads();
    if (tid < 64)
        d_a3v[((size_t)(bh*ML + i))*DH + tid] =
            (pbuf[tid] + pbuf[tid+64] + pbuf[tid+128] + pbuf[tid+192]) / s;
}

// -------------------- a1 softmax @ w2: one warp per token --------------------
#define TPB 8   // tokens per block = warps per block
__global__ __launch_bounds__(256) void a1_out_k() {
    int blk = blockIdx.x;
    int bh = blk / (NP/TPB);
    int t0 = (blk % (NP/TPB)) * TPB;
    int tid = threadIdx.x;
    int wid = tid >> 5, lane = tid & 31;
    int b = bh / NH, h = bh % NH;
    int t = t0 + wid;
    __shared__ float qsh[TPB][64];
    __shared__ float psh[TPB][256];
    const float* qp = d_qkv + ((size_t)(b*NP + t))*1536 + h*64;
    qsh[wid][lane]      = qp[lane]      * 0.125f;
    qsh[wid][lane + 32] = qp[lane + 32] * 0.125f;
    __syncwarp();
    float scv[8];
#pragma unroll
    for (int j = 0; j < 8; j++) {
        int l = j*32 + lane;
        scv[j] = dot64(qsh[wid], d_kl + ((size_t)(bh*ML + l))*DH);
    }
    float m = scv[0];
#pragma unroll
    for (int j = 1; j < 8; j++) m = fmaxf(m, scv[j]);
#pragma unroll
    for (int o = 16; o > 0; o >>= 1) m = fmaxf(m, __shfl_xor_sync(0xffffffffu, m, o));
    float s = 0.f;
#pragma unroll
    for (int j = 0; j < 8; j++) { scv[j] = expf(scv[j] - m); s += scv[j]; }
#pragma unroll
    for (int o = 16; o > 0; o >>= 1) s += __shfl_xor_sync(0xffffffffu, s, o);
    float Zi = 1.f / s;
#pragma unroll
    for (int j = 0; j < 8; j++) psh[wid][j*32 + lane] = scv[j];
    __syncwarp();
    float acc0 = 0.f, acc1 = 0.f;
    const float* wbase = d_w2 + ((size_t)bh*ML)*DH;
#pragma unroll 4
    for (int l = 0; l < ML; l++) {
        float p = psh[wid][l];
        acc0 += p * wbase[l*DH + lane];
        acc1 += p * wbase[l*DH + lane + 32];
    }
    float* op = d_attn + ((size_t)(b*NP + t))*EMBD + h*64;
    op[lane]      = acc0 * Zi;
    op[lane + 32] = acc1 * Zi;
}

__global__ void conv_res_k(const float* __restrict__ w) {
    size_t idx = (size_t)blockIdx.x*256 + threadIdx.x;
    if (idx >= (size_t)BB*NH*NP*DH) return;
    int dd = idx & 63; size_t r = idx >> 6;
    int t = r % NP; r /= NP; int h = r % NH; int b = (int)(r / NH);
    float s = 0.f;
#pragma unroll
    for (int k = 0; k < 33; k++) {
        int tt = t + k - 16;
        if (tt >= 0 && tt < NP)
            s += d_qkv[((size_t)(b*NP + tt))*1536 + 1024 + h*64 + dd] * w[h*33 + k];
    }
    d_attn[((size_t)(b*NP + t))*EMBD + h*64 + dd] += s;
}

__global__ void add_res_k() {
    size_t idx = (size_t)blockIdx.x*256 + threadIdx.x;
    if (idx >= (size_t)BB*NT*EMBD) return;
    int c = idx % EMBD; size_t r = idx / EMBD; int t = r % NT; int b = (int)(r / NT);
    d_h[idx] += d_xn[((size_t)(b*NP + t + PADT))*EMBD + c];
}

__global__ __launch_bounds__(256) void ppeg_k(
    const float* __restrict__ w7, const float* __restrict__ b7,
    const float* __restrict__ w5, const float* __restrict__ b5,
    const float* __restrict__ w3, const float* __restrict__ b3)
{
    int blk = blockIdx.x; int b = blk / NPIX; int pix = blk % NPIX;
    int i = pix / HW, j = pix % HW;
    int tid = threadIdx.x;
    for (int c = tid; c < EMBD; c += 256) {
        float s = d_h[((size_t)(b*NT + 1 + pix))*EMBD + c] + b7[c] + b5[c] + b3[c];
#pragma unroll
        for (int a = 0; a < 7; a++) {
            int ii = i - 3 + a; if (ii < 0 || ii >= HW) continue;
#pragma unroll
            for (int q = 0; q < 7; q++) {
                int jj = j - 3 + q; if (jj < 0 || jj >= HW) continue;
                s += d_h[((size_t)(b*NT + 1 + ii*HW + jj))*EMBD + c] * w7[c*49 + a*7 + q];
            }
        }
#pragma unroll
        for (int a = 0; a < 5; a++) {
            int ii = i - 2 + a; if (ii < 0 || ii >= HW) continue;
#pragma unroll
            for (int q = 0; q < 5; q++) {
                int jj = j - 2 + q; if (jj < 0 || jj >= HW) continue;
                s += d_h[((size_t)(b*NT + 1 + ii*HW + jj))*EMBD + c] * w5[c*25 + a*5 + q];
            }
        }
#pragma unroll
        for (int a = 0; a < 3; a++) {
            int ii = i - 1 + a; if (ii < 0 || ii >= HW) continue;
#pragma unroll
            for (int q = 0; q < 3; q++) {
                int jj = j - 1 + q; if (jj < 0 || jj >= HW) continue;
                s += d_h[((size_t)(b*NT + 1 + ii*HW + jj))*EMBD + c] * w3[c*9 + a*3 + q];
            }
        }
        d_xn[((size_t)(b*NPIX + pix))*EMBD + c] = s;
    }
}

__global__ void ppeg_copy_k() {
    size_t idx = (size_t)blockIdx.x*256 + threadIdx.x;
    if (idx >= (size_t)BB*NPIX*EMBD) return;
    int c = idx % EMBD; size_t r = idx / EMBD; int pix = r % NPIX; int b = (int)(r / NPIX);
    d_h[((size_t)(b*NT + 1 + pix))*EMBD + c] = d_xn[idx];
}

__global__ __launch_bounds__(256) void head_k(
    const float* __restrict__ g, const float* __restrict__ bp,
    const float* __restrict__ w, const float* __restrict__ bias, float* __restrict__ out)
{
    int b = blockIdx.x; int tid = threadIdx.x;
    __shared__ float xs[512];
    __shared__ float red[256];
    __shared__ float lg[4];
    const float* x = d_h + (size_t)b*NT*EMBD;
    float v0 = x[tid], v1 = x[tid+256];
    red[tid] = v0 + v1; __syncthreads();
    for (int o = 128; o > 0; o >>= 1) { if (tid < o) red[tid] += red[tid+o]; __syncthreads(); }
    float mean = red[0] * (1.f/512.f); __syncthreads();
    float e0 = v0 - mean, e1 = v1 - mean;
    red[tid] = e0*e0 + e1*e1; __syncthreads();
    for (int o = 128; o > 0; o >>= 1) { if (tid < o) red[tid] += red[tid+o]; __syncthreads(); }
    float inv = rsqrtf(red[0] * (1.f/512.f) + 1e-5f);
    xs[tid]     = e0*inv*g[tid]     + bp[tid];
    xs[tid+256] = e1*inv*g[tid+256] + bp[tid+256];
    __syncthreads();
    if (tid < 4) {
        float s = bias[tid];
        for (int k = 0; k < 512; k++) s += xs[k]*w[k*4 + tid];
        lg[tid] = s;
    }
    __syncthreads();
    if (tid == 0) {
        int best = 0; float bv = lg[0];
        for (int k = 1; k < 4; k++) if (lg[k] > bv) { bv = lg[k]; best = k; }
        float S = 1.f;
        for (int k = 0; k < 4; k++) {
            float hz = 1.f / (1.f + expf(-lg[k]));
            out[b*4 + k] = hz;
            S *= (1.f - hz);
            out[16 + b*4 + k] = S;
        }
        out[32 + b] = (float)best;
    }
}

// -------------------- host orchestration --------------------
static float* symaddr(const void* sym) { void* p = nullptr; cudaGetSymbolAddress(&p, sym); return (float*)p; }

static void attn_layer(const float* lng, const float* lnb, const float* qkvw,
                       const float* outw, const float* outb, const float* resw)
{
    float* xnp   = symaddr(d_xn);
    float* qkvp  = symaddr(d_qkv);
    float* attnp = symaddr(d_attn);
    float* a2p   = symaddr(d_a2);
    float* z0p   = symaddr(d_z0);
    float* z1p   = symaddr(d_z1);
    float* t0p   = symaddr(d_t0);
    float* t1p   = symaddr(d_t1);
    float* t2p   = symaddr(d_t2);
    float* a3vp  = symaddr(d_a3v);
    float* w2p   = symaddr(d_w2);

    ln_pad_k<<<BB*NP, 256>>>(lng, lnb);
    sgemm_k<<<dim3(1536/128, NP/128, BB), 256>>>(
        xnp, qkvw, nullptr, qkvp, NP, 1536, EMBD,
        (size_t)NP*EMBD, 0, (size_t)NP*1536, 0.f, 1.f, 1.f, 0);
    landmarks_k<<<BH*ML, 64>>>();
    a2_k<<<BH*ML, 256>>>();
    reset_mx_k<<<1, 1>>>();
    a2_stats_k<<<BH, 256>>>();
    z_init_k<<<(BH*ML*ML + 255)/256, 256>>>();

    const size_t SB = (size_t)ML*ML;
    float* zin = z0p; float* zout = z1p;
    for (int it = 0; it < 6; it++) {
        sgemm_k<<<dim3(2, 2, BH), 256>>>(a2p, zin, nullptr, t0p, 256, 256, 256, SB, SB, SB, 0.f,  1.f, 1.f,  0);
        sgemm_k<<<dim3(2, 2, BH), 256>>>(t0p, t0p, nullptr, t1p, 256, 256, 256, SB, SB, SB, 7.f, -1.f, 1.f,  0);
        sgemm_k<<<dim3(2, 2, BH), 256>>>(t0p, t1p, nullptr, t2p, 256, 256, 256, SB, SB, SB, 15.f,-1.f, 1.f,  0);
        sgemm_k<<<dim3(2, 2, BH), 256>>>(zin, t2p, nullptr, zout,256, 256, 256, SB, SB, SB, 13.f,-1.f, 0.25f,0);
        float* tmp = zin; zin = zout; zout = tmp;
    }
    // zin now holds a2_inv (back in d_z0)

    a3v_flash_k<<<BH*ML, 256>>>();
    bgemm_epi<<<dim3(1, 4, BH), 256>>>(zin, a3vp, w2p, 256, 64, 256, 0.f, 1.f, 1.f);
    a1_out_k<<<BH*(NP/TPB), 256>>>();
    conv_res_k<<<(int)(((size_t)BB*NH*NP*DH + 255)/256), 256>>>(resw);
    sgemm_k<<<dim3(EMBD/128, NP/128, BB), 256>>>(
        attnp, outw, outb, xnp, NP, EMBD, EMBD,
        (size_t)NP*EMBD, 0, (size_t)NP*EMBD, 0.f, 1.f, 1.f, 0);
    add_res_k<<<(int)(((size_t)BB*NT*EMBD + 255)/256), 256>>>();
}

extern "C" void kernel_launch(void* const* d_in, const int* in_sizes, int n_in,
                              void* d_out, int out_size)
{
    (void)in_sizes; (void)n_in; (void)out_size;
    const float* x_path = (const float*)d_in[0];
    const float* fc1_w  = (const float*)d_in[1];
    const float* fc1_b  = (const float*)d_in[2];
    const float* cls    = (const float*)d_in[3];
    const float* ln1g   = (const float*)d_in[4];
    const float* ln1b   = (const float*)d_in[5];
    const float* qkv1w  = (const float*)d_in[6];
    const float* out1w  = (const float*)d_in[7];
    const float* out1b  = (const float*)d_in[8];
    const float* res1w  = (const float*)d_in[9];
    const float* ln2g   = (const float*)d_in[10];
    const float* ln2b   = (const float*)d_in[11];
    const float* qkv2w  = (const float*)d_in[12];
    const float* out2w  = (const float*)d_in[13];
    const float* out2b  = (const float*)d_in[14];
    const float* res2w  = (const float*)d_in[15];
    const float* c7w    = (const float*)d_in[16];
    const float* c7b    = (const float*)d_in[17];
    const float* c5w    = (const float*)d_in[18];
    const float* c5b    = (const float*)d_in[19];
    const float* c3w    = (const float*)d_in[20];
    const float* c3b    = (const float*)d_in[21];
    const float* ng     = (const float*)d_in[22];
    const float* nb     = (const float*)d_in[23];
    const float* fc2w   = (const float*)d_in[24];
    const float* fc2b   = (const float*)d_in[25];
    float* out = (float*)d_out;

    float* hp = symaddr(d_h);

    // fc1 + relu -> tokens 1..6000 of d_h (per batch)
    sgemm_k<<<dim3(EMBD/128, (N0 + 127)/128, BB), 256>>>(
        x_path, fc1_w, fc1_b, hp + EMBD, N0, EMBD, 1024,
        (size_t)N0*1024, 0, (size_t)NT*EMBD, 0.f, 1.f, 1.f, 1);
    fill_cls_k<<<(BB*EMBD + 255)/256, 256>>>(cls);
    fill_wrap_k<<<(BB*ADDW*EMBD + 255)/256, 256>>>();

    // layer 1 attention
    attn_layer(ln1g, ln1b, qkv1w, out1w, out1b, res1w);

    // PPEG
    ppeg_k<<<BB*NPIX, 256>>>(c7w, c7b, c5w, c5b, c3w, c3b);
    ppeg_copy_k<<<(int)(((size_t)BB*NPIX*EMBD + 255)/256), 256>>>();

    // layer 2 attention
    attn_layer(ln2g, ln2b, qkv2w, out2w, out2b, res2w);

    // head: layernorm(token0) @ fc2 -> hazards, S, Y_hat
    head_k<<<BB, 256>>>(ng, nb, fc2w, fc2b, out);
}

// round 3
// speedup vs baseline: 1.4979x; 1.1585x over previous
#include <cuda_runtime.h>
#include <math.h>
#include <stdint.h>

#define BB   4
#define N0   6000
#define HW   78
#define NPIX (HW*HW)        // 6084
#define ADDW (NPIX - N0)    // 84
#define NT   (NPIX + 1)     // 6085
#define NP   6144
#define PADT (NP - NT)      // 59
#define EMBD 512
#define NH   8
#define DH   64
#define ML   256
#define LWIN (NP/ML)        // 24
#define BH   (BB*NH)        // 32

// -------------------- scratch (device globals, no allocation) --------------------
__device__ float d_h   [(size_t)BB*NT*EMBD];
__device__ float d_xn  [(size_t)BB*NP*EMBD];
__device__ float d_qkv [(size_t)BB*NP*3*EMBD];
__device__ float d_attn[(size_t)BB*NP*EMBD];
__device__ float d_ql  [BH*ML*DH];
__device__ float d_kl  [BH*ML*DH];
__device__ float d_a2  [BH*ML*ML];
__device__ float d_z0  [BH*ML*ML];
__device__ float d_z1  [BH*ML*ML];
__device__ float d_t0  [BH*ML*ML];
__device__ float d_t1  [BH*ML*ML];
__device__ float d_t2  [BH*ML*ML];
__device__ float d_a3v [BH*ML*DH];
__device__ float d_w2  [BH*ML*DH];
__device__ float d_mx  [2];

__device__ __forceinline__ float dot64(const float* __restrict__ a, const float* __restrict__ kp) {
    float s = 0.f;
#pragma unroll
    for (int i = 0; i < 16; i++) {
        float4 x = *(const float4*)(kp + 4*i);
        s += a[4*i]*x.x + a[4*i+1]*x.y + a[4*i+2]*x.z + a[4*i+3]*x.w;
    }
    return s;
}

__device__ __forceinline__ uint32_t f2tf32(float f) {
    uint32_t r;
    asm("cvt.rna.tf32.f32 %0, %1;" : "=r"(r) : "f"(f));
    return r;
}

__device__ __forceinline__ void mma_tf32(float* c, const uint32_t* a, const uint32_t* b) {
    asm volatile("mma.sync.aligned.m16n8k8.row.col.f32.tf32.tf32.f32 "
        "{%0,%1,%2,%3}, {%4,%5,%6,%7}, {%8,%9}, {%0,%1,%2,%3};"
        : "+f"(c[0]), "+f"(c[1]), "+f"(c[2]), "+f"(c[3])
        : "r"(a[0]), "r"(a[1]), "r"(a[2]), "r"(a[3]), "r"(b[0]), "r"(b[1]));
}

// ==================== tf32 tensor-core GEMM, 128x128x8 double-buffered ====================
// C = sc * ( A @ (cI*I + eB*B) ) + bias, optional relu.
// N multiple of 128, K multiple of 8, M guarded.
__global__ __launch_bounds__(256) void tf32gemm_k(
    const float* __restrict__ A, const float* __restrict__ B,
    const float* __restrict__ bias, float* __restrict__ C,
    int M, int N, int K, size_t sA, size_t sB, size_t sC,
    float cI, float eB, float sc, int act)
{
    __shared__ uint32_t As[2][8][136];
    __shared__ uint32_t Bs[2][8][136];
    A += (size_t)blockIdx.z * sA;
    B += (size_t)blockIdx.z * sB;
    C += (size_t)blockIdx.z * sC;
    int bm = blockIdx.y * 128, bn = blockIdx.x * 128;
    int tid = threadIdx.x;
    int arow = tid >> 1, acol = (tid & 1) << 2;     // A tile: 128 x 8
    int brow = tid >> 5, bcol = (tid & 31) << 2;    // B tile: 8 x 128
    int wid = tid >> 5, lane = tid & 31;
    int wy = wid >> 2, wx = wid & 3;                // warp grid 2 x 4 -> 64 x 32 per warp
    int g = lane >> 2, tg = lane & 3;

    float acc[4][4][4];
#pragma unroll
    for (int mi = 0; mi < 4; mi++)
#pragma unroll
        for (int ni = 0; ni < 4; ni++)
#pragma unroll
            for (int q = 0; q < 4; q++) acc[mi][ni][q] = 0.f;

    int nk = K >> 3;
    int col0 = bn + bcol;

    // prologue tile 0 -> buf 0
    {
        int r = bm + arow;
        float4 va = make_float4(0.f,0.f,0.f,0.f);
        if (r < M) va = *(const float4*)(A + (size_t)r*K + acol);
        As[0][acol+0][arow] = f2tf32(va.x);
        As[0][acol+1][arow] = f2tf32(va.y);
        As[0][acol+2][arow] = f2tf32(va.z);
        As[0][acol+3][arow] = f2tf32(va.w);
        float4 vb = *(const float4*)(B + (size_t)brow*N + col0);
        float e0 = eB*vb.x, e1 = eB*vb.y, e2 = eB*vb.z, e3 = eB*vb.w;
        if (brow == col0    ) e0 += cI;
        if (brow == col0 + 1) e1 += cI;
        if (brow == col0 + 2) e2 += cI;
        if (brow == col0 + 3) e3 += cI;
        Bs[0][brow][bcol  ] = f2tf32(e0);
        Bs[0][brow][bcol+1] = f2tf32(e1);
        Bs[0][brow][bcol+2] = f2tf32(e2);
        Bs[0][brow][bcol+3] = f2tf32(e3);
    }
    __syncthreads();

    int buf = 0;
    for (int kt = 0; kt < nk; kt++) {
        float4 va, vb;
        bool pf = (kt + 1 < nk);
        if (pf) {
            int k0 = (kt + 1) << 3;
            int r = bm + arow;
            va = make_float4(0.f,0.f,0.f,0.f);
            if (r < M) va = *(const float4*)(A + (size_t)r*K + k0 + acol);
            vb = *(const float4*)(B + (size_t)(k0 + brow)*N + col0);
        }
        // fragments
        uint32_t af[4][4];
#pragma unroll
        for (int mi = 0; mi < 4; mi++) {
            int r0 = wy*64 + mi*16;
            af[mi][0] = As[buf][tg  ][r0 + g];
            af[mi][1] = As[buf][tg  ][r0 + g + 8];
            af[mi][2] = As[buf][tg+4][r0 + g];
            af[mi][3] = As[buf][tg+4][r0 + g + 8];
        }
        uint32_t bfr[4][2];
#pragma unroll
        for (int ni = 0; ni < 4; ni++) {
            int c0 = wx*32 + ni*8;
            bfr[ni][0] = Bs[buf][tg  ][c0 + g];
            bfr[ni][1] = Bs[buf][tg+4][c0 + g];
        }
#pragma unroll
        for (int mi = 0; mi < 4; mi++)
#pragma unroll
            for (int ni = 0; ni < 4; ni++)
                mma_tf32(acc[mi][ni], af[mi], bfr[ni]);

        if (pf) {
            int nb = buf ^ 1;
            int kr = ((kt + 1) << 3) + brow;
            As[nb][acol+0][arow] = f2tf32(va.x);
            As[nb][acol+1][arow] = f2tf32(va.y);
            As[nb][acol+2][arow] = f2tf32(va.z);
            As[nb][acol+3][arow] = f2tf32(va.w);
            float e0 = eB*vb.x, e1 = eB*vb.y, e2 = eB*vb.z, e3 = eB*vb.w;
            if (kr == col0    ) e0 += cI;
            if (kr == col0 + 1) e1 += cI;
            if (kr == col0 + 2) e2 += cI;
            if (kr == col0 + 3) e3 += cI;
            Bs[nb][brow][bcol  ] = f2tf32(e0);
            Bs[nb][brow][bcol+1] = f2tf32(e1);
            Bs[nb][brow][bcol+2] = f2tf32(e2);
            Bs[nb][brow][bcol+3] = f2tf32(e3);
        }
        __syncthreads();
        buf ^= 1;
    }

#pragma unroll
    for (int mi = 0; mi < 4; mi++) {
#pragma unroll
        for (int half = 0; half < 2; half++) {
            int r = bm + wy*64 + mi*16 + g + half*8;
            if (r >= M) continue;
#pragma unroll
            for (int ni = 0; ni < 4; ni++) {
                int c = bn + wx*32 + ni*8 + 2*tg;
                float v0 = sc*acc[mi][ni][half*2+0] + (bias ? bias[c]   : 0.f);
                float v1 = sc*acc[mi][ni][half*2+1] + (bias ? bias[c+1] : 0.f);
                if (act == 1) { v0 = fmaxf(v0, 0.f); v1 = fmaxf(v1, 0.f); }
                *(float2*)(C + (size_t)r*N + c) = make_float2(v0, v1);
            }
        }
    }
}

// ==================== 128x128x8 double-buffered fp32 SGEMM (precision path) ====================
__global__ __launch_bounds__(256) void sgemm_k(
    const float* __restrict__ A, const float* __restrict__ B,
    const float* __restrict__ bias, float* __restrict__ C,
    int M, int N, int K, size_t sA, size_t sB, size_t sC,
    float cI, float eB, float sc, int act)
{
    __shared__ float As[2][8][132];
    __shared__ float Bs[2][8][132];
    A += (size_t)blockIdx.z * sA;
    B += (size_t)blockIdx.z * sB;
    C += (size_t)blockIdx.z * sC;
    int bm = blockIdx.y * 128, bn = blockIdx.x * 128;
    int tid = threadIdx.x;
    int arow = tid >> 1, acol = (tid & 1) << 2;
    int brow = tid >> 5, bcol = (tid & 31) << 2;
    int ty = tid >> 4, tx = tid & 15;

    float acc[8][8];
#pragma unroll
    for (int i = 0; i < 8; i++)
#pragma unroll
        for (int j = 0; j < 8; j++) acc[i][j] = 0.f;

    int nk = K >> 3;
    int col0 = bn + bcol;

    {
        int r = bm + arow;
        float4 va = make_float4(0.f,0.f,0.f,0.f);
        if (r < M) va = *(const float4*)(A + (size_t)r*K + acol);
        As[0][acol+0][arow] = va.x;
        As[0][acol+1][arow] = va.y;
        As[0][acol+2][arow] = va.z;
        As[0][acol+3][arow] = va.w;
        float4 vb = *(const float4*)(B + (size_t)brow*N + col0);
        float e0 = eB*vb.x, e1 = eB*vb.y, e2 = eB*vb.z, e3 = eB*vb.w;
        if (brow == col0    ) e0 += cI;
        if (brow == col0 + 1) e1 += cI;
        if (brow == col0 + 2) e2 += cI;
        if (brow == col0 + 3) e3 += cI;
        Bs[0][brow][bcol  ] = e0;
        Bs[0][brow][bcol+1] = e1;
        Bs[0][brow][bcol+2] = e2;
        Bs[0][brow][bcol+3] = e3;
    }
    __syncthreads();

    int buf = 0;
    for (int kt = 0; kt < nk; kt++) {
        float4 va, vb;
        bool pf = (kt + 1 < nk);
        if (pf) {
            int k0 = (kt + 1) << 3;
            int r = bm + arow;
            va = make_float4(0.f,0.f,0.f,0.f);
            if (r < M) va = *(const float4*)(A + (size_t)r*K + k0 + acol);
            vb = *(const float4*)(B + (size_t)(k0 + brow)*N + col0);
        }
#pragma unroll
        for (int kk = 0; kk < 8; kk++) {
            float4 a0 = *(const float4*)&As[buf][kk][ty*8];
            float4 a1 = *(const float4*)&As[buf][kk][ty*8 + 4];
            float4 b0 = *(const float4*)&Bs[buf][kk][tx*8];
            float4 b1 = *(const float4*)&Bs[buf][kk][tx*8 + 4];
            float ar[8] = {a0.x,a0.y,a0.z,a0.w,a1.x,a1.y,a1.z,a1.w};
            float br[8] = {b0.x,b0.y,b0.z,b0.w,b1.x,b1.y,b1.z,b1.w};
#pragma unroll
            for (int i = 0; i < 8; i++)
#pragma unroll
                for (int j = 0; j < 8; j++) acc[i][j] += ar[i]*br[j];
        }
        if (pf) {
            int nb = buf ^ 1;
            int kr = ((kt + 1) << 3) + brow;
            As[nb][acol+0][arow] = va.x;
            As[nb][acol+1][arow] = va.y;
            As[nb][acol+2][arow] = va.z;
            As[nb][acol+3][arow] = va.w;
            float e0 = eB*vb.x, e1 = eB*vb.y, e2 = eB*vb.z, e3 = eB*vb.w;
            if (kr == col0    ) e0 += cI;
            if (kr == col0 + 1) e1 += cI;
            if (kr == col0 + 2) e2 += cI;
            if (kr == col0 + 3) e3 += cI;
            Bs[nb][brow][bcol  ] = e0;
            Bs[nb][brow][bcol+1] = e1;
            Bs[nb][brow][bcol+2] = e2;
            Bs[nb][brow][bcol+3] = e3;
        }
        __syncthreads();
        buf ^= 1;
    }

    float bj[8];
#pragma unroll
    for (int j = 0; j < 8; j++) bj[j] = bias ? bias[bn + tx*8 + j] : 0.f;
#pragma unroll
    for (int i = 0; i < 8; i++) {
        int r = bm + ty*8 + i;
        if (r >= M) continue;
        float* Crow = C + (size_t)r*N + bn + tx*8;
#pragma unroll
        for (int j0 = 0; j0 < 8; j0 += 4) {
            float4 v;
            v.x = sc*acc[i][j0+0] + bj[j0+0];
            v.y = sc*acc[i][j0+1] + bj[j0+1];
            v.z = sc*acc[i][j0+2] + bj[j0+2];
            v.w = sc*acc[i][j0+3] + bj[j0+3];
            if (act == 1) {
                v.x = fmaxf(v.x, 0.f); v.y = fmaxf(v.y, 0.f);
                v.z = fmaxf(v.z, 0.f); v.w = fmaxf(v.w, 0.f);
            }
            *(float4*)(Crow + j0) = v;
        }
    }
}

// -------------------- small 64-tile batched GEMM (fp32, N=64 case) --------------------
__global__ __launch_bounds__(256) void bgemm_epi(
    const float* __restrict__ A, const float* __restrict__ Bm, float* __restrict__ C,
    int Md, int Nd, int Kd, float cI, float eB, float s)
{
    __shared__ float As[16][64];
    __shared__ float Bs[16][64];
    A  += (size_t)blockIdx.z * Md * Kd;
    Bm += (size_t)blockIdx.z * Kd * Nd;
    C  += (size_t)blockIdx.z * Md * Nd;
    int bm = blockIdx.y * 64, bn = blockIdx.x * 64;
    int tid = threadIdx.x;
    int la_r = tid >> 2, la_c = (tid & 3) << 2;
    int lb_r = tid >> 4, lb_c = (tid & 15) << 2;
    int ty = tid >> 4, tx = tid & 15;
    float acc[4][4];
#pragma unroll
    for (int i = 0; i < 4; i++)
#pragma unroll
        for (int j = 0; j < 4; j++) acc[i][j] = 0.f;

    for (int k0 = 0; k0 < Kd; k0 += 16) {
        float4 av = *(const float4*)(A + (size_t)(bm + la_r)*Kd + k0 + la_c);
        As[la_c  ][la_r] = av.x;
        As[la_c+1][la_r] = av.y;
        As[la_c+2][la_r] = av.z;
        As[la_c+3][la_r] = av.w;
        int kr = k0 + lb_r;
        float4 bv = *(const float4*)(Bm + (size_t)kr*Nd + bn + lb_c);
        float e0 = eB*bv.x, e1 = eB*bv.y, e2 = eB*bv.z, e3 = eB*bv.w;
        int c0 = bn + lb_c;
        if (kr == c0    ) e0 += cI;
        if (kr == c0 + 1) e1 += cI;
        if (kr == c0 + 2) e2 += cI;
        if (kr == c0 + 3) e3 += cI;
        Bs[lb_r][lb_c  ] = e0;
        Bs[lb_r][lb_c+1] = e1;
        Bs[lb_r][lb_c+2] = e2;
        Bs[lb_r][lb_c+3] = e3;
        __syncthreads();
#pragma unroll
        for (int kk = 0; kk < 16; kk++) {
            float a0 = As[kk][ty*4+0], a1 = As[kk][ty*4+1], a2 = As[kk][ty*4+2], a3 = As[kk][ty*4+3];
            float b0 = Bs[kk][tx*4+0], b1 = Bs[kk][tx*4+1], b2 = Bs[kk][tx*4+2], b3 = Bs[kk][tx*4+3];
            acc[0][0]+=a0*b0; acc[0][1]+=a0*b1; acc[0][2]+=a0*b2; acc[0][3]+=a0*b3;
            acc[1][0]+=a1*b0; acc[1][1]+=a1*b1; acc[1][2]+=a1*b2; acc[1][3]+=a1*b3;
            acc[2][0]+=a2*b0; acc[2][1]+=a2*b1; acc[2][2]+=a2*b2; acc[2][3]+=a2*b3;
            acc[3][0]+=a3*b0; acc[3][1]+=a3*b1; acc[3][2]+=a3*b2; acc[3][3]+=a3*b3;
        }
        __syncthreads();
    }
#pragma unroll
    for (int i = 0; i < 4; i++) {
        int r = bm + ty*4 + i;
#pragma unroll
        for (int j = 0; j < 4; j++) {
            int c = bn + tx*4 + j;
            C[(size_t)r*Nd + c] = s * acc[i][j];
        }
    }
}

// -------------------- misc small kernels --------------------
__global__ void fill_cls_k(const float* __restrict__ cls) {
    int i = blockIdx.x*256 + threadIdx.x;
    if (i < BB*EMBD) d_h[(size_t)(i/EMBD)*NT*EMBD + (i % EMBD)] = cls[i % EMBD];
}

__global__ void fill_wrap_k() {
    int i = blockIdx.x*256 + threadIdx.x;
    if (i >= BB*ADDW*EMBD) return;
    int c = i % EMBD; int r = i / EMBD; int j = r % ADDW; int b = r / ADDW;
    d_h[((size_t)(b*NT + 1 + N0 + j))*EMBD + c] = d_h[((size_t)(b*NT + 1 + j))*EMBD + c];
}

__global__ __launch_bounds__(256) void ln_pad_k(const float* __restrict__ g, const float* __restrict__ bp) {
    int row = blockIdx.x; int b = row / NP; int t = row % NP;
    int tid = threadIdx.x;
    float* out = d_xn + (size_t)row*EMBD;
    if (t < PADT) { out[tid] = 0.f; out[tid+256] = 0.f; return; }
    const float* x = d_h + ((size_t)b*NT + (t - PADT))*EMBD;
    float v0 = x[tid], v1 = x[tid+256];
    __shared__ float red[256];
    red[tid] = v0 + v1; __syncthreads();
    for (int o = 128; o > 0; o >>= 1) { if (tid < o) red[tid] += red[tid+o]; __syncthreads(); }
    float mean = red[0] * (1.f/512.f); __syncthreads();
    float e0 = v0 - mean, e1 = v1 - mean;
    red[tid] = e0*e0 + e1*e1; __syncthreads();
    for (int o = 128; o > 0; o >>= 1) { if (tid < o) red[tid] += red[tid+o]; __syncthreads(); }
    float inv = rsqrtf(red[0] * (1.f/512.f) + 1e-5f);
    out[tid]     = e0*inv*g[tid]     + bp[tid];
    out[tid+256] = e1*inv*g[tid+256] + bp[tid+256];
}

__global__ void landmarks_k() {
    int blk = blockIdx.x; int bh = blk >> 8; int i = blk & 255;
    int d = threadIdx.x;  // 64 threads
    int b = bh / NH, h = bh % NH;
    const float* base = d_qkv + ((size_t)(b*NP) + (size_t)i*LWIN)*1536 + h*64 + d;
    float sq = 0.f, sk = 0.f;
#pragma unroll
    for (int j = 0; j < LWIN; j++) { sq += base[(size_t)j*1536]; sk += base[(size_t)j*1536 + 512]; }
    d_ql[((size_t)(bh*ML + i))*DH + d] = sq * (0.125f / LWIN);
    d_kl[((size_t)(bh*ML + i))*DH + d] = sk * (1.f   / LWIN);
}

__global__ __launch_bounds__(256) void a2_k() {
    int blk = blockIdx.x; int bh = blk >> 8; int i = blk & 255;
    int tid = threadIdx.x;
    __shared__ float sq[64];
    __shared__ float red[256];
    if (tid < 64) sq[tid] = d_ql[((size_t)(bh*ML + i))*DH + tid];
    __syncthreads();
    float s = dot64(sq, d_kl + ((size_t)(bh*ML + tid))*DH);
    red[tid] = s; __syncthreads();
    for (int o = 128; o > 0; o >>= 1) { if (tid < o) red[tid] = fmaxf(red[tid], red[tid+o]); __syncthreads(); }
    float m = red[0]; __syncthreads();
    float p = expf(s - m);
    red[tid] = p; __syncthreads();
    for (int o = 128; o > 0; o >>= 1) { if (tid < o) red[tid] += red[tid+o]; __syncthreads(); }
    float Z = red[0];
    d_a2[((size_t)bh << 16) + ((size_t)i << 8) + tid] = p / Z;
}

__global__ void reset_mx_k() { d_mx[0] = 0.f; d_mx[1] = 0.f; }

__global__ __launch_bounds__(256) void a2_stats_k() {
    int bh = blockIdx.x; int tid = threadIdx.x;
    const float* a = d_a2 + ((size_t)bh << 16);
    float cs = 0.f, rs = 0.f;
    for (int i = 0; i < ML; i++) cs += a[(size_t)i*ML + tid];
    for (int j = 0; j < ML; j++) rs += a[(size_t)tid*ML + j];
    __shared__ float red[256];
    red[tid] = cs; __syncthreads();
    for (int o = 128; o > 0; o >>= 1) { if (tid < o) red[tid] = fmaxf(red[tid], red[tid+o]); __syncthreads(); }
    if (tid == 0) atomicMax((int*)&d_mx[1], __float_as_int(red[0]));
    __syncthreads();
    red[tid] = rs; __syncthreads();
    for (int o = 128; o > 0; o >>= 1) { if (tid < o) red[tid] = fmaxf(red[tid], red[tid+o]); __syncthreads(); }
    if (tid == 0) atomicMax((int*)&d_mx[0], __float_as_int(red[0]));
}

__global__ void z_init_k() {
    size_t idx = (size_t)blockIdx.x*256 + threadIdx.x;
    if (idx >= (size_t)BH*ML*ML) return;
    size_t bh = idx >> 16; size_t r = (idx >> 8) & 255; size_t c = idx & 255;
    float denom = d_mx[0] * d_mx[1];
    d_z0[idx] = d_a2[(bh << 16) + (c << 8) + r] / denom;
}

// -------------------- fused a3 @ v with online softmax (flash-style) --------------------
__global__ __launch_bounds__(256) void a3v_flash_k() {
    int blk = blockIdx.x; int bh = blk >> 8; int i = blk & 255;
    int tid = threadIdx.x; int b = bh / NH, h = bh % NH;
    __shared__ float sq[64];
    __shared__ float pbuf[256];
    __shared__ float red[256];
    if (tid < 64) sq[tid] = d_ql[((size_t)(bh*ML + i))*DH + tid];
    __syncthreads();
    int g = tid >> 6, dd = tid & 63;
    float m = -1e30f, s = 0.f, acc = 0.f;
    for (int c0 = 0; c0 < NP; c0 += 256) {
        const float* kp = d_qkv + ((size_t)(b*NP + c0 + tid))*1536 + 512 + h*64;
        float scv = dot64(sq, kp);
        red[tid] = scv; __syncthreads();
        for (int o = 128; o > 0; o >>= 1) { if (tid < o) red[tid] = fmaxf(red[tid], red[tid+o]); __syncthreads(); }
        float cm = red[0]; __syncthreads();
        float newm = fmaxf(m, cm);
        float f = expf(m - newm);
        float p = expf(scv - newm);
        pbuf[tid] = p; red[tid] = p; __syncthreads();
        for (int o = 128; o > 0; o >>= 1) { if (tid < o) red[tid] += red[tid+o]; __syncthreads(); }
        float ps = red[0]; __syncthreads();
        s = s*f + ps; m = newm;
        acc *= f;
        const float* vb = d_qkv + ((size_t)(b*NP + c0 + (g << 6)))*1536 + 1024 + h*64 + dd;
        const float* pb = pbuf + (g << 6);
#pragma unroll 8
        for (int j = 0; j < 64; j++) acc += pb[j] * vb[(size_t)j*1536];
    }
    __syncthreads();
    pbuf[tid] = acc; __syncthreads();
    if (tid < 64)
        d_a3v[((size_t)(bh*ML + i))*DH + tid] =
            (pbuf[tid] + pbuf[tid+64] + pbuf[tid+128] + pbuf[tid+192]) / s;
}

// -------------------- a1 softmax @ w2: one warp per token --------------------
#define TPB 8
__global__ __launch_bounds__(256) void a1_out_k() {
    int blk = blockIdx.x;
    int bh = blk / (NP/TPB);
    int t0 = (blk % (NP/TPB)) * TPB;
    int tid = threadIdx.x;
    int wid = tid >> 5, lane = tid & 31;
    int b = bh / NH, h = bh % NH;
    int t = t0 + wid;
    __shared__ float qsh[TPB][64];
    __shared__ float psh[TPB][256];
    const float* qp = d_qkv + ((size_t)(b*NP + t))*1536 + h*64;
    qsh[wid][lane]      = qp[lane]      * 0.125f;
    qsh[wid][lane + 32] = qp[lane + 32] * 0.125f;
    __syncwarp();
    float scv[8];
#pragma unroll
    for (int j = 0; j < 8; j++) {
        int l = j*32 + lane;
        scv[j] = dot64(qsh[wid], d_kl + ((size_t)(bh*ML + l))*DH);
    }
    float m = scv[0];
#pragma unroll
    for (int j = 1; j < 8; j++) m = fmaxf(m, scv[j]);
#pragma unroll
    for (int o = 16; o > 0; o >>= 1) m = fmaxf(m, __shfl_xor_sync(0xffffffffu, m, o));
    float s = 0.f;
#pragma unroll
    for (int j = 0; j < 8; j++) { scv[j] = expf(scv[j] - m); s += scv[j]; }
#pragma unroll
    for (int o = 16; o > 0; o >>= 1) s += __shfl_xor_sync(0xffffffffu, s, o);
    float Zi = 1.f / s;
#pragma unroll
    for (int j = 0; j < 8; j++) psh[wid][j*32 + lane] = scv[j];
    __syncwarp();
    float acc0 = 0.f, acc1 = 0.f;
    const float* wbase = d_w2 + ((size_t)bh*ML)*DH;
#pragma unroll 4
    for (int l = 0; l < ML; l++) {
        float p = psh[wid][l];
        acc0 += p * wbase[l*DH + lane];
        acc1 += p * wbase[l*DH + lane + 32];
    }
    float* op = d_attn + ((size_t)(b*NP + t))*EMBD + h*64;
    op[lane]      = acc0 * Zi;
    op[lane + 32] = acc1 * Zi;
}

__global__ void conv_res_k(const float* __restrict__ w) {
    size_t idx = (size_t)blockIdx.x*256 + threadIdx.x;
    if (idx >= (size_t)BB*NH*NP*DH) return;
    int dd = idx & 63; size_t r = idx >> 6;
    int t = r % NP; r /= NP; int h = r % NH; int b = (int)(r / NH);
    float s = 0.f;
#pragma unroll
    for (int k = 0; k < 33; k++) {
        int tt = t + k - 16;
        if (tt >= 0 && tt < NP)
            s += d_qkv[((size_t)(b*NP + tt))*1536 + 1024 + h*64 + dd] * w[h*33 + k];
    }
    d_attn[((size_t)(b*NP + t))*EMBD + h*64 + dd] += s;
}

__global__ void add_res_k() {
    size_t idx = (size_t)blockIdx.x*256 + threadIdx.x;
    if (idx >= (size_t)BB*NT*EMBD) return;
    int c = idx % EMBD; size_t r = idx / EMBD; int t = r % NT; int b = (int)(r / NT);
    d_h[idx] += d_xn[((size_t)(b*NP + t + PADT))*EMBD + c];
}

__global__ __launch_bounds__(256) void ppeg_k(
    const float* __restrict__ w7, const float* __restrict__ b7,
    const float* __restrict__ w5, const float* __restrict__ b5,
    const float* __restrict__ w3, const float* __restrict__ b3)
{
    int blk = blockIdx.x; int b = blk / NPIX; int pix = blk % NPIX;
    int i = pix / HW, j = pix % HW;
    int tid = threadIdx.x;
    for (int c = tid; c < EMBD; c += 256) {
        float s = d_h[((size_t)(b*NT + 1 + pix))*EMBD + c] + b7[c] + b5[c] + b3[c];
#pragma unroll
        for (int a = 0; a < 7; a++) {
            int ii = i - 3 + a; if (ii < 0 || ii >= HW) continue;
#pragma unroll
            for (int q = 0; q < 7; q++) {
                int jj = j - 3 + q; if (jj < 0 || jj >= HW) continue;
                s += d_h[((size_t)(b*NT + 1 + ii*HW + jj))*EMBD + c] * w7[c*49 + a*7 + q];
            }
        }
#pragma unroll
        for (int a = 0; a < 5; a++) {
            int ii = i - 2 + a; if (ii < 0 || ii >= HW) continue;
#pragma unroll
            for (int q = 0; q < 5; q++) {
                int jj = j - 2 + q; if (jj < 0 || jj >= HW) continue;
                s += d_h[((size_t)(b*NT + 1 + ii*HW + jj))*EMBD + c] * w5[c*25 + a*5 + q];
            }
        }
#pragma unroll
        for (int a = 0; a < 3; a++) {
            int ii = i - 1 + a; if (ii < 0 || ii >= HW) continue;
#pragma unroll
            for (int q = 0; q < 3; q++) {
                int jj = j - 1 + q; if (jj < 0 || jj >= HW) continue;
                s += d_h[((size_t)(b*NT + 1 + ii*HW + jj))*EMBD + c] * w3[c*9 + a*3 + q];
            }
        }
        d_xn[((size_t)(b*NPIX + pix))*EMBD + c] = s;
    }
}

__global__ void ppeg_copy_k() {
    size_t idx = (size_t)blockIdx.x*256 + threadIdx.x;
    if (idx >= (size_t)BB*NPIX*EMBD) return;
    int c = idx % EMBD; size_t r = idx / EMBD; int pix = r % NPIX; int b = (int)(r / NPIX);
    d_h[((size_t)(b*NT + 1 + pix))*EMBD + c] = d_xn[idx];
}

__global__ __launch_bounds__(256) void head_k(
    const float* __restrict__ g, const float* __restrict__ bp,
    const float* __restrict__ w, const float* __restrict__ bias, float* __restrict__ out)
{
    int b = blockIdx.x; int tid = threadIdx.x;
    __shared__ float xs[512];
    __shared__ float red[256];
    __shared__ float lg[4];
    const float* x = d_h + (size_t)b*NT*EMBD;
    float v0 = x[tid], v1 = x[tid+256];
    red[tid] = v0 + v1; __syncthreads();
    for (int o = 128; o > 0; o >>= 1) { if (tid < o) red[tid] += red[tid+o]; __syncthreads(); }
    float mean = red[0] * (1.f/512.f); __syncthreads();
    float e0 = v0 - mean, e1 = v1 - mean;
    red[tid] = e0*e0 + e1*e1; __syncthreads();
    for (int o = 128; o > 0; o >>= 1) { if (tid < o) red[tid] += red[tid+o]; __syncthreads(); }
    float inv = rsqrtf(red[0] * (1.f/512.f) + 1e-5f);
    xs[tid]     = e0*inv*g[tid]     + bp[tid];
    xs[tid+256] = e1*inv*g[tid+256] + bp[tid+256];
    __syncthreads();
    if (tid < 4) {
        float s = bias[tid];
        for (int k = 0; k < 512; k++) s += xs[k]*w[k*4 + tid];
        lg[tid] = s;
    }
    __syncthreads();
    if (tid == 0) {
        int best = 0; float bv = lg[0];
        for (int k = 1; k < 4; k++) if (lg[k] > bv) { bv = lg[k]; best = k; }
        float S = 1.f;
        for (int k = 0; k < 4; k++) {
            float hz = 1.f / (1.f + expf(-lg[k]));
            out[b*4 + k] = hz;
            S *= (1.f - hz);
            out[16 + b*4 + k] = S;
        }
        out[32 + b] = (float)best;
    }
}

// -------------------- host orchestration --------------------
static float* symaddr(const void* sym) { void* p = nullptr; cudaGetSymbolAddress(&p, sym); return (float*)p; }

static void attn_layer(const float* lng, const float* lnb, const float* qkvw,
                       const float* outw, const float* outb, const float* resw)
{
    float* xnp   = symaddr(d_xn);
    float* qkvp  = symaddr(d_qkv);
    float* attnp = symaddr(d_attn);
    float* a2p   = symaddr(d_a2);
    float* z0p   = symaddr(d_z0);
    float* z1p   = symaddr(d_z1);
    float* t0p   = symaddr(d_t0);
    float* t1p   = symaddr(d_t1);
    float* t2p   = symaddr(d_t2);
    float* a3vp  = symaddr(d_a3v);
    float* w2p   = symaddr(d_w2);

    ln_pad_k<<<BB*NP, 256>>>(lng, lnb);
    tf32gemm_k<<<dim3(1536/128, NP/128, BB), 256>>>(
        xnp, qkvw, nullptr, qkvp, NP, 1536, EMBD,
        (size_t)NP*EMBD, 0, (size_t)NP*1536, 0.f, 1.f, 1.f, 0);
    landmarks_k<<<BH*ML, 64>>>();
    a2_k<<<BH*ML, 256>>>();
    reset_mx_k<<<1, 1>>>();
    a2_stats_k<<<BH, 256>>>();
    z_init_k<<<(BH*ML*ML + 255)/256, 256>>>();

    const size_t SB = (size_t)ML*ML;
    float* zin = z0p; float* zout = z1p;
    // iterations 0..4 in tf32 (Newton self-corrects), iteration 5 in fp32
    for (int it = 0; it < 5; it++) {
        tf32gemm_k<<<dim3(2, 2, BH), 256>>>(a2p, zin, nullptr, t0p, 256, 256, 256, SB, SB, SB, 0.f,  1.f, 1.f,  0);
        tf32gemm_k<<<dim3(2, 2, BH), 256>>>(t0p, t0p, nullptr, t1p, 256, 256, 256, SB, SB, SB, 7.f, -1.f, 1.f,  0);
        tf32gemm_k<<<dim3(2, 2, BH), 256>>>(t0p, t1p, nullptr, t2p, 256, 256, 256, SB, SB, SB, 15.f,-1.f, 1.f,  0);
        tf32gemm_k<<<dim3(2, 2, BH), 256>>>(zin, t2p, nullptr, zout,256, 256, 256, SB, SB, SB, 13.f,-1.f, 0.25f,0);
        float* tmp = zin; zin = zout; zout = tmp;
    }
    sgemm_k<<<dim3(2, 2, BH), 256>>>(a2p, zin, nullptr, t0p, 256, 256, 256, SB, SB, SB, 0.f,  1.f, 1.f,  0);
    sgemm_k<<<dim3(2, 2, BH), 256>>>(t0p, t0p, nullptr, t1p, 256, 256, 256, SB, SB, SB, 7.f, -1.f, 1.f,  0);
    sgemm_k<<<dim3(2, 2, BH), 256>>>(t0p, t1p, nullptr, t2p, 256, 256, 256, SB, SB, SB, 15.f,-1.f, 1.f,  0);
    sgemm_k<<<dim3(2, 2, BH), 256>>>(zin, t2p, nullptr, zout,256, 256, 256, SB, SB, SB, 13.f,-1.f, 0.25f,0);
    { float* tmp = zin; zin = zout; zout = tmp; }
    // zin now holds a2_inv (back in d_z0)

    a3v_flash_k<<<BH*ML, 256>>>();
    bgemm_epi<<<dim3(1, 4, BH), 256>>>(zin, a3vp, w2p, 256, 64, 256, 0.f, 1.f, 1.f);
    a1_out_k<<<BH*(NP/TPB), 256>>>();
    conv_res_k<<<(int)(((size_t)BB*NH*NP*DH + 255)/256), 256>>>(resw);
    tf32gemm_k<<<dim3(EMBD/128, NP/128, BB), 256>>>(
        attnp, outw, outb, xnp, NP, EMBD, EMBD,
        (size_t)NP*EMBD, 0, (size_t)NP*EMBD, 0.f, 1.f, 1.f, 0);
    add_res_k<<<(int)(((size_t)BB*NT*EMBD + 255)/256), 256>>>();
}

extern "C" void kernel_launch(void* const* d_in, const int* in_sizes, int n_in,
                              void* d_out, int out_size)
{
    (void)in_sizes; (void)n_in; (void)out_size;
    const float* x_path = (const float*)d_in[0];
    const float* fc1_w  = (const float*)d_in[1];
    const float* fc1_b  = (const float*)d_in[2];
    const float* cls    = (const float*)d_in[3];
    const float* ln1g   = (const float*)d_in[4];
    const float* ln1b   = (const float*)d_in[5];
    const float* qkv1w  = (const float*)d_in[6];
    const float* out1w  = (const float*)d_in[7];
    const float* out1b  = (const float*)d_in[8];
    const float* res1w  = (const float*)d_in[9];
    const float* ln2g   = (const float*)d_in[10];
    const float* ln2b   = (const float*)d_in[11];
    const float* qkv2w  = (const float*)d_in[12];
    const float* out2w  = (const float*)d_in[13];
    const float* out2b  = (const float*)d_in[14];
    const float* res2w  = (const float*)d_in[15];
    const float* c7w    = (const float*)d_in[16];
    const float* c7b    = (const float*)d_in[17];
    const float* c5w    = (const float*)d_in[18];
    const float* c5b    = (const float*)d_in[19];
    const float* c3w    = (const float*)d_in[20];
    const float* c3b    = (const float*)d_in[21];
    const float* ng     = (const float*)d_in[22];
    const float* nb     = (const float*)d_in[23];
    const float* fc2w   = (const float*)d_in[24];
    const float* fc2b   = (const float*)d_in[25];
    float* out = (float*)d_out;

    float* hp = symaddr(d_h);

    // fc1 + relu -> tokens 1..6000 of d_h (per batch)
    tf32gemm_k<<<dim3(EMBD/128, (N0 + 127)/128, BB), 256>>>(
        x_path, fc1_w, fc1_b, hp + EMBD, N0, EMBD, 1024,
        (size_t)N0*1024, 0, (size_t)NT*EMBD, 0.f, 1.f, 1.f, 1);
    fill_cls_k<<<(BB*EMBD + 255)/256, 256>>>(cls);
    fill_wrap_k<<<(BB*ADDW*EMBD + 255)/256, 256>>>();

    // layer 1 attention
    attn_layer(ln1g, ln1b, qkv1w, out1w, out1b, res1w);

    // PPEG
    ppeg_k<<<BB*NPIX, 256>>>(c7w, c7b, c5w, c5b, c3w, c3b);
    ppeg_copy_k<<<(int)(((size_t)BB*NPIX*EMBD + 255)/256), 256>>>();

    // layer 2 attention
    attn_layer(ln2g, ln2b, qkv2w, out2w, out2b, res2w);

    // head
    head_k<<<BB, 256>>>(ng, nb, fc2w, fc2b, out);
}

// round 4
// speedup vs baseline: 5.2638x; 3.5142x over previous
#include <cuda_runtime.h>
#include <math.h>
#include <stdint.h>

#define BB   4
#define N0   6000
#define HW   78
#define NPIX (HW*HW)        // 6084
#define ADDW (NPIX - N0)    // 84
#define NT   (NPIX + 1)     // 6085
#define NP   6144
#define PADT (NP - NT)      // 59
#define EMBD 512
#define NH   8
#define DH   64
#define ML   256
#define LWIN (NP/ML)        // 24
#define BH   (BB*NH)        // 32

// -------------------- scratch (device globals, no allocation) --------------------
__device__ float d_h   [(size_t)BB*NT*EMBD];
__device__ float d_xn  [(size_t)BB*NP*EMBD];
__device__ float d_qkv [(size_t)BB*NP*3*EMBD];
__device__ float d_attn[(size_t)BB*NP*EMBD];
__device__ float d_ql  [BH*ML*DH];
__device__ float d_kl  [BH*ML*DH];
__device__ float d_a2  [BH*ML*ML];
__device__ float d_z0  [BH*ML*ML];
__device__ float d_z1  [BH*ML*ML];
__device__ float d_t0  [BH*ML*ML];
__device__ float d_t1  [BH*ML*ML];
__device__ float d_t2  [BH*ML*ML];
__device__ float d_a3v [BH*ML*DH];
__device__ float d_w2  [BH*ML*DH];
__device__ float d_pp  [(size_t)BH*NP*ML];   // 201 MB: holds P3 then P1
__device__ float d_rs  [(size_t)BH*NP];      // row sums
__device__ float d_mx  [2];

__device__ __forceinline__ float dot64(const float* __restrict__ a, const float* __restrict__ kp) {
    float s = 0.f;
#pragma unroll
    for (int i = 0; i < 16; i++) {
        float4 x = *(const float4*)(kp + 4*i);
        s += a[4*i]*x.x + a[4*i+1]*x.y + a[4*i+2]*x.z + a[4*i+3]*x.w;
    }
    return s;
}

__device__ __forceinline__ uint32_t f2tf32(float f) {
    uint32_t r;
    asm("cvt.rna.tf32.f32 %0, %1;" : "=r"(r) : "f"(f));
    return r;
}

__device__ __forceinline__ void mma_tf32(float* c, const uint32_t* a, const uint32_t* b) {
    asm volatile("mma.sync.aligned.m16n8k8.row.col.f32.tf32.tf32.f32 "
        "{%0,%1,%2,%3}, {%4,%5,%6,%7}, {%8,%9}, {%0,%1,%2,%3};"
        : "+f"(c[0]), "+f"(c[1]), "+f"(c[2]), "+f"(c[3])
        : "r"(a[0]), "r"(a[1]), "r"(a[2]), "r"(a[3]), "r"(b[0]), "r"(b[1]));
}

// ==================== tf32 tensor-core GEMM, 128x128x8 double-buffered ====================
// C = sc * ( A @ (cI*I + eB*B) ) + bias, optional relu.
__global__ __launch_bounds__(256) void tf32gemm_k(
    const float* __restrict__ A, const float* __restrict__ B,
    const float* __restrict__ bias, float* __restrict__ C,
    int M, int N, int K, size_t sA, size_t sB, size_t sC,
    float cI, float eB, float sc, int act)
{
    __shared__ uint32_t As[2][8][136];
    __shared__ uint32_t Bs[2][8][136];
    A += (size_t)blockIdx.z * sA;
    B += (size_t)blockIdx.z * sB;
    C += (size_t)blockIdx.z * sC;
    int bm = blockIdx.y * 128, bn = blockIdx.x * 128;
    int tid = threadIdx.x;
    int arow = tid >> 1, acol = (tid & 1) << 2;
    int brow = tid >> 5, bcol = (tid & 31) << 2;
    int wid = tid >> 5, lane = tid & 31;
    int wy = wid >> 2, wx = wid & 3;
    int g = lane >> 2, tg = lane & 3;

    float acc[4][4][4];
#pragma unroll
    for (int mi = 0; mi < 4; mi++)
#pragma unroll
        for (int ni = 0; ni < 4; ni++)
#pragma unroll
            for (int q = 0; q < 4; q++) acc[mi][ni][q] = 0.f;

    int nk = K >> 3;
    int col0 = bn + bcol;

    {
        int r = bm + arow;
        float4 va = make_float4(0.f,0.f,0.f,0.f);
        if (r < M) va = *(const float4*)(A + (size_t)r*K + acol);
        As[0][acol+0][arow] = f2tf32(va.x);
        As[0][acol+1][arow] = f2tf32(va.y);
        As[0][acol+2][arow] = f2tf32(va.z);
        As[0][acol+3][arow] = f2tf32(va.w);
        float4 vb = *(const float4*)(B + (size_t)brow*N + col0);
        float e0 = eB*vb.x, e1 = eB*vb.y, e2 = eB*vb.z, e3 = eB*vb.w;
        if (brow == col0    ) e0 += cI;
        if (brow == col0 + 1) e1 += cI;
        if (brow == col0 + 2) e2 += cI;
        if (brow == col0 + 3) e3 += cI;
        Bs[0][brow][bcol  ] = f2tf32(e0);
        Bs[0][brow][bcol+1] = f2tf32(e1);
        Bs[0][brow][bcol+2] = f2tf32(e2);
        Bs[0][brow][bcol+3] = f2tf32(e3);
    }
    __syncthreads();

    int buf = 0;
    for (int kt = 0; kt < nk; kt++) {
        float4 va, vb;
        bool pf = (kt + 1 < nk);
        if (pf) {
            int k0 = (kt + 1) << 3;
            int r = bm + arow;
            va = make_float4(0.f,0.f,0.f,0.f);
            if (r < M) va = *(const float4*)(A + (size_t)r*K + k0 + acol);
            vb = *(const float4*)(B + (size_t)(k0 + brow)*N + col0);
        }
        uint32_t af[4][4];
#pragma unroll
        for (int mi = 0; mi < 4; mi++) {
            int r0 = wy*64 + mi*16;
            af[mi][0] = As[buf][tg  ][r0 + g];
            af[mi][1] = As[buf][tg  ][r0 + g + 8];
            af[mi][2] = As[buf][tg+4][r0 + g];
            af[mi][3] = As[buf][tg+4][r0 + g + 8];
        }
        uint32_t bfr[4][2];
#pragma unroll
        for (int ni = 0; ni < 4; ni++) {
            int c0 = wx*32 + ni*8;
            bfr[ni][0] = Bs[buf][tg  ][c0 + g];
            bfr[ni][1] = Bs[buf][tg+4][c0 + g];
        }
#pragma unroll
        for (int mi = 0; mi < 4; mi++)
#pragma unroll
            for (int ni = 0; ni < 4; ni++)
                mma_tf32(acc[mi][ni], af[mi], bfr[ni]);

        if (pf) {
            int nb = buf ^ 1;
            int kr = ((kt + 1) << 3) + brow;
            As[nb][acol+0][arow] = f2tf32(va.x);
            As[nb][acol+1][arow] = f2tf32(va.y);
            As[nb][acol+2][arow] = f2tf32(va.z);
            As[nb][acol+3][arow] = f2tf32(va.w);
            float e0 = eB*vb.x, e1 = eB*vb.y, e2 = eB*vb.z, e3 = eB*vb.w;
            if (kr == col0    ) e0 += cI;
            if (kr == col0 + 1) e1 += cI;
            if (kr == col0 + 2) e2 += cI;
            if (kr == col0 + 3) e3 += cI;
            Bs[nb][brow][bcol  ] = f2tf32(e0);
            Bs[nb][brow][bcol+1] = f2tf32(e1);
            Bs[nb][brow][bcol+2] = f2tf32(e2);
            Bs[nb][brow][bcol+3] = f2tf32(e3);
        }
        __syncthreads();
        buf ^= 1;
    }

#pragma unroll
    for (int mi = 0; mi < 4; mi++) {
#pragma unroll
        for (int half = 0; half < 2; half++) {
            int r = bm + wy*64 + mi*16 + g + half*8;
            if (r >= M) continue;
#pragma unroll
            for (int ni = 0; ni < 4; ni++) {
                int c = bn + wx*32 + ni*8 + 2*tg;
                float v0 = sc*acc[mi][ni][half*2+0] + (bias ? bias[c]   : 0.f);
                float v1 = sc*acc[mi][ni][half*2+1] + (bias ? bias[c+1] : 0.f);
                if (act == 1) { v0 = fmaxf(v0, 0.f); v1 = fmaxf(v1, 0.f); }
                *(float2*)(C + (size_t)r*N + c) = make_float2(v0, v1);
            }
        }
    }
}

// ==================== fp32 SGEMM (precision path for last pinv iter) ====================
__global__ __launch_bounds__(256) void sgemm_k(
    const float* __restrict__ A, const float* __restrict__ B,
    const float* __restrict__ bias, float* __restrict__ C,
    int M, int N, int K, size_t sA, size_t sB, size_t sC,
    float cI, float eB, float sc, int act)
{
    __shared__ float As[2][8][132];
    __shared__ float Bs[2][8][132];
    A += (size_t)blockIdx.z * sA;
    B += (size_t)blockIdx.z * sB;
    C += (size_t)blockIdx.z * sC;
    int bm = blockIdx.y * 128, bn = blockIdx.x * 128;
    int tid = threadIdx.x;
    int arow = tid >> 1, acol = (tid & 1) << 2;
    int brow = tid >> 5, bcol = (tid & 31) << 2;
    int ty = tid >> 4, tx = tid & 15;

    float acc[8][8];
#pragma unroll
    for (int i = 0; i < 8; i++)
#pragma unroll
        for (int j = 0; j < 8; j++) acc[i][j] = 0.f;

    int nk = K >> 3;
    int col0 = bn + bcol;

    {
        int r = bm + arow;
        float4 va = make_float4(0.f,0.f,0.f,0.f);
        if (r < M) va = *(const float4*)(A + (size_t)r*K + acol);
        As[0][acol+0][arow] = va.x;
        As[0][acol+1][arow] = va.y;
        As[0][acol+2][arow] = va.z;
        As[0][acol+3][arow] = va.w;
        float4 vb = *(const float4*)(B + (size_t)brow*N + col0);
        float e0 = eB*vb.x, e1 = eB*vb.y, e2 = eB*vb.z, e3 = eB*vb.w;
        if (brow == col0    ) e0 += cI;
        if (brow == col0 + 1) e1 += cI;
        if (brow == col0 + 2) e2 += cI;
        if (brow == col0 + 3) e3 += cI;
        Bs[0][brow][bcol  ] = e0;
        Bs[0][brow][bcol+1] = e1;
        Bs[0][brow][bcol+2] = e2;
        Bs[0][brow][bcol+3] = e3;
    }
    __syncthreads();

    int buf = 0;
    for (int kt = 0; kt < nk; kt++) {
        float4 va, vb;
        bool pf = (kt + 1 < nk);
        if (pf) {
            int k0 = (kt + 1) << 3;
            int r = bm + arow;
            va = make_float4(0.f,0.f,0.f,0.f);
            if (r < M) va = *(const float4*)(A + (size_t)r*K + k0 + acol);
            vb = *(const float4*)(B + (size_t)(k0 + brow)*N + col0);
        }
#pragma unroll
        for (int kk = 0; kk < 8; kk++) {
            float4 a0 = *(const float4*)&As[buf][kk][ty*8];
            float4 a1 = *(const float4*)&As[buf][kk][ty*8 + 4];
            float4 b0 = *(const float4*)&Bs[buf][kk][tx*8];
            float4 b1 = *(const float4*)&Bs[buf][kk][tx*8 + 4];
            float ar[8] = {a0.x,a0.y,a0.z,a0.w,a1.x,a1.y,a1.z,a1.w};
            float br[8] = {b0.x,b0.y,b0.z,b0.w,b1.x,b1.y,b1.z,b1.w};
#pragma unroll
            for (int i = 0; i < 8; i++)
#pragma unroll
                for (int j = 0; j < 8; j++) acc[i][j] += ar[i]*br[j];
        }
        if (pf) {
            int nb = buf ^ 1;
            int kr = ((kt + 1) << 3) + brow;
            As[nb][acol+0][arow] = va.x;
            As[nb][acol+1][arow] = va.y;
            As[nb][acol+2][arow] = va.z;
            As[nb][acol+3][arow] = va.w;
            float e0 = eB*vb.x, e1 = eB*vb.y, e2 = eB*vb.z, e3 = eB*vb.w;
            if (kr == col0    ) e0 += cI;
            if (kr == col0 + 1) e1 += cI;
            if (kr == col0 + 2) e2 += cI;
            if (kr == col0 + 3) e3 += cI;
            Bs[nb][brow][bcol  ] = e0;
            Bs[nb][brow][bcol+1] = e1;
            Bs[nb][brow][bcol+2] = e2;
            Bs[nb][brow][bcol+3] = e3;
        }
        __syncthreads();
        buf ^= 1;
    }

    float bj[8];
#pragma unroll
    for (int j = 0; j < 8; j++) bj[j] = bias ? bias[bn + tx*8 + j] : 0.f;
#pragma unroll
    for (int i = 0; i < 8; i++) {
        int r = bm + ty*8 + i;
        if (r >= M) continue;
        float* Crow = C + (size_t)r*N + bn + tx*8;
#pragma unroll
        for (int j0 = 0; j0 < 8; j0 += 4) {
            float4 v;
            v.x = sc*acc[i][j0+0] + bj[j0+0];
            v.y = sc*acc[i][j0+1] + bj[j0+1];
            v.z = sc*acc[i][j0+2] + bj[j0+2];
            v.w = sc*acc[i][j0+3] + bj[j0+3];
            if (act == 1) {
                v.x = fmaxf(v.x, 0.f); v.y = fmaxf(v.y, 0.f);
                v.z = fmaxf(v.z, 0.f); v.w = fmaxf(v.w, 0.f);
            }
            *(float4*)(Crow + j0) = v;
        }
    }
}

// ==================== score GEMM: P = exp(scaleA*A @ B^T), rowsum atomics ====================
// A: M x 64 (row stride ldA), B: N x 64 (row stride ldB), per batch z offsets.
// P: [z][M][N] (ld N), rs: [z][M]. M,N multiples of 128.
__global__ __launch_bounds__(256) void score_gemm_k(
    const float* __restrict__ Abase, size_t a_sb, size_t a_sh, int ldA, float scaleA,
    const float* __restrict__ Bbase, size_t b_sb, size_t b_sh, int ldB,
    float* __restrict__ P, float* __restrict__ rs, int M, int N)
{
    int z = blockIdx.z;
    int zb = z / NH, zh = z % NH;
    const float* A = Abase + (size_t)zb*a_sb + (size_t)zh*a_sh;
    const float* B = Bbase + (size_t)zb*b_sb + (size_t)zh*b_sh;
    P  += (size_t)z*M*N;
    rs += (size_t)z*M;
    int bm = blockIdx.y*128, bn = blockIdx.x*128;
    __shared__ uint32_t As[32][133];
    __shared__ uint32_t Bs[32][133];
    __shared__ float rsum[128];
    int tid = threadIdx.x;
    int wid = tid >> 5, lane = tid & 31;
    int wy = wid >> 2, wx = wid & 3;
    int g = lane >> 2, tg = lane & 3;

    float acc[4][4][4];
#pragma unroll
    for (int mi = 0; mi < 4; mi++)
#pragma unroll
        for (int ni = 0; ni < 4; ni++)
#pragma unroll
            for (int q = 0; q < 4; q++) acc[mi][ni][q] = 0.f;

    int kcb = (tid & 7) << 2;   // k 0..28 step 4
    int rb  = tid >> 3;         // 0..31

#pragma unroll
    for (int kc = 0; kc < 2; kc++) {
        int kof = kc*32;
#pragma unroll
        for (int rr = 0; rr < 4; rr++) {
            int r = rb + rr*32;
            float4 va = *(const float4*)(A + (size_t)(bm + r)*ldA + kof + kcb);
            As[kcb+0][r] = f2tf32(va.x * scaleA);
            As[kcb+1][r] = f2tf32(va.y * scaleA);
            As[kcb+2][r] = f2tf32(va.z * scaleA);
            As[kcb+3][r] = f2tf32(va.w * scaleA);
            float4 vb = *(const float4*)(B + (size_t)(bn + r)*ldB + kof + kcb);
            Bs[kcb+0][r] = f2tf32(vb.x);
            Bs[kcb+1][r] = f2tf32(vb.y);
            Bs[kcb+2][r] = f2tf32(vb.z);
            Bs[kcb+3][r] = f2tf32(vb.w);
        }
        __syncthreads();
#pragma unroll
        for (int ks = 0; ks < 4; ks++) {
            uint32_t af[4][4], bfr[4][2];
#pragma unroll
            for (int mi = 0; mi < 4; mi++) {
                int r0 = wy*64 + mi*16;
                af[mi][0] = As[ks*8+tg  ][r0 + g];
                af[mi][1] = As[ks*8+tg  ][r0 + g + 8];
                af[mi][2] = As[ks*8+tg+4][r0 + g];
                af[mi][3] = As[ks*8+tg+4][r0 + g + 8];
            }
#pragma unroll
            for (int ni = 0; ni < 4; ni++) {
                int c0 = wx*32 + ni*8;
                bfr[ni][0] = Bs[ks*8+tg  ][c0 + g];
                bfr[ni][1] = Bs[ks*8+tg+4][c0 + g];
            }
#pragma unroll
            for (int mi = 0; mi < 4; mi++)
#pragma unroll
                for (int ni = 0; ni < 4; ni++)
                    mma_tf32(acc[mi][ni], af[mi], bfr[ni]);
        }
        __syncthreads();
    }

    if (tid < 128) rsum[tid] = 0.f;
    __syncthreads();
#pragma unroll
    for (int mi = 0; mi < 4; mi++) {
#pragma unroll
        for (int half = 0; half < 2; half++) {
            int rl = wy*64 + mi*16 + g + half*8;
            int r = bm + rl;
            float rowacc = 0.f;
#pragma unroll
            for (int ni = 0; ni < 4; ni++) {
                int c = bn + wx*32 + ni*8 + 2*tg;
                float v0 = __expf(acc[mi][ni][half*2+0]);
                float v1 = __expf(acc[mi][ni][half*2+1]);
                *(float2*)(P + (size_t)r*N + c) = make_float2(v0, v1);
                rowacc += v0 + v1;
            }
            atomicAdd(&rsum[rl], rowacc);
        }
    }
    __syncthreads();
    if (tid < 128) atomicAdd(&rs[bm + tid], rsum[tid]);
}

// ==================== out GEMM: C = (A @ B) / rs[row], tile 128x64, optional K-split atomic ====================
__global__ __launch_bounds__(256) void out_gemm_k(
    const float* __restrict__ Abase, size_t a_sb, size_t a_sh, int ldA,
    const float* __restrict__ Bbase, size_t b_sb, size_t b_sh, int ldB,
    float* __restrict__ Cbase, size_t c_sb, size_t c_sh, int ldC,
    const float* __restrict__ rsbase, int M, int kChunk, int useAtomic)
{
    int z = blockIdx.z;
    int zb = z / NH, zh = z % NH;
    const float* A = Abase + (size_t)zb*a_sb + (size_t)zh*a_sh;
    const float* B = Bbase + (size_t)zb*b_sb + (size_t)zh*b_sh;
    float* C = Cbase + (size_t)zb*c_sb + (size_t)zh*c_sh;
    const float* rs = rsbase + (size_t)z*M;
    int bm = blockIdx.y*128;
    int kBeg = blockIdx.x*kChunk;

    __shared__ uint32_t As[2][8][132];
    __shared__ uint32_t Bs[2][8][68];
    int tid = threadIdx.x;
    int arow = tid >> 1, acol = (tid & 1) << 2;
    int brow = tid >> 5, bcol = (tid & 31) << 1;
    int wid = tid >> 5, lane = tid & 31;
    int wy = wid >> 2, wx = wid & 3;       // warp tile 64 x 16
    int g = lane >> 2, tg = lane & 3;

    float acc[4][2][4];
#pragma unroll
    for (int mi = 0; mi < 4; mi++)
#pragma unroll
        for (int ni = 0; ni < 2; ni++)
#pragma unroll
            for (int q = 0; q < 4; q++) acc[mi][ni][q] = 0.f;

    int nk = kChunk >> 3;

    {
        float4 va = *(const float4*)(A + (size_t)(bm + arow)*ldA + kBeg + acol);
        As[0][acol+0][arow] = f2tf32(va.x);
        As[0][acol+1][arow] = f2tf32(va.y);
        As[0][acol+2][arow] = f2tf32(va.z);
        As[0][acol+3][arow] = f2tf32(va.w);
        float2 vb = *(const float2*)(B + (size_t)(kBeg + brow)*ldB + bcol);
        Bs[0][brow][bcol  ] = f2tf32(vb.x);
        Bs[0][brow][bcol+1] = f2tf32(vb.y);
    }
    __syncthreads();

    int buf = 0;
    for (int kt = 0; kt < nk; kt++) {
        float4 va; float2 vb;
        bool pf = (kt + 1 < nk);
        if (pf) {
            int k0 = kBeg + ((kt + 1) << 3);
            va = *(const float4*)(A + (size_t)(bm + arow)*ldA + k0 + acol);
            vb = *(const float2*)(B + (size_t)(k0 + brow)*ldB + bcol);
        }
        uint32_t af[4][4], bfr[2][2];
#pragma unroll
        for (int mi = 0; mi < 4; mi++) {
            int r0 = wy*64 + mi*16;
            af[mi][0] = As[buf][tg  ][r0 + g];
            af[mi][1] = As[buf][tg  ][r0 + g + 8];
            af[mi][2] = As[buf][tg+4][r0 + g];
            af[mi][3] = As[buf][tg+4][r0 + g + 8];
        }
#pragma unroll
        for (int ni = 0; ni < 2; ni++) {
            int c0 = wx*16 + ni*8;
            bfr[ni][0] = Bs[buf][tg  ][c0 + g];
            bfr[ni][1] = Bs[buf][tg+4][c0 + g];
        }
#pragma unroll
        for (int mi = 0; mi < 4; mi++)
#pragma unroll
            for (int ni = 0; ni < 2; ni++)
                mma_tf32(acc[mi][ni], af[mi], bfr[ni]);

        if (pf) {
            int nb = buf ^ 1;
            As[nb][acol+0][arow] = f2tf32(va.x);
            As[nb][acol+1][arow] = f2tf32(va.y);
            As[nb][acol+2][arow] = f2tf32(va.z);
            As[nb][acol+3][arow] = f2tf32(va.w);
            Bs[nb][brow][bcol  ] = f2tf32(vb.x);
            Bs[nb][brow][bcol+1] = f2tf32(vb.y);
        }
        __syncthreads();
        buf ^= 1;
    }

#pragma unroll
    for (int mi = 0; mi < 4; mi++) {
#pragma unroll
        for (int half = 0; half < 2; half++) {
            int r = bm + wy*64 + mi*16 + g + half*8;
            float inv = rsbase ? (1.f / rs[r]) : 1.f;
#pragma unroll
            for (int ni = 0; ni < 2; ni++) {
                int c = wx*16 + ni*8 + 2*tg;
                float v0 = acc[mi][ni][half*2+0] * inv;
                float v1 = acc[mi][ni][half*2+1] * inv;
                if (useAtomic) {
                    atomicAdd(C + (size_t)r*ldC + c,     v0);
                    atomicAdd(C + (size_t)r*ldC + c + 1, v1);
                } else {
                    *(float2*)(C + (size_t)r*ldC + c) = make_float2(v0, v1);
                }
            }
        }
    }
}

// -------------------- small 64-tile batched GEMM (fp32) --------------------
__global__ __launch_bounds__(256) void bgemm_epi(
    const float* __restrict__ A, const float* __restrict__ Bm, float* __restrict__ C,
    int Md, int Nd, int Kd, float cI, float eB, float s)
{
    __shared__ float As[16][64];
    __shared__ float Bs[16][64];
    A  += (size_t)blockIdx.z * Md * Kd;
    Bm += (size_t)blockIdx.z * Kd * Nd;
    C  += (size_t)blockIdx.z * Md * Nd;
    int bm = blockIdx.y * 64, bn = blockIdx.x * 64;
    int tid = threadIdx.x;
    int la_r = tid >> 2, la_c = (tid & 3) << 2;
    int lb_r = tid >> 4, lb_c = (tid & 15) << 2;
    int ty = tid >> 4, tx = tid & 15;
    float acc[4][4];
#pragma unroll
    for (int i = 0; i < 4; i++)
#pragma unroll
        for (int j = 0; j < 4; j++) acc[i][j] = 0.f;

    for (int k0 = 0; k0 < Kd; k0 += 16) {
        float4 av = *(const float4*)(A + (size_t)(bm + la_r)*Kd + k0 + la_c);
        As[la_c  ][la_r] = av.x;
        As[la_c+1][la_r] = av.y;
        As[la_c+2][la_r] = av.z;
        As[la_c+3][la_r] = av.w;
        int kr = k0 + lb_r;
        float4 bv = *(const float4*)(Bm + (size_t)kr*Nd + bn + lb_c);
        float e0 = eB*bv.x, e1 = eB*bv.y, e2 = eB*bv.z, e3 = eB*bv.w;
        int c0 = bn + lb_c;
        if (kr == c0    ) e0 += cI;
        if (kr == c0 + 1) e1 += cI;
        if (kr == c0 + 2) e2 += cI;
        if (kr == c0 + 3) e3 += cI;
        Bs[lb_r][lb_c  ] = e0;
        Bs[lb_r][lb_c+1] = e1;
        Bs[lb_r][lb_c+2] = e2;
        Bs[lb_r][lb_c+3] = e3;
        __syncthreads();
#pragma unroll
        for (int kk = 0; kk < 16; kk++) {
            float a0 = As[kk][ty*4+0], a1 = As[kk][ty*4+1], a2 = As[kk][ty*4+2], a3 = As[kk][ty*4+3];
            float b0 = Bs[kk][tx*4+0], b1 = Bs[kk][tx*4+1], b2 = Bs[kk][tx*4+2], b3 = Bs[kk][tx*4+3];
            acc[0][0]+=a0*b0; acc[0][1]+=a0*b1; acc[0][2]+=a0*b2; acc[0][3]+=a0*b3;
            acc[1][0]+=a1*b0; acc[1][1]+=a1*b1; acc[1][2]+=a1*b2; acc[1][3]+=a1*b3;
            acc[2][0]+=a2*b0; acc[2][1]+=a2*b1; acc[2][2]+=a2*b2; acc[2][3]+=a2*b3;
            acc[3][0]+=a3*b0; acc[3][1]+=a3*b1; acc[3][2]+=a3*b2; acc[3][3]+=a3*b3;
        }
        __syncthreads();
    }
#pragma unroll
    for (int i = 0; i < 4; i++) {
        int r = bm + ty*4 + i;
#pragma unroll
        for (int j = 0; j < 4; j++) {
            int c = bn + tx*4 + j;
            C[(size_t)r*Nd + c] = s * acc[i][j];
        }
    }
}

// -------------------- misc small kernels --------------------
__global__ void fill_cls_k(const float* __restrict__ cls) {
    int i = blockIdx.x*256 + threadIdx.x;
    if (i < BB*EMBD) d_h[(size_t)(i/EMBD)*NT*EMBD + (i % EMBD)] = cls[i % EMBD];
}

__global__ void fill_wrap_k() {
    int i = blockIdx.x*256 + threadIdx.x;
    if (i >= BB*ADDW*EMBD) return;
    int c = i % EMBD; int r = i / EMBD; int j = r % ADDW; int b = r / ADDW;
    d_h[((size_t)(b*NT + 1 + N0 + j))*EMBD + c] = d_h[((size_t)(b*NT + 1 + j))*EMBD + c];
}

__global__ __launch_bounds__(256) void ln_pad_k(const float* __restrict__ g, const float* __restrict__ bp) {
    int row = blockIdx.x; int b = row / NP; int t = row % NP;
    int tid = threadIdx.x;
    float* out = d_xn + (size_t)row*EMBD;
    if (t < PADT) { out[tid] = 0.f; out[tid+256] = 0.f; return; }
    const float* x = d_h + ((size_t)b*NT + (t - PADT))*EMBD;
    float v0 = x[tid], v1 = x[tid+256];
    __shared__ float red[256];
    red[tid] = v0 + v1; __syncthreads();
    for (int o = 128; o > 0; o >>= 1) { if (tid < o) red[tid] += red[tid+o]; __syncthreads(); }
    float mean = red[0] * (1.f/512.f); __syncthreads();
    float e0 = v0 - mean, e1 = v1 - mean;
    red[tid] = e0*e0 + e1*e1; __syncthreads();
    for (int o = 128; o > 0; o >>= 1) { if (tid < o) red[tid] += red[tid+o]; __syncthreads(); }
    float inv = rsqrtf(red[0] * (1.f/512.f) + 1e-5f);
    out[tid]     = e0*inv*g[tid]     + bp[tid];
    out[tid+256] = e1*inv*g[tid+256] + bp[tid+256];
}

__global__ void landmarks_k() {
    int blk = blockIdx.x; int bh = blk >> 8; int i = blk & 255;
    int d = threadIdx.x;  // 64 threads
    int b = bh / NH, h = bh % NH;
    const float* base = d_qkv + ((size_t)(b*NP) + (size_t)i*LWIN)*1536 + h*64 + d;
    float sq = 0.f, sk = 0.f;
#pragma unroll
    for (int j = 0; j < LWIN; j++) { sq += base[(size_t)j*1536]; sk += base[(size_t)j*1536 + 512]; }
    d_ql[((size_t)(bh*ML + i))*DH + d] = sq * (0.125f / LWIN);
    d_kl[((size_t)(bh*ML + i))*DH + d] = sk * (1.f   / LWIN);
}

__global__ __launch_bounds__(256) void a2_k() {
    int blk = blockIdx.x; int bh = blk >> 8; int i = blk & 255;
    int tid = threadIdx.x;
    __shared__ float sq[64];
    __shared__ float red[256];
    if (tid < 64) sq[tid] = d_ql[((size_t)(bh*ML + i))*DH + tid];
    __syncthreads();
    float s = dot64(sq, d_kl + ((size_t)(bh*ML + tid))*DH);
    red[tid] = s; __syncthreads();
    for (int o = 128; o > 0; o >>= 1) { if (tid < o) red[tid] = fmaxf(red[tid], red[tid+o]); __syncthreads(); }
    float m = red[0]; __syncthreads();
    float p = expf(s - m);
    red[tid] = p; __syncthreads();
    for (int o = 128; o > 0; o >>= 1) { if (tid < o) red[tid] += red[tid+o]; __syncthreads(); }
    float Z = red[0];
    d_a2[((size_t)bh << 16) + ((size_t)i << 8) + tid] = p / Z;
}

__global__ void reset_mx_k() { d_mx[0] = 0.f; d_mx[1] = 0.f; }

__global__ __launch_bounds__(256) void a2_stats_k() {
    int bh = blockIdx.x; int tid = threadIdx.x;
    const float* a = d_a2 + ((size_t)bh << 16);
    float cs = 0.f, rs = 0.f;
    for (int i = 0; i < ML; i++) cs += a[(size_t)i*ML + tid];
    for (int j = 0; j < ML; j++) rs += a[(size_t)tid*ML + j];
    __shared__ float red[256];
    red[tid] = cs; __syncthreads();
    for (int o = 128; o > 0; o >>= 1) { if (tid < o) red[tid] = fmaxf(red[tid], red[tid+o]); __syncthreads(); }
    if (tid == 0) atomicMax((int*)&d_mx[1], __float_as_int(red[0]));
    __syncthreads();
    red[tid] = rs; __syncthreads();
    for (int o = 128; o > 0; o >>= 1) { if (tid < o) red[tid] = fmaxf(red[tid], red[tid+o]); __syncthreads(); }
    if (tid == 0) atomicMax((int*)&d_mx[0], __float_as_int(red[0]));
}

__global__ void z_init_k() {
    size_t idx = (size_t)blockIdx.x*256 + threadIdx.x;
    if (idx >= (size_t)BH*ML*ML) return;
    size_t bh = idx >> 16; size_t r = (idx >> 8) & 255; size_t c = idx & 255;
    float denom = d_mx[0] * d_mx[1];
    d_z0[idx] = d_a2[(bh << 16) + (c << 8) + r] / denom;
}

__global__ void conv_res_k(const float* __restrict__ w) {
    size_t idx = (size_t)blockIdx.x*256 + threadIdx.x;
    if (idx >= (size_t)BB*NH*NP*DH) return;
    int dd = idx & 63; size_t r = idx >> 6;
    int t = r % NP; r /= NP; int h = r % NH; int b = (int)(r / NH);
    float s = 0.f;
#pragma unroll
    for (int k = 0; k < 33; k++) {
        int tt = t + k - 16;
        if (tt >= 0 && tt < NP)
            s += d_qkv[((size_t)(b*NP + tt))*1536 + 1024 + h*64 + dd] * w[h*33 + k];
    }
    d_attn[((size_t)(b*NP + t))*EMBD + h*64 + dd] += s;
}

__global__ void add_res_k() {
    size_t idx = (size_t)blockIdx.x*256 + threadIdx.x;
    if (idx >= (size_t)BB*NT*EMBD) return;
    int c = idx % EMBD; size_t r = idx / EMBD; int t = r % NT; int b = (int)(r / NT);
    d_h[idx] += d_xn[((size_t)(b*NP + t + PADT))*EMBD + c];
}

__global__ __launch_bounds__(256) void ppeg_k(
    const float* __restrict__ w7, const float* __restrict__ b7,
    const float* __restrict__ w5, const float* __restrict__ b5,
    const float* __restrict__ w3, const float* __restrict__ b3)
{
    int blk = blockIdx.x; int b = blk / NPIX; int pix = blk % NPIX;
    int i = pix / HW, j = pix % HW;
    int tid = threadIdx.x;
    for (int c = tid; c < EMBD; c += 256) {
        float s = d_h[((size_t)(b*NT + 1 + pix))*EMBD + c] + b7[c] + b5[c] + b3[c];
#pragma unroll
        for (int a = 0; a < 7; a++) {
            int ii = i - 3 + a; if (ii < 0 || ii >= HW) continue;
#pragma unroll
            for (int q = 0; q < 7; q++) {
                int jj = j - 3 + q; if (jj < 0 || jj >= HW) continue;
                s += d_h[((size_t)(b*NT + 1 + ii*HW + jj))*EMBD + c] * w7[c*49 + a*7 + q];
            }
        }
#pragma unroll
        for (int a = 0; a < 5; a++) {
            int ii = i - 2 + a; if (ii < 0 || ii >= HW) continue;
#pragma unroll
            for (int q = 0; q < 5; q++) {
                int jj = j - 2 + q; if (jj < 0 || jj >= HW) continue;
                s += d_h[((size_t)(b*NT + 1 + ii*HW + jj))*EMBD + c] * w5[c*25 + a*5 + q];
            }
        }
#pragma unroll
        for (int a = 0; a < 3; a++) {
            int ii = i - 1 + a; if (ii < 0 || ii >= HW) continue;
#pragma unroll
            for (int q = 0; q < 3; q++) {
                int jj = j - 1 + q; if (jj < 0 || jj >= HW) continue;
                s += d_h[((size_t)(b*NT + 1 + ii*HW + jj))*EMBD + c] * w3[c*9 + a*3 + q];
            }
        }
        d_xn[((size_t)(b*NPIX + pix))*EMBD + c] = s;
    }
}

__global__ void ppeg_copy_k() {
    size_t idx = (size_t)blockIdx.x*256 + threadIdx.x;
    if (idx >= (size_t)BB*NPIX*EMBD) return;
    int c = idx % EMBD; size_t r = idx / EMBD; int pix = r % NPIX; int b = (int)(r / NPIX);
    d_h[((size_t)(b*NT + 1 + pix))*EMBD + c] = d_xn[idx];
}

__global__ __launch_bounds__(256) void head_k(
    const float* __restrict__ g, const float* __restrict__ bp,
    const float* __restrict__ w, const float* __restrict__ bias, float* __restrict__ out)
{
    int b = blockIdx.x; int tid = threadIdx.x;
    __shared__ float xs[512];
    __shared__ float red[256];
    __shared__ float lg[4];
    const float* x = d_h + (size_t)b*NT*EMBD;
    float v0 = x[tid], v1 = x[tid+256];
    red[tid] = v0 + v1; __syncthreads();
    for (int o = 128; o > 0; o >>= 1) { if (tid < o) red[tid] += red[tid+o]; __syncthreads(); }
    float mean = red[0] * (1.f/512.f); __syncthreads();
    float e0 = v0 - mean, e1 = v1 - mean;
    red[tid] = e0*e0 + e1*e1; __syncthreads();
    for (int o = 128; o > 0; o >>= 1) { if (tid < o) red[tid] += red[tid+o]; __syncthreads(); }
    float inv = rsqrtf(red[0] * (1.f/512.f) + 1e-5f);
    xs[tid]     = e0*inv*g[tid]     + bp[tid];
    xs[tid+256] = e1*inv*g[tid+256] + bp[tid+256];
    __syncthreads();
    if (tid < 4) {
        float s = bias[tid];
        for (int k = 0; k < 512; k++) s += xs[k]*w[k*4 + tid];
        lg[tid] = s;
    }
    __syncthreads();
    if (tid == 0) {
        int best = 0; float bv = lg[0];
        for (int k = 1; k < 4; k++) if (lg[k] > bv) { bv = lg[k]; best = k; }
        float S = 1.f;
        for (int k = 0; k < 4; k++) {
            float hz = 1.f / (1.f + expf(-lg[k]));
            out[b*4 + k] = hz;
            S *= (1.f - hz);
            out[16 + b*4 + k] = S;
        }
        out[32 + b] = (float)best;
    }
}

// -------------------- host orchestration --------------------
static float* symaddr(const void* sym) { void* p = nullptr; cudaGetSymbolAddress(&p, sym); return (float*)p; }

static void attn_layer(const float* lng, const float* lnb, const float* qkvw,
                       const float* outw, const float* outb, const float* resw)
{
    float* xnp   = symaddr(d_xn);
    float* qkvp  = symaddr(d_qkv);
    float* attnp = symaddr(d_attn);
    float* a2p   = symaddr(d_a2);
    float* z0p   = symaddr(d_z0);
    float* z1p   = symaddr(d_z1);
    float* t0p   = symaddr(d_t0);
    float* t1p   = symaddr(d_t1);
    float* t2p   = symaddr(d_t2);
    float* a3vp  = symaddr(d_a3v);
    float* w2p   = symaddr(d_w2);
    float* qlp   = symaddr(d_ql);
    float* klp   = symaddr(d_kl);
    float* ppp   = symaddr(d_pp);
    float* rsp   = symaddr(d_rs);

    ln_pad_k<<<BB*NP, 256>>>(lng, lnb);
    tf32gemm_k<<<dim3(1536/128, NP/128, BB), 256>>>(
        xnp, qkvw, nullptr, qkvp, NP, 1536, EMBD,
        (size_t)NP*EMBD, 0, (size_t)NP*1536, 0.f, 1.f, 1.f, 0);
    landmarks_k<<<BH*ML, 64>>>();
    a2_k<<<BH*ML, 256>>>();
    reset_mx_k<<<1, 1>>>();
    a2_stats_k<<<BH, 256>>>();
    z_init_k<<<(BH*ML*ML + 255)/256, 256>>>();

    const size_t SB = (size_t)ML*ML;
    float* zin = z0p; float* zout = z1p;
    for (int it = 0; it < 5; it++) {
        tf32gemm_k<<<dim3(2, 2, BH), 256>>>(a2p, zin, nullptr, t0p, 256, 256, 256, SB, SB, SB, 0.f,  1.f, 1.f,  0);
        tf32gemm_k<<<dim3(2, 2, BH), 256>>>(t0p, t0p, nullptr, t1p, 256, 256, 256, SB, SB, SB, 7.f, -1.f, 1.f,  0);
        tf32gemm_k<<<dim3(2, 2, BH), 256>>>(t0p, t1p, nullptr, t2p, 256, 256, 256, SB, SB, SB, 15.f,-1.f, 1.f,  0);
        tf32gemm_k<<<dim3(2, 2, BH), 256>>>(zin, t2p, nullptr, zout,256, 256, 256, SB, SB, SB, 13.f,-1.f, 0.25f,0);
        float* tmp = zin; zin = zout; zout = tmp;
    }
    sgemm_k<<<dim3(2, 2, BH), 256>>>(a2p, zin, nullptr, t0p, 256, 256, 256, SB, SB, SB, 0.f,  1.f, 1.f,  0);
    sgemm_k<<<dim3(2, 2, BH), 256>>>(t0p, t0p, nullptr, t1p, 256, 256, 256, SB, SB, SB, 7.f, -1.f, 1.f,  0);
    sgemm_k<<<dim3(2, 2, BH), 256>>>(t0p, t1p, nullptr, t2p, 256, 256, 256, SB, SB, SB, 15.f,-1.f, 1.f,  0);
    sgemm_k<<<dim3(2, 2, BH), 256>>>(zin, t2p, nullptr, zout,256, 256, 256, SB, SB, SB, 13.f,-1.f, 0.25f,0);
    { float* tmp = zin; zin = zout; zout = tmp; }
    // zin holds a2_inv (d_z0)

    // ---- a3 path: P3 = exp(ql @ K^T), a3v = (P3 @ V)/rowsum ----
    cudaMemsetAsync(rsp, 0, (size_t)BH*ML*sizeof(float));
    score_gemm_k<<<dim3(NP/128, ML/128, BH), 256>>>(
        qlp, (size_t)NH*ML*DH, (size_t)ML*DH, DH, 1.f,
        qkvp + 512, (size_t)NP*1536, 64, 1536,
        ppp, rsp, ML, NP);
    cudaMemsetAsync(a3vp, 0, (size_t)BH*ML*DH*sizeof(float));
    out_gemm_k<<<dim3(8, ML/128, BH), 256>>>(
        ppp, (size_t)NH*ML*NP, (size_t)ML*NP, NP,
        qkvp + 1024, (size_t)NP*1536, 64, 1536,
        a3vp, (size_t)NH*ML*DH, (size_t)ML*DH, DH,
        rsp, ML, NP/8, 1);
    // w2 = a2_inv @ a3v
    bgemm_epi<<<dim3(1, 4, BH), 256>>>(zin, a3vp, w2p, 256, 64, 256, 0.f, 1.f, 1.f);

    // ---- a1 path: P1 = exp(q*0.125 @ kl^T), attn = (P1 @ w2)/rowsum ----
    cudaMemsetAsync(rsp, 0, (size_t)BH*NP*sizeof(float));
    score_gemm_k<<<dim3(ML/128, NP/128, BH), 256>>>(
        qkvp, (size_t)NP*1536, 64, 1536, 0.125f,
        klp, (size_t)NH*ML*DH, (size_t)ML*DH, DH,
        ppp, rsp, NP, ML);
    out_gemm_k<<<dim3(1, NP/128, BH), 256>>>(
        ppp, (size_t)NH*NP*ML, (size_t)NP*ML, ML,
        w2p, (size_t)NH*ML*DH, (size_t)ML*DH, DH,
        attnp, (size_t)NP*EMBD, 64, EMBD,
        rsp, NP, ML, 0);

    conv_res_k<<<(int)(((size_t)BB*NH*NP*DH + 255)/256), 256>>>(resw);
    tf32gemm_k<<<dim3(EMBD/128, NP/128, BB), 256>>>(
        attnp, outw, outb, xnp, NP, EMBD, EMBD,
        (size_t)NP*EMBD, 0, (size_t)NP*EMBD, 0.f, 1.f, 1.f, 0);
    add_res_k<<<(int)(((size_t)BB*NT*EMBD + 255)/256), 256>>>();
}

extern "C" void kernel_launch(void* const* d_in, const int* in_sizes, int n_in,
                              void* d_out, int out_size)
{
    (void)in_sizes; (void)n_in; (void)out_size;
    const float* x_path = (const float*)d_in[0];
    const float* fc1_w  = (const float*)d_in[1];
    const float* fc1_b  = (const float*)d_in[2];
    const float* cls    = (const float*)d_in[3];
    const float* ln1g   = (const float*)d_in[4];
    const float* ln1b   = (const float*)d_in[5];
    const float* qkv1w  = (const float*)d_in[6];
    const float* out1w  = (const float*)d_in[7];
    const float* out1b  = (const float*)d_in[8];
    const float* res1w  = (const float*)d_in[9];
    const float* ln2g   = (const float*)d_in[10];
    const float* ln2b   = (const float*)d_in[11];
    const float* qkv2w  = (const float*)d_in[12];
    const float* out2w  = (const float*)d_in[13];
    const float* out2b  = (const float*)d_in[14];
    const float* res2w  = (const float*)d_in[15];
    const float* c7w    = (const float*)d_in[16];
    const float* c7b    = (const float*)d_in[17];
    const float* c5w    = (const float*)d_in[18];
    const float* c5b    = (const float*)d_in[19];
    const float* c3w    = (const float*)d_in[20];
    const float* c3b    = (const float*)d_in[21];
    const float* ng     = (const float*)d_in[22];
    const float* nb     = (const float*)d_in[23];
    const float* fc2w   = (const float*)d_in[24];
    const float* fc2b   = (const float*)d_in[25];
    float* out = (float*)d_out;

    float* hp = symaddr(d_h);

    tf32gemm_k<<<dim3(EMBD/128, (N0 + 127)/128, BB), 256>>>(
        x_path, fc1_w, fc1_b, hp + EMBD, N0, EMBD, 1024,
        (size_t)N0*1024, 0, (size_t)NT*EMBD, 0.f, 1.f, 1.f, 1);
    fill_cls_k<<<(BB*EMBD + 255)/256, 256>>>(cls);
    fill_wrap_k<<<(BB*ADDW*EMBD + 255)/256, 256>>>();

    attn_layer(ln1g, ln1b, qkv1w, out1w, out1b, res1w);

    ppeg_k<<<BB*NPIX, 256>>>(c7w, c7b, c5w, c5b, c3w, c3b);
    ppeg_copy_k<<<(int)(((size_t)BB*NPIX*EMBD + 255)/256), 256>>>();

    attn_layer(ln2g, ln2b, qkv2w, out2w, out2b, res2w);

    head_k<<<BB, 256>>>(ng, nb, fc2w, fc2b, out);
}

// round 5
// speedup vs baseline: 7.2568x; 1.3786x over previous
#include <cuda_runtime.h>
#include <math.h>
#include <stdint.h>

#define BB   4
#define N0   6000
#define HW   78
#define NPIX (HW*HW)        // 6084
#define ADDW (NPIX - N0)    // 84
#define NT   (NPIX + 1)     // 6085
#define NP   6144
#define PADT (NP - NT)      // 59
#define EMBD 512
#define NH   8
#define DH   64
#define ML   256
#define LWIN (NP/ML)        // 24
#define BH   (BB*NH)        // 32

// -------------------- scratch (device globals, no allocation) --------------------
__device__ float d_h   [(size_t)BB*NT*EMBD];
__device__ float d_xn  [(size_t)BB*NP*EMBD];
__device__ float d_qkv [(size_t)BB*NP*3*EMBD];
__device__ float d_attn[(size_t)BB*NP*EMBD];
__device__ float d_ql  [BH*ML*DH];
__device__ float d_kl  [BH*ML*DH];
__device__ float d_a2  [BH*ML*ML];
__device__ float d_z0  [BH*ML*ML];
__device__ float d_z1  [BH*ML*ML];
__device__ float d_t0  [BH*ML*ML];
__device__ float d_t1  [BH*ML*ML];
__device__ float d_t2  [BH*ML*ML];
__device__ float d_a3v [BH*ML*DH];
__device__ float d_w2  [BH*ML*DH];
__device__ float d_rs  [BH*ML];
__device__ float d_mx  [2];
__device__ float d_w7t [49*EMBD];
__device__ float d_w5t [25*EMBD];
__device__ float d_w3t [9*EMBD];

__device__ __forceinline__ float dot64(const float* __restrict__ a, const float* __restrict__ kp) {
    float s = 0.f;
#pragma unroll
    for (int i = 0; i < 16; i++) {
        float4 x = *(const float4*)(kp + 4*i);
        s += a[4*i]*x.x + a[4*i+1]*x.y + a[4*i+2]*x.z + a[4*i+3]*x.w;
    }
    return s;
}

__device__ __forceinline__ uint32_t f2tf32(float f) {
    uint32_t r;
    asm("cvt.rna.tf32.f32 %0, %1;" : "=r"(r) : "f"(f));
    return r;
}

__device__ __forceinline__ void mma_tf32(float* c, const uint32_t* a, const uint32_t* b) {
    asm volatile("mma.sync.aligned.m16n8k8.row.col.f32.tf32.tf32.f32 "
        "{%0,%1,%2,%3}, {%4,%5,%6,%7}, {%8,%9}, {%0,%1,%2,%3};"
        : "+f"(c[0]), "+f"(c[1]), "+f"(c[2]), "+f"(c[3])
        : "r"(a[0]), "r"(a[1]), "r"(a[2]), "r"(a[3]), "r"(b[0]), "r"(b[1]));
}

// ==================== tf32 tensor-core GEMM, 128x128x8 double-buffered ====================
// C = sc * ( A @ (cI*I + eB*B) ) + bias, optional relu.
__global__ __launch_bounds__(256) void tf32gemm_k(
    const float* __restrict__ A, const float* __restrict__ B,
    const float* __restrict__ bias, float* __restrict__ C,
    int M, int N, int K, size_t sA, size_t sB, size_t sC,
    float cI, float eB, float sc, int act)
{
    __shared__ uint32_t As[2][8][136];
    __shared__ uint32_t Bs[2][8][136];
    A += (size_t)blockIdx.z * sA;
    B += (size_t)blockIdx.z * sB;
    C += (size_t)blockIdx.z * sC;
    int bm = blockIdx.y * 128, bn = blockIdx.x * 128;
    int tid = threadIdx.x;
    int arow = tid >> 1, acol = (tid & 1) << 2;
    int brow = tid >> 5, bcol = (tid & 31) << 2;
    int wid = tid >> 5, lane = tid & 31;
    int wy = wid >> 2, wx = wid & 3;
    int g = lane >> 2, tg = lane & 3;

    float acc[4][4][4];
#pragma unroll
    for (int mi = 0; mi < 4; mi++)
#pragma unroll
        for (int ni = 0; ni < 4; ni++)
#pragma unroll
            for (int q = 0; q < 4; q++) acc[mi][ni][q] = 0.f;

    int nk = K >> 3;
    int col0 = bn + bcol;

    {
        int r = bm + arow;
        float4 va = make_float4(0.f,0.f,0.f,0.f);
        if (r < M) va = *(const float4*)(A + (size_t)r*K + acol);
        As[0][acol+0][arow] = f2tf32(va.x);
        As[0][acol+1][arow] = f2tf32(va.y);
        As[0][acol+2][arow] = f2tf32(va.z);
        As[0][acol+3][arow] = f2tf32(va.w);
        float4 vb = *(const float4*)(B + (size_t)brow*N + col0);
        float e0 = eB*vb.x, e1 = eB*vb.y, e2 = eB*vb.z, e3 = eB*vb.w;
        if (brow == col0    ) e0 += cI;
        if (brow == col0 + 1) e1 += cI;
        if (brow == col0 + 2) e2 += cI;
        if (brow == col0 + 3) e3 += cI;
        Bs[0][brow][bcol  ] = f2tf32(e0);
        Bs[0][brow][bcol+1] = f2tf32(e1);
        Bs[0][brow][bcol+2] = f2tf32(e2);
        Bs[0][brow][bcol+3] = f2tf32(e3);
    }
    __syncthreads();

    int buf = 0;
    for (int kt = 0; kt < nk; kt++) {
        float4 va, vb;
        bool pf = (kt + 1 < nk);
        if (pf) {
            int k0 = (kt + 1) << 3;
            int r = bm + arow;
            va = make_float4(0.f,0.f,0.f,0.f);
            if (r < M) va = *(const float4*)(A + (size_t)r*K + k0 + acol);
            vb = *(const float4*)(B + (size_t)(k0 + brow)*N + col0);
        }
        uint32_t af[4][4];
#pragma unroll
        for (int mi = 0; mi < 4; mi++) {
            int r0 = wy*64 + mi*16;
            af[mi][0] = As[buf][tg  ][r0 + g];
            af[mi][1] = As[buf][tg  ][r0 + g + 8];
            af[mi][2] = As[buf][tg+4][r0 + g];
            af[mi][3] = As[buf][tg+4][r0 + g + 8];
        }
        uint32_t bfr[4][2];
#pragma unroll
        for (int ni = 0; ni < 4; ni++) {
            int c0 = wx*32 + ni*8;
            bfr[ni][0] = Bs[buf][tg  ][c0 + g];
            bfr[ni][1] = Bs[buf][tg+4][c0 + g];
        }
#pragma unroll
        for (int mi = 0; mi < 4; mi++)
#pragma unroll
            for (int ni = 0; ni < 4; ni++)
                mma_tf32(acc[mi][ni], af[mi], bfr[ni]);

        if (pf) {
            int nb = buf ^ 1;
            int kr = ((kt + 1) << 3) + brow;
            As[nb][acol+0][arow] = f2tf32(va.x);
            As[nb][acol+1][arow] = f2tf32(va.y);
            As[nb][acol+2][arow] = f2tf32(va.z);
            As[nb][acol+3][arow] = f2tf32(va.w);
            float e0 = eB*vb.x, e1 = eB*vb.y, e2 = eB*vb.z, e3 = eB*vb.w;
            if (kr == col0    ) e0 += cI;
            if (kr == col0 + 1) e1 += cI;
            if (kr == col0 + 2) e2 += cI;
            if (kr == col0 + 3) e3 += cI;
            Bs[nb][brow][bcol  ] = f2tf32(e0);
            Bs[nb][brow][bcol+1] = f2tf32(e1);
            Bs[nb][brow][bcol+2] = f2tf32(e2);
            Bs[nb][brow][bcol+3] = f2tf32(e3);
        }
        __syncthreads();
        buf ^= 1;
    }

#pragma unroll
    for (int mi = 0; mi < 4; mi++) {
#pragma unroll
        for (int half = 0; half < 2; half++) {
            int r = bm + wy*64 + mi*16 + g + half*8;
            if (r >= M) continue;
#pragma unroll
            for (int ni = 0; ni < 4; ni++) {
                int c = bn + wx*32 + ni*8 + 2*tg;
                float v0 = sc*acc[mi][ni][half*2+0] + (bias ? bias[c]   : 0.f);
                float v1 = sc*acc[mi][ni][half*2+1] + (bias ? bias[c+1] : 0.f);
                if (act == 1) { v0 = fmaxf(v0, 0.f); v1 = fmaxf(v1, 0.f); }
                *(float2*)(C + (size_t)r*N + c) = make_float2(v0, v1);
            }
        }
    }
}

// ==================== fused attention kernels ====================
// SMEM layout (uint32 words): qs [64][133], Ks [64][133], Vs [128][68], Ps [128][133], rsm [128]
#define SMW_QS 0
#define SMW_KS (64*133)
#define SMW_VS (2*64*133)
#define SMW_PS (2*64*133 + 128*68)
#define SMW_RS (SMW_PS + 128*133)
#define SMEM_FUSED_BYTES ((SMW_RS + 128)*4)

// a3 path: for 128 ql rows, stream K/V chunks of 128 tokens:
//   acc_o += exp(ql @ K^T) @ V, rowsum accumulated; atomic-accumulated to d_a3v/d_rs.
__global__ __launch_bounds__(256) void a3_fused_k() {
    extern __shared__ uint32_t sm[];
    uint32_t* qs = sm + SMW_QS;
    uint32_t* Ks = sm + SMW_KS;
    uint32_t* Vs = sm + SMW_VS;
    uint32_t* Ps = sm + SMW_PS;
    float* rsm = (float*)(sm + SMW_RS);

    int split = blockIdx.x;               // 0..7 column splits
    int bm = blockIdx.y * 128;            // ql row base (ML=256 -> 2)
    int z = blockIdx.z; int zb = z / NH, zh = z % NH;
    int tid = threadIdx.x;
    int wid = tid >> 5, lane = tid & 31;
    int wy = wid >> 2, wx = wid & 3;      // mma1: 2x4 warps, 64x32 each
    int wy2 = wid >> 1, wx2 = wid & 1;    // mma2: 4x2 warps, 32x32 each
    int g = lane >> 2, tg = lane & 3;

    if (tid < 128) rsm[tid] = 0.f;

    for (int i = tid; i < 128*16; i += 256) {
        int row = i >> 4, f4 = (i & 15) << 2;
        float4 v = *(const float4*)(d_ql + ((size_t)(z*ML + bm + row))*DH + f4);
        qs[(f4+0)*133 + row] = f2tf32(v.x);
        qs[(f4+1)*133 + row] = f2tf32(v.y);
        qs[(f4+2)*133 + row] = f2tf32(v.z);
        qs[(f4+3)*133 + row] = f2tf32(v.w);
    }

    float acc_o[2][4][4];
#pragma unroll
    for (int a = 0; a < 2; a++)
#pragma unroll
        for (int b = 0; b < 4; b++)
#pragma unroll
            for (int q = 0; q < 4; q++) acc_o[a][b][q] = 0.f;
    float rs_loc[8];
#pragma unroll
    for (int a = 0; a < 8; a++) rs_loc[a] = 0.f;

    for (int ci = 0; ci < 6; ci++) {
        int c0 = split*768 + ci*128;
        for (int i = tid; i < 128*16; i += 256) {
            int tok = i >> 4, f4 = (i & 15) << 2;
            const float* kvb = d_qkv + ((size_t)(zb*NP + c0 + tok))*1536 + zh*64 + f4;
            float4 kv = *(const float4*)(kvb + 512);
            Ks[(f4+0)*133 + tok] = f2tf32(kv.x);
            Ks[(f4+1)*133 + tok] = f2tf32(kv.y);
            Ks[(f4+2)*133 + tok] = f2tf32(kv.z);
            Ks[(f4+3)*133 + tok] = f2tf32(kv.w);
            float4 vv = *(const float4*)(kvb + 1024);
            Vs[tok*68 + f4+0] = f2tf32(vv.x);
            Vs[tok*68 + f4+1] = f2tf32(vv.y);
            Vs[tok*68 + f4+2] = f2tf32(vv.z);
            Vs[tok*68 + f4+3] = f2tf32(vv.w);
        }
        __syncthreads();

        float acc_s[4][4][4];
#pragma unroll
        for (int a = 0; a < 4; a++)
#pragma unroll
            for (int b = 0; b < 4; b++)
#pragma unroll
                for (int q = 0; q < 4; q++) acc_s[a][b][q] = 0.f;

#pragma unroll
        for (int ks = 0; ks < 8; ks++) {
            uint32_t af[4][4], bfr[4][2];
#pragma unroll
            for (int mi = 0; mi < 4; mi++) {
                int r0 = wy*64 + mi*16;
                af[mi][0] = qs[(ks*8+tg  )*133 + r0 + g];
                af[mi][1] = qs[(ks*8+tg  )*133 + r0 + g + 8];
                af[mi][2] = qs[(ks*8+tg+4)*133 + r0 + g];
                af[mi][3] = qs[(ks*8+tg+4)*133 + r0 + g + 8];
            }
#pragma unroll
            for (int ni = 0; ni < 4; ni++) {
                int cw = wx*32 + ni*8;
                bfr[ni][0] = Ks[(ks*8+tg  )*133 + cw + g];
                bfr[ni][1] = Ks[(ks*8+tg+4)*133 + cw + g];
            }
#pragma unroll
            for (int mi = 0; mi < 4; mi++)
#pragma unroll
                for (int ni = 0; ni < 4; ni++)
                    mma_tf32(acc_s[mi][ni], af[mi], bfr[ni]);
        }

#pragma unroll
        for (int mi = 0; mi < 4; mi++)
#pragma unroll
            for (int half = 0; half < 2; half++) {
                int rl = wy*64 + mi*16 + half*8 + g;
                float ra = 0.f;
#pragma unroll
                for (int ni = 0; ni < 4; ni++) {
                    int cc = wx*32 + ni*8 + 2*tg;
                    float v0 = __expf(acc_s[mi][ni][half*2+0]);
                    float v1 = __expf(acc_s[mi][ni][half*2+1]);
                    Ps[cc*133 + rl]     = f2tf32(v0);
                    Ps[(cc+1)*133 + rl] = f2tf32(v1);
                    ra += v0 + v1;
                }
                rs_loc[mi*2 + half] += ra;
            }
        __syncthreads();

#pragma unroll
        for (int ks = 0; ks < 16; ks++) {
            uint32_t af2[2][4], bf2[4][2];
#pragma unroll
            for (int mi2 = 0; mi2 < 2; mi2++) {
                int m0 = wy2*32 + mi2*16;
                af2[mi2][0] = Ps[(ks*8+tg  )*133 + m0 + g];
                af2[mi2][1] = Ps[(ks*8+tg  )*133 + m0 + g + 8];
                af2[mi2][2] = Ps[(ks*8+tg+4)*133 + m0 + g];
                af2[mi2][3] = Ps[(ks*8+tg+4)*133 + m0 + g + 8];
            }
#pragma unroll
            for (int ni2 = 0; ni2 < 4; ni2++) {
                int cw = wx2*32 + ni2*8;
                bf2[ni2][0] = Vs[(ks*8+tg  )*68 + cw + g];
                bf2[ni2][1] = Vs[(ks*8+tg+4)*68 + cw + g];
            }
#pragma unroll
            for (int mi2 = 0; mi2 < 2; mi2++)
#pragma unroll
                for (int ni2 = 0; ni2 < 4; ni2++)
                    mma_tf32(acc_o[mi2][ni2], af2[mi2], bf2[ni2]);
        }
        __syncthreads();
    }

#pragma unroll
    for (int j2 = 0; j2 < 8; j2++) {
        int rl = wy*64 + (j2>>1)*16 + (j2&1)*8 + g;
        atomicAdd(&rsm[rl], rs_loc[j2]);
    }
    __syncthreads();
    if (tid < 128) atomicAdd(d_rs + (size_t)z*ML + bm + tid, rsm[tid]);
#pragma unroll
    for (int mi2 = 0; mi2 < 2; mi2++)
#pragma unroll
        for (int half = 0; half < 2; half++) {
            int m = wy2*32 + mi2*16 + half*8 + g;
#pragma unroll
            for (int ni2 = 0; ni2 < 4; ni2++) {
                int cc = wx2*32 + ni2*8 + 2*tg;
                float* dst = d_a3v + ((size_t)(z*ML + bm + m))*DH + cc;
                atomicAdd(dst,     acc_o[mi2][ni2][half*2+0]);
                atomicAdd(dst + 1, acc_o[mi2][ni2][half*2+1]);
            }
        }
}

// a1 path: for 128 tokens, 2 landmark chunks:
//   acc_o += exp(0.125*q @ kl^T) @ w2; divide by rowsum; write d_attn slice.
__global__ __launch_bounds__(256) void a1_fused_k() {
    extern __shared__ uint32_t sm[];
    uint32_t* qs = sm + SMW_QS;
    uint32_t* Ks = sm + SMW_KS;   // kl chunk [d][lm]
    uint32_t* Vs = sm + SMW_VS;   // w2 chunk [lm][d]
    uint32_t* Ps = sm + SMW_PS;
    float* rsm = (float*)(sm + SMW_RS);

    int bm = blockIdx.x * 128;    // token base
    int z = blockIdx.y; int zb = z / NH, zh = z % NH;
    int tid = threadIdx.x;
    int wid = tid >> 5, lane = tid & 31;
    int wy = wid >> 2, wx = wid & 3;
    int wy2 = wid >> 1, wx2 = wid & 1;
    int g = lane >> 2, tg = lane & 3;

    if (tid < 128) rsm[tid] = 0.f;

    for (int i = tid; i < 128*16; i += 256) {
        int row = i >> 4, f4 = (i & 15) << 2;
        float4 v = *(const float4*)(d_qkv + ((size_t)(zb*NP + bm + row))*1536 + zh*64 + f4);
        qs[(f4+0)*133 + row] = f2tf32(v.x * 0.125f);
        qs[(f4+1)*133 + row] = f2tf32(v.y * 0.125f);
        qs[(f4+2)*133 + row] = f2tf32(v.z * 0.125f);
        qs[(f4+3)*133 + row] = f2tf32(v.w * 0.125f);
    }

    float acc_o[2][4][4];
#pragma unroll
    for (int a = 0; a < 2; a++)
#pragma unroll
        for (int b = 0; b < 4; b++)
#pragma unroll
            for (int q = 0; q < 4; q++) acc_o[a][b][q] = 0.f;
    float rs_loc[8];
#pragma unroll
    for (int a = 0; a < 8; a++) rs_loc[a] = 0.f;

    for (int lc = 0; lc < 2; lc++) {
        for (int i = tid; i < 128*16; i += 256) {
            int lm = i >> 4, f4 = (i & 15) << 2;
            const float* kb = d_kl + ((size_t)(z*ML + lc*128 + lm))*DH + f4;
            float4 kv = *(const float4*)kb;
            Ks[(f4+0)*133 + lm] = f2tf32(kv.x);
            Ks[(f4+1)*133 + lm] = f2tf32(kv.y);
            Ks[(f4+2)*133 + lm] = f2tf32(kv.z);
            Ks[(f4+3)*133 + lm] = f2tf32(kv.w);
            const float* wb = d_w2 + ((size_t)(z*ML + lc*128 + lm))*DH + f4;
            float4 wv = *(const float4*)wb;
            Vs[lm*68 + f4+0] = f2tf32(wv.x);
            Vs[lm*68 + f4+1] = f2tf32(wv.y);
            Vs[lm*68 + f4+2] = f2tf32(wv.z);
            Vs[lm*68 + f4+3] = f2tf32(wv.w);
        }
        __syncthreads();

        float acc_s[4][4][4];
#pragma unroll
        for (int a = 0; a < 4; a++)
#pragma unroll
            for (int b = 0; b < 4; b++)
#pragma unroll
                for (int q = 0; q < 4; q++) acc_s[a][b][q] = 0.f;

#pragma unroll
        for (int ks = 0; ks < 8; ks++) {
            uint32_t af[4][4], bfr[4][2];
#pragma unroll
            for (int mi = 0; mi < 4; mi++) {
                int r0 = wy*64 + mi*16;
                af[mi][0] = qs[(ks*8+tg  )*133 + r0 + g];
                af[mi][1] = qs[(ks*8+tg  )*133 + r0 + g + 8];
                af[mi][2] = qs[(ks*8+tg+4)*133 + r0 + g];
                af[mi][3] = qs[(ks*8+tg+4)*133 + r0 + g + 8];
            }
#pragma unroll
            for (int ni = 0; ni < 4; ni++) {
                int cw = wx*32 + ni*8;
                bfr[ni][0] = Ks[(ks*8+tg  )*133 + cw + g];
                bfr[ni][1] = Ks[(ks*8+tg+4)*133 + cw + g];
            }
#pragma unroll
            for (int mi = 0; mi < 4; mi++)
#pragma unroll
                for (int ni = 0; ni < 4; ni++)
                    mma_tf32(acc_s[mi][ni], af[mi], bfr[ni]);
        }

#pragma unroll
        for (int mi = 0; mi < 4; mi++)
#pragma unroll
            for (int half = 0; half < 2; half++) {
                int rl = wy*64 + mi*16 + half*8 + g;
                float ra = 0.f;
#pragma unroll
                for (int ni = 0; ni < 4; ni++) {
                    int cc = wx*32 + ni*8 + 2*tg;
                    float v0 = __expf(acc_s[mi][ni][half*2+0]);
                    float v1 = __expf(acc_s[mi][ni][half*2+1]);
                    Ps[cc*133 + rl]     = f2tf32(v0);
                    Ps[(cc+1)*133 + rl] = f2tf32(v1);
                    ra += v0 + v1;
                }
                rs_loc[mi*2 + half] += ra;
            }
        __syncthreads();

#pragma unroll
        for (int ks = 0; ks < 16; ks++) {
            uint32_t af2[2][4], bf2[4][2];
#pragma unroll
            for (int mi2 = 0; mi2 < 2; mi2++) {
                int m0 = wy2*32 + mi2*16;
                af2[mi2][0] = Ps[(ks*8+tg  )*133 + m0 + g];
                af2[mi2][1] = Ps[(ks*8+tg  )*133 + m0 + g + 8];
                af2[mi2][2] = Ps[(ks*8+tg+4)*133 + m0 + g];
                af2[mi2][3] = Ps[(ks*8+tg+4)*133 + m0 + g + 8];
            }
#pragma unroll
            for (int ni2 = 0; ni2 < 4; ni2++) {
                int cw = wx2*32 + ni2*8;
                bf2[ni2][0] = Vs[(ks*8+tg  )*68 + cw + g];
                bf2[ni2][1] = Vs[(ks*8+tg+4)*68 + cw + g];
            }
#pragma unroll
            for (int mi2 = 0; mi2 < 2; mi2++)
#pragma unroll
                for (int ni2 = 0; ni2 < 4; ni2++)
                    mma_tf32(acc_o[mi2][ni2], af2[mi2], bf2[ni2]);
        }
        __syncthreads();
    }

#pragma unroll
    for (int j2 = 0; j2 < 8; j2++) {
        int rl = wy*64 + (j2>>1)*16 + (j2&1)*8 + g;
        atomicAdd(&rsm[rl], rs_loc[j2]);
    }
    __syncthreads();
#pragma unroll
    for (int mi2 = 0; mi2 < 2; mi2++)
#pragma unroll
        for (int half = 0; half < 2; half++) {
            int m = wy2*32 + mi2*16 + half*8 + g;
            float inv = 1.f / rsm[m];
#pragma unroll
            for (int ni2 = 0; ni2 < 4; ni2++) {
                int cc = wx2*32 + ni2*8 + 2*tg;
                *(float2*)(d_attn + ((size_t)(zb*NP + bm + m))*EMBD + zh*64 + cc) =
                    make_float2(acc_o[mi2][ni2][half*2+0]*inv, acc_o[mi2][ni2][half*2+1]*inv);
            }
        }
}

// -------------------- small 64-tile batched GEMM (fp32) with optional B row-scale --------------------
__global__ __launch_bounds__(256) void bgemm_epi(
    const float* __restrict__ A, const float* __restrict__ Bm, float* __restrict__ C,
    int Md, int Nd, int Kd, float cI, float eB, float s, const float* __restrict__ rsc)
{
    __shared__ float As[16][64];
    __shared__ float Bs[16][64];
    A  += (size_t)blockIdx.z * Md * Kd;
    Bm += (size_t)blockIdx.z * Kd * Nd;
    C  += (size_t)blockIdx.z * Md * Nd;
    const float* rscz = rsc ? rsc + (size_t)blockIdx.z * Kd : nullptr;
    int bm = blockIdx.y * 64, bn = blockIdx.x * 64;
    int tid = threadIdx.x;
    int la_r = tid >> 2, la_c = (tid & 3) << 2;
    int lb_r = tid >> 4, lb_c = (tid & 15) << 2;
    int ty = tid >> 4, tx = tid & 15;
    float acc[4][4];
#pragma unroll
    for (int i = 0; i < 4; i++)
#pragma unroll
        for (int j = 0; j < 4; j++) acc[i][j] = 0.f;

    for (int k0 = 0; k0 < Kd; k0 += 16) {
        float4 av = *(const float4*)(A + (size_t)(bm + la_r)*Kd + k0 + la_c);
        As[la_c  ][la_r] = av.x;
        As[la_c+1][la_r] = av.y;
        As[la_c+2][la_r] = av.z;
        As[la_c+3][la_r] = av.w;
        int kr = k0 + lb_r;
        float4 bv = *(const float4*)(Bm + (size_t)kr*Nd + bn + lb_c);
        float rsv = rscz ? (1.f / rscz[kr]) : 1.f;
        float e0 = eB*rsv*bv.x, e1 = eB*rsv*bv.y, e2 = eB*rsv*bv.z, e3 = eB*rsv*bv.w;
        int c0 = bn + lb_c;
        if (kr == c0    ) e0 += cI;
        if (kr == c0 + 1) e1 += cI;
        if (kr == c0 + 2) e2 += cI;
        if (kr == c0 + 3) e3 += cI;
        Bs[lb_r][lb_c  ] = e0;
        Bs[lb_r][lb_c+1] = e1;
        Bs[lb_r][lb_c+2] = e2;
        Bs[lb_r][lb_c+3] = e3;
        __syncthreads();
#pragma unroll
        for (int kk = 0; kk < 16; kk++) {
            float a0 = As[kk][ty*4+0], a1 = As[kk][ty*4+1], a2 = As[kk][ty*4+2], a3 = As[kk][ty*4+3];
            float b0 = Bs[kk][tx*4+0], b1 = Bs[kk][tx*4+1], b2 = Bs[kk][tx*4+2], b3 = Bs[kk][tx*4+3];
            acc[0][0]+=a0*b0; acc[0][1]+=a0*b1; acc[0][2]+=a0*b2; acc[0][3]+=a0*b3;
            acc[1][0]+=a1*b0; acc[1][1]+=a1*b1; acc[1][2]+=a1*b2; acc[1][3]+=a1*b3;
            acc[2][0]+=a2*b0; acc[2][1]+=a2*b1; acc[2][2]+=a2*b2; acc[2][3]+=a2*b3;
            acc[3][0]+=a3*b0; acc[3][1]+=a3*b1; acc[3][2]+=a3*b2; acc[3][3]+=a3*b3;
        }
        __syncthreads();
    }
#pragma unroll
    for (int i = 0; i < 4; i++) {
        int r = bm + ty*4 + i;
#pragma unroll
        for (int j = 0; j < 4; j++) {
            int c = bn + tx*4 + j;
            C[(size_t)r*Nd + c] = s * acc[i][j];
        }
    }
}

// -------------------- misc small kernels --------------------
__global__ void fill_cls_k(const float* __restrict__ cls) {
    int i = blockIdx.x*256 + threadIdx.x;
    if (i < BB*EMBD) d_h[(size_t)(i/EMBD)*NT*EMBD + (i % EMBD)] = cls[i % EMBD];
}

__global__ void fill_wrap_k() {
    int i = blockIdx.x*256 + threadIdx.x;
    if (i >= BB*ADDW*EMBD) return;
    int c = i % EMBD; int r = i / EMBD; int j = r % ADDW; int b = r / ADDW;
    d_h[((size_t)(b*NT + 1 + N0 + j))*EMBD + c] = d_h[((size_t)(b*NT + 1 + j))*EMBD + c];
}

__global__ __launch_bounds__(256) void ln_pad_k(const float* __restrict__ g, const float* __restrict__ bp) {
    int row = blockIdx.x; int b = row / NP; int t = row % NP;
    int tid = threadIdx.x;
    float* out = d_xn + (size_t)row*EMBD;
    if (t < PADT) { out[tid] = 0.f; out[tid+256] = 0.f; return; }
    const float* x = d_h + ((size_t)b*NT + (t - PADT))*EMBD;
    float v0 = x[tid], v1 = x[tid+256];
    __shared__ float red[256];
    red[tid] = v0 + v1; __syncthreads();
    for (int o = 128; o > 0; o >>= 1) { if (tid < o) red[tid] += red[tid+o]; __syncthreads(); }
    float mean = red[0] * (1.f/512.f); __syncthreads();
    float e0 = v0 - mean, e1 = v1 - mean;
    red[tid] = e0*e0 + e1*e1; __syncthreads();
    for (int o = 128; o > 0; o >>= 1) { if (tid < o) red[tid] += red[tid+o]; __syncthreads(); }
    float inv = rsqrtf(red[0] * (1.f/512.f) + 1e-5f);
    out[tid]     = e0*inv*g[tid]     + bp[tid];
    out[tid+256] = e1*inv*g[tid+256] + bp[tid+256];
}

__global__ void landmarks_k() {
    int blk = blockIdx.x; int bh = blk >> 8; int i = blk & 255;
    int d = threadIdx.x;  // 64 threads
    int b = bh / NH, h = bh % NH;
    const float* base = d_qkv + ((size_t)(b*NP) + (size_t)i*LWIN)*1536 + h*64 + d;
    float sq = 0.f, sk = 0.f;
#pragma unroll
    for (int j = 0; j < LWIN; j++) { sq += base[(size_t)j*1536]; sk += base[(size_t)j*1536 + 512]; }
    d_ql[((size_t)(bh*ML + i))*DH + d] = sq * (0.125f / LWIN);
    d_kl[((size_t)(bh*ML + i))*DH + d] = sk * (1.f   / LWIN);
}

__global__ __launch_bounds__(256) void a2_k() {
    int blk = blockIdx.x; int bh = blk >> 8; int i = blk & 255;
    int tid = threadIdx.x;
    __shared__ float sq[64];
    __shared__ float red[256];
    if (tid < 64) sq[tid] = d_ql[((size_t)(bh*ML + i))*DH + tid];
    __syncthreads();
    float s = dot64(sq, d_kl + ((size_t)(bh*ML + tid))*DH);
    red[tid] = s; __syncthreads();
    for (int o = 128; o > 0; o >>= 1) { if (tid < o) red[tid] = fmaxf(red[tid], red[tid+o]); __syncthreads(); }
    float m = red[0]; __syncthreads();
    float p = expf(s - m);
    red[tid] = p; __syncthreads();
    for (int o = 128; o > 0; o >>= 1) { if (tid < o) red[tid] += red[tid+o]; __syncthreads(); }
    float Z = red[0];
    d_a2[((size_t)bh << 16) + ((size_t)i << 8) + tid] = p / Z;
}

__global__ void reset_mx_k() { d_mx[0] = 0.f; d_mx[1] = 0.f; }

__global__ __launch_bounds__(256) void a2_stats_k() {
    int bh = blockIdx.x; int tid = threadIdx.x;
    const float* a = d_a2 + ((size_t)bh << 16);
    float cs = 0.f, rs = 0.f;
    for (int i = 0; i < ML; i++) cs += a[(size_t)i*ML + tid];
    for (int j = 0; j < ML; j++) rs += a[(size_t)tid*ML + j];
    __shared__ float red[256];
    red[tid] = cs; __syncthreads();
    for (int o = 128; o > 0; o >>= 1) { if (tid < o) red[tid] = fmaxf(red[tid], red[tid+o]); __syncthreads(); }
    if (tid == 0) atomicMax((int*)&d_mx[1], __float_as_int(red[0]));
    __syncthreads();
    red[tid] = rs; __syncthreads();
    for (int o = 128; o > 0; o >>= 1) { if (tid < o) red[tid] = fmaxf(red[tid], red[tid+o]); __syncthreads(); }
    if (tid == 0) atomicMax((int*)&d_mx[0], __float_as_int(red[0]));
}

__global__ void z_init_k() {
    size_t idx = (size_t)blockIdx.x*256 + threadIdx.x;
    if (idx >= (size_t)BH*ML*ML) return;
    size_t bh = idx >> 16; size_t r = (idx >> 8) & 255; size_t c = idx & 255;
    float denom = d_mx[0] * d_mx[1];
    d_z0[idx] = d_a2[(bh << 16) + (c << 8) + r] / denom;
}

__global__ void conv_res_k(const float* __restrict__ w) {
    size_t idx = (size_t)blockIdx.x*256 + threadIdx.x;
    if (idx >= (size_t)BB*NH*NP*16) return;
    int d4 = (int)(idx & 15) << 2; size_t r = idx >> 4;
    int t = (int)(r % NP); r /= NP; int h = (int)(r % NH); int b = (int)(r / NH);
    float4 s = make_float4(0.f,0.f,0.f,0.f);
#pragma unroll
    for (int k = 0; k < 33; k++) {
        int tt = t + k - 16;
        if (tt >= 0 && tt < NP) {
            float4 v = *(const float4*)(d_qkv + ((size_t)(b*NP + tt))*1536 + 1024 + h*64 + d4);
            float wk = w[h*33 + k];
            s.x += v.x*wk; s.y += v.y*wk; s.z += v.z*wk; s.w += v.w*wk;
        }
    }
    float4* dst = (float4*)(d_attn + ((size_t)(b*NP + t))*EMBD + h*64 + d4);
    float4 cur = *dst;
    cur.x += s.x; cur.y += s.y; cur.z += s.z; cur.w += s.w;
    *dst = cur;
}

__global__ void add_res_k() {
    size_t idx = (size_t)blockIdx.x*256 + threadIdx.x;
    if (idx >= (size_t)BB*NT*EMBD) return;
    int c = idx % EMBD; size_t r = idx / EMBD; int t = r % NT; int b = (int)(r / NT);
    d_h[idx] += d_xn[((size_t)(b*NP + t + PADT))*EMBD + c];
}

// weight transpose for PPEG: [c][tap] -> [tap][c]
__global__ void wtrans_k(const float* __restrict__ w7, const float* __restrict__ w5,
                         const float* __restrict__ w3) {
    int i = blockIdx.x*256 + threadIdx.x;
    if (i < 49*EMBD) { int c = i / 49, t = i % 49; d_w7t[t*EMBD + c] = w7[i]; }
    if (i < 25*EMBD) { int c = i / 25, t = i % 25; d_w5t[t*EMBD + c] = w5[i]; }
    if (i < 9*EMBD)  { int c = i / 9,  t = i % 9;  d_w3t[t*EMBD + c] = w3[i]; }
}

__global__ __launch_bounds__(128) void ppeg2_k(
    const float* __restrict__ b7, const float* __restrict__ b5, const float* __restrict__ b3)
{
    int blk = blockIdx.x; int b = blk / NPIX; int pix = blk % NPIX;
    int i = pix / HW, j = pix % HW;
    int c = threadIdx.x << 2;
    const float* hbase = d_h + ((size_t)(b*NT + 1))*EMBD + c;
    float4 s = *(const float4*)(hbase + (size_t)pix*EMBD);
    {
        float4 x7 = *(const float4*)(b7 + c);
        float4 x5 = *(const float4*)(b5 + c);
        float4 x3 = *(const float4*)(b3 + c);
        s.x += x7.x + x5.x + x3.x; s.y += x7.y + x5.y + x3.y;
        s.z += x7.z + x5.z + x3.z; s.w += x7.w + x5.w + x3.w;
    }
#pragma unroll
    for (int a = 0; a < 7; a++) {
        int ii = i - 3 + a; if (ii < 0 || ii >= HW) continue;
#pragma unroll
        for (int q = 0; q < 7; q++) {
            int jj = j - 3 + q; if (jj < 0 || jj >= HW) continue;
            float4 x = *(const float4*)(hbase + (size_t)(ii*HW + jj)*EMBD);
            float4 w = *(const float4*)(d_w7t + (a*7 + q)*EMBD + c);
            s.x += x.x*w.x; s.y += x.y*w.y; s.z += x.z*w.z; s.w += x.w*w.w;
        }
    }
#pragma unroll
    for (int a = 0; a < 5; a++) {
        int ii = i - 2 + a; if (ii < 0 || ii >= HW) continue;
#pragma unroll
        for (int q = 0; q < 5; q++) {
            int jj = j - 2 + q; if (jj < 0 || jj >= HW) continue;
            float4 x = *(const float4*)(hbase + (size_t)(ii*HW + jj)*EMBD);
            float4 w = *(const float4*)(d_w5t + (a*5 + q)*EMBD + c);
            s.x += x.x*w.x; s.y += x.y*w.y; s.z += x.z*w.z; s.w += x.w*w.w;
        }
    }
#pragma unroll
    for (int a = 0; a < 3; a++) {
        int ii = i - 1 + a; if (ii < 0 || ii >= HW) continue;
#pragma unroll
        for (int q = 0; q < 3; q++) {
            int jj = j - 1 + q; if (jj < 0 || jj >= HW) continue;
            float4 x = *(const float4*)(hbase + (size_t)(ii*HW + jj)*EMBD);
            float4 w = *(const float4*)(d_w3t + (a*3 + q)*EMBD + c);
            s.x += x.x*w.x; s.y += x.y*w.y; s.z += x.z*w.z; s.w += x.w*w.w;
        }
    }
    *(float4*)(d_xn + ((size_t)(b*NPIX + pix))*EMBD + c) = s;
}

__global__ void ppeg_copy_k() {
    size_t idx = (size_t)blockIdx.x*256 + threadIdx.x;
    if (idx >= (size_t)BB*NPIX*EMBD) return;
    int c = idx % EMBD; size_t r = idx / EMBD; int pix = r % NPIX; int b = (int)(r / NPIX);
    d_h[((size_t)(b*NT + 1 + pix))*EMBD + c] = d_xn[idx];
}

__global__ __launch_bounds__(256) void head_k(
    const float* __restrict__ g, const float* __restrict__ bp,
    const float* __restrict__ w, const float* __restrict__ bias, float* __restrict__ out)
{
    int b = blockIdx.x; int tid = threadIdx.x;
    __shared__ float xs[512];
    __shared__ float red[256];
    __shared__ float lg[4];
    const float* x = d_h + (size_t)b*NT*EMBD;
    float v0 = x[tid], v1 = x[tid+256];
    red[tid] = v0 + v1; __syncthreads();
    for (int o = 128; o > 0; o >>= 1) { if (tid < o) red[tid] += red[tid+o]; __syncthreads(); }
    float mean = red[0] * (1.f/512.f); __syncthreads();
    float e0 = v0 - mean, e1 = v1 - mean;
    red[tid] = e0*e0 + e1*e1; __syncthreads();
    for (int o = 128; o > 0; o >>= 1) { if (tid < o) red[tid] += red[tid+o]; __syncthreads(); }
    float inv = rsqrtf(red[0] * (1.f/512.f) + 1e-5f);
    xs[tid]     = e0*inv*g[tid]     + bp[tid];
    xs[tid+256] = e1*inv*g[tid+256] + bp[tid+256];
    __syncthreads();
    if (tid < 4) {
        float s = bias[tid];
        for (int k = 0; k < 512; k++) s += xs[k]*w[k*4 + tid];
        lg[tid] = s;
    }
    __syncthreads();
    if (tid == 0) {
        int best = 0; float bv = lg[0];
        for (int k = 1; k < 4; k++) if (lg[k] > bv) { bv = lg[k]; best = k; }
        float S = 1.f;
        for (int k = 0; k < 4; k++) {
            float hz = 1.f / (1.f + expf(-lg[k]));
            out[b*4 + k] = hz;
            S *= (1.f - hz);
            out[16 + b*4 + k] = S;
        }
        out[32 + b] = (float)best;
    }
}

// -------------------- host orchestration --------------------
static float* symaddr(const void* sym) { void* p = nullptr; cudaGetSymbolAddress(&p, sym); return (float*)p; }

static void attn_layer(const float* lng, const float* lnb, const float* qkvw,
                       const float* outw, const float* outb, const float* resw)
{
    float* xnp   = symaddr(d_xn);
    float* qkvp  = symaddr(d_qkv);
    float* attnp = symaddr(d_attn);
    float* a2p   = symaddr(d_a2);
    float* z0p   = symaddr(d_z0);
    float* z1p   = symaddr(d_z1);
    float* t0p   = symaddr(d_t0);
    float* t1p   = symaddr(d_t1);
    float* t2p   = symaddr(d_t2);
    float* a3vp  = symaddr(d_a3v);
    float* w2p   = symaddr(d_w2);
    float* rsp   = symaddr(d_rs);

    ln_pad_k<<<BB*NP, 256>>>(lng, lnb);
    tf32gemm_k<<<dim3(1536/128, NP/128, BB), 256>>>(
        xnp, qkvw, nullptr, qkvp, NP, 1536, EMBD,
        (size_t)NP*EMBD, 0, (size_t)NP*1536, 0.f, 1.f, 1.f, 0);
    landmarks_k<<<BH*ML, 64>>>();
    a2_k<<<BH*ML, 256>>>();
    reset_mx_k<<<1, 1>>>();
    a2_stats_k<<<BH, 256>>>();
    z_init_k<<<(BH*ML*ML + 255)/256, 256>>>();

    const size_t SB = (size_t)ML*ML;
    float* zin = z0p; float* zout = z1p;
    for (int it = 0; it < 6; it++) {
        tf32gemm_k<<<dim3(2, 2, BH), 256>>>(a2p, zin, nullptr, t0p, 256, 256, 256, SB, SB, SB, 0.f,  1.f, 1.f,  0);
        tf32gemm_k<<<dim3(2, 2, BH), 256>>>(t0p, t0p, nullptr, t1p, 256, 256, 256, SB, SB, SB, 7.f, -1.f, 1.f,  0);
        tf32gemm_k<<<dim3(2, 2, BH), 256>>>(t0p, t1p, nullptr, t2p, 256, 256, 256, SB, SB, SB, 15.f,-1.f, 1.f,  0);
        tf32gemm_k<<<dim3(2, 2, BH), 256>>>(zin, t2p, nullptr, zout,256, 256, 256, SB, SB, SB, 13.f,-1.f, 0.25f,0);
        float* tmp = zin; zin = zout; zout = tmp;
    }
    // zin holds a2_inv (d_z0)

    // ---- a3 path fused ----
    cudaMemsetAsync(rsp, 0, (size_t)BH*ML*sizeof(float));
    cudaMemsetAsync(a3vp, 0, (size_t)BH*ML*DH*sizeof(float));
    a3_fused_k<<<dim3(8, 2, BH), 256, SMEM_FUSED_BYTES>>>();
    // w2 = a2_inv @ (a3v / rowsum)
    bgemm_epi<<<dim3(1, 4, BH), 256>>>(zin, a3vp, w2p, 256, 64, 256, 0.f, 1.f, 1.f, rsp);

    // ---- a1 path fused ----
    a1_fused_k<<<dim3(NP/128, BH), 256, SMEM_FUSED_BYTES>>>();

    conv_res_k<<<(int)(((size_t)BB*NH*NP*16 + 255)/256), 256>>>(resw);
    tf32gemm_k<<<dim3(EMBD/128, NP/128, BB), 256>>>(
        attnp, outw, outb, xnp, NP, EMBD, EMBD,
        (size_t)NP*EMBD, 0, (size_t)NP*EMBD, 0.f, 1.f, 1.f, 0);
    add_res_k<<<(int)(((size_t)BB*NT*EMBD + 255)/256), 256>>>();
}

extern "C" void kernel_launch(void* const* d_in, const int* in_sizes, int n_in,
                              void* d_out, int out_size)
{
    (void)in_sizes; (void)n_in; (void)out_size;
    const float* x_path = (const float*)d_in[0];
    const float* fc1_w  = (const float*)d_in[1];
    const float* fc1_b  = (const float*)d_in[2];
    const float* cls    = (const float*)d_in[3];
    const float* ln1g   = (const float*)d_in[4];
    const float* ln1b   = (const float*)d_in[5];
    const float* qkv1w  = (const float*)d_in[6];
    const float* out1w  = (const float*)d_in[7];
    const float* out1b  = (const float*)d_in[8];
    const float* res1w  = (const float*)d_in[9];
    const float* ln2g   = (const float*)d_in[10];
    const float* ln2b   = (const float*)d_in[11];
    const float* qkv2w  = (const float*)d_in[12];
    const float* out2w  = (const float*)d_in[13];
    const float* out2b  = (const float*)d_in[14];
    const float* res2w  = (const float*)d_in[15];
    const float* c7w    = (const float*)d_in[16];
    const float* c7b    = (const float*)d_in[17];
    const float* c5w    = (const float*)d_in[18];
    const float* c5b    = (const float*)d_in[19];
    const float* c3w    = (const float*)d_in[20];
    const float* c3b    = (const float*)d_in[21];
    const float* ng     = (const float*)d_in[22];
    const float* nb     = (const float*)d_in[23];
    const float* fc2w   = (const float*)d_in[24];
    const float* fc2b   = (const float*)d_in[25];
    float* out = (float*)d_out;

    static int smem_cfg = 0;
    if (!smem_cfg) {
        cudaFuncSetAttribute(a3_fused_k, cudaFuncAttributeMaxDynamicSharedMemorySize, SMEM_FUSED_BYTES);
        cudaFuncSetAttribute(a1_fused_k, cudaFuncAttributeMaxDynamicSharedMemorySize, SMEM_FUSED_BYTES);
        smem_cfg = 1;
    }

    float* hp = symaddr(d_h);

    tf32gemm_k<<<dim3(EMBD/128, (N0 + 127)/128, BB), 256>>>(
        x_path, fc1_w, fc1_b, hp + EMBD, N0, EMBD, 1024,
        (size_t)N0*1024, 0, (size_t)NT*EMBD, 0.f, 1.f, 1.f, 1);
    fill_cls_k<<<(BB*EMBD + 255)/256, 256>>>(cls);
    fill_wrap_k<<<(BB*ADDW*EMBD + 255)/256, 256>>>();
    wtrans_k<<<(49*EMBD + 255)/256, 256>>>(c7w, c5w, c3w);

    attn_layer(ln1g, ln1b, qkv1w, out1w, out1b, res1w);

    ppeg2_k<<<BB*NPIX, 128>>>(c7b, c5b, c3b);
    ppeg_copy_k<<<(int)(((size_t)BB*NPIX*EMBD + 255)/256), 256>>>();

    attn_layer(ln2g, ln2b, qkv2w, out2w, out2b, res2w);

    head_k<<<BB, 256>>>(ng, nb, fc2w, fc2b, out);
}

// round 6
// speedup vs baseline: 7.2743x; 1.0024x over previous
#include <cuda_runtime.h>
#include <math.h>
#include <stdint.h>

#define BB   4
#define N0   6000
#define HW   78
#define NPIX (HW*HW)        // 6084
#define ADDW (NPIX - N0)    // 84
#define NT   (NPIX + 1)     // 6085
#define NP   6144
#define PADT (NP - NT)      // 59
#define EMBD 512
#define NH   8
#define DH   64
#define ML   256
#define LWIN (NP/ML)        // 24
#define BH   (BB*NH)        // 32

// -------------------- scratch (device globals, no allocation) --------------------
__device__ float d_h   [(size_t)BB*NT*EMBD];
__device__ float d_xn  [(size_t)BB*NP*EMBD];
__device__ float d_qkv [(size_t)BB*NP*3*EMBD];
__device__ float d_attn[(size_t)BB*NP*EMBD];
__device__ float d_ql  [BH*ML*DH];
__device__ float d_kl  [BH*ML*DH];
__device__ float d_a2  [BH*ML*ML];
__device__ float d_z0  [BH*ML*ML];
__device__ float d_z1  [BH*ML*ML];
__device__ float d_t0  [BH*ML*ML];
__device__ float d_t1  [BH*ML*ML];
__device__ float d_t2  [BH*ML*ML];
__device__ float d_a3v [BH*ML*DH];
__device__ float d_w2  [BH*ML*DH];
__device__ float d_rs  [BH*ML];
__device__ float d_mx  [2];
__device__ float d_w7t [49*EMBD];
__device__ float d_w5t [25*EMBD];
__device__ float d_w3t [9*EMBD];

__device__ __forceinline__ float dot64(const float* __restrict__ a, const float* __restrict__ kp) {
    float s = 0.f;
#pragma unroll
    for (int i = 0; i < 16; i++) {
        float4 x = *(const float4*)(kp + 4*i);
        s += a[4*i]*x.x + a[4*i+1]*x.y + a[4*i+2]*x.z + a[4*i+3]*x.w;
    }
    return s;
}

__device__ __forceinline__ uint32_t f2tf32(float f) {
    uint32_t r;
    asm("cvt.rna.tf32.f32 %0, %1;" : "=r"(r) : "f"(f));
    return r;
}

__device__ __forceinline__ void mma_tf32(float* c, const uint32_t* a, const uint32_t* b) {
    asm volatile("mma.sync.aligned.m16n8k8.row.col.f32.tf32.tf32.f32 "
        "{%0,%1,%2,%3}, {%4,%5,%6,%7}, {%8,%9}, {%0,%1,%2,%3};"
        : "+f"(c[0]), "+f"(c[1]), "+f"(c[2]), "+f"(c[3])
        : "r"(a[0]), "r"(a[1]), "r"(a[2]), "r"(a[3]), "r"(b[0]), "r"(b[1]));
}

// ==================== tf32 tensor-core GEMM, 128x128x8 double-buffered ====================
// C = sc * ( A @ (cI*I + eB*B) ) + bias, optional relu.
__global__ __launch_bounds__(256) void tf32gemm_k(
    const float* __restrict__ A, const float* __restrict__ B,
    const float* __restrict__ bias, float* __restrict__ C,
    int M, int N, int K, size_t sA, size_t sB, size_t sC,
    float cI, float eB, float sc, int act)
{
    __shared__ uint32_t As[2][8][136];
    __shared__ uint32_t Bs[2][8][136];
    A += (size_t)blockIdx.z * sA;
    B += (size_t)blockIdx.z * sB;
    C += (size_t)blockIdx.z * sC;
    int bm = blockIdx.y * 128, bn = blockIdx.x * 128;
    int tid = threadIdx.x;
    int arow = tid >> 1, acol = (tid & 1) << 2;
    int brow = tid >> 5, bcol = (tid & 31) << 2;
    int wid = tid >> 5, lane = tid & 31;
    int wy = wid >> 2, wx = wid & 3;
    int g = lane >> 2, tg = lane & 3;

    float acc[4][4][4];
#pragma unroll
    for (int mi = 0; mi < 4; mi++)
#pragma unroll
        for (int ni = 0; ni < 4; ni++)
#pragma unroll
            for (int q = 0; q < 4; q++) acc[mi][ni][q] = 0.f;

    int nk = K >> 3;
    int col0 = bn + bcol;

    {
        int r = bm + arow;
        float4 va = make_float4(0.f,0.f,0.f,0.f);
        if (r < M) va = *(const float4*)(A + (size_t)r*K + acol);
        As[0][acol+0][arow] = f2tf32(va.x);
        As[0][acol+1][arow] = f2tf32(va.y);
        As[0][acol+2][arow] = f2tf32(va.z);
        As[0][acol+3][arow] = f2tf32(va.w);
        float4 vb = *(const float4*)(B + (size_t)brow*N + col0);
        float e0 = eB*vb.x, e1 = eB*vb.y, e2 = eB*vb.z, e3 = eB*vb.w;
        if (brow == col0    ) e0 += cI;
        if (brow == col0 + 1) e1 += cI;
        if (brow == col0 + 2) e2 += cI;
        if (brow == col0 + 3) e3 += cI;
        Bs[0][brow][bcol  ] = f2tf32(e0);
        Bs[0][brow][bcol+1] = f2tf32(e1);
        Bs[0][brow][bcol+2] = f2tf32(e2);
        Bs[0][brow][bcol+3] = f2tf32(e3);
    }
    __syncthreads();

    int buf = 0;
    for (int kt = 0; kt < nk; kt++) {
        float4 va, vb;
        bool pf = (kt + 1 < nk);
        if (pf) {
            int k0 = (kt + 1) << 3;
            int r = bm + arow;
            va = make_float4(0.f,0.f,0.f,0.f);
            if (r < M) va = *(const float4*)(A + (size_t)r*K + k0 + acol);
            vb = *(const float4*)(B + (size_t)(k0 + brow)*N + col0);
        }
        uint32_t af[4][4];
#pragma unroll
        for (int mi = 0; mi < 4; mi++) {
            int r0 = wy*64 + mi*16;
            af[mi][0] = As[buf][tg  ][r0 + g];
            af[mi][1] = As[buf][tg  ][r0 + g + 8];
            af[mi][2] = As[buf][tg+4][r0 + g];
            af[mi][3] = As[buf][tg+4][r0 + g + 8];
        }
        uint32_t bfr[4][2];
#pragma unroll
        for (int ni = 0; ni < 4; ni++) {
            int c0 = wx*32 + ni*8;
            bfr[ni][0] = Bs[buf][tg  ][c0 + g];
            bfr[ni][1] = Bs[buf][tg+4][c0 + g];
        }
#pragma unroll
        for (int mi = 0; mi < 4; mi++)
#pragma unroll
            for (int ni = 0; ni < 4; ni++)
                mma_tf32(acc[mi][ni], af[mi], bfr[ni]);

        if (pf) {
            int nb = buf ^ 1;
            int kr = ((kt + 1) << 3) + brow;
            As[nb][acol+0][arow] = f2tf32(va.x);
            As[nb][acol+1][arow] = f2tf32(va.y);
            As[nb][acol+2][arow] = f2tf32(va.z);
            As[nb][acol+3][arow] = f2tf32(va.w);
            float e0 = eB*vb.x, e1 = eB*vb.y, e2 = eB*vb.z, e3 = eB*vb.w;
            if (kr == col0    ) e0 += cI;
            if (kr == col0 + 1) e1 += cI;
            if (kr == col0 + 2) e2 += cI;
            if (kr == col0 + 3) e3 += cI;
            Bs[nb][brow][bcol  ] = f2tf32(e0);
            Bs[nb][brow][bcol+1] = f2tf32(e1);
            Bs[nb][brow][bcol+2] = f2tf32(e2);
            Bs[nb][brow][bcol+3] = f2tf32(e3);
        }
        __syncthreads();
        buf ^= 1;
    }

#pragma unroll
    for (int mi = 0; mi < 4; mi++) {
#pragma unroll
        for (int half = 0; half < 2; half++) {
            int r = bm + wy*64 + mi*16 + g + half*8;
            if (r >= M) continue;
#pragma unroll
            for (int ni = 0; ni < 4; ni++) {
                int c = bn + wx*32 + ni*8 + 2*tg;
                float v0 = sc*acc[mi][ni][half*2+0] + (bias ? bias[c]   : 0.f);
                float v1 = sc*acc[mi][ni][half*2+1] + (bias ? bias[c+1] : 0.f);
                if (act == 1) { v0 = fmaxf(v0, 0.f); v1 = fmaxf(v1, 0.f); }
                *(float2*)(C + (size_t)r*N + c) = make_float2(v0, v1);
            }
        }
    }
}

// ==================== fused attention kernels (64-wide chunks, ~103KB smem, 2 CTA/SM) ====================
// SMEM words: qs [64][133], Ks [64][68], Vs [64][68], Ps [64][133], rsm [128]
#define SMW_QS 0
#define SMW_KS (64*133)
#define SMW_VS (64*133 + 64*68)
#define SMW_PS (64*133 + 2*64*68)
#define SMW_RS (2*64*133 + 2*64*68)
#define SMEM_FUSED_BYTES ((SMW_RS + 128)*4)

// a3 path: 128 ql rows vs streamed 64-token chunks: acc_o += exp(ql@K^T)@V.
__global__ __launch_bounds__(256) void a3_fused_k() {
    extern __shared__ uint32_t sm[];
    uint32_t* qs = sm + SMW_QS;
    uint32_t* Ks = sm + SMW_KS;
    uint32_t* Vs = sm + SMW_VS;
    uint32_t* Ps = sm + SMW_PS;
    float* rsm = (float*)(sm + SMW_RS);

    int split = blockIdx.x;               // 0..7
    int bm = blockIdx.y * 128;            // ql row base
    int z = blockIdx.z; int zb = z / NH, zh = z % NH;
    int tid = threadIdx.x;
    int wid = tid >> 5, lane = tid & 31;
    int wy = wid >> 2, wx = wid & 3;      // mma1: 2x4 warps, 64x16 each
    int wy2 = wid >> 1, wx2 = wid & 1;    // mma2: 4x2 warps, 32x32 each
    int g = lane >> 2, tg = lane & 3;

    if (tid < 128) rsm[tid] = 0.f;

    for (int i = tid; i < 128*16; i += 256) {
        int row = i >> 4, f4 = (i & 15) << 2;
        float4 v = *(const float4*)(d_ql + ((size_t)(z*ML + bm + row))*DH + f4);
        qs[(f4+0)*133 + row] = f2tf32(v.x);
        qs[(f4+1)*133 + row] = f2tf32(v.y);
        qs[(f4+2)*133 + row] = f2tf32(v.z);
        qs[(f4+3)*133 + row] = f2tf32(v.w);
    }

    float acc_o[2][4][4];
#pragma unroll
    for (int a = 0; a < 2; a++)
#pragma unroll
        for (int b = 0; b < 4; b++)
#pragma unroll
            for (int q = 0; q < 4; q++) acc_o[a][b][q] = 0.f;
    float rs_loc[8];
#pragma unroll
    for (int a = 0; a < 8; a++) rs_loc[a] = 0.f;

    for (int ci = 0; ci < 12; ci++) {
        int c0 = split*768 + ci*64;
        for (int i = tid; i < 64*16; i += 256) {
            int tok = i >> 4, f4 = (i & 15) << 2;
            const float* kvb = d_qkv + ((size_t)(zb*NP + c0 + tok))*1536 + zh*64 + f4;
            float4 kv = *(const float4*)(kvb + 512);
            Ks[(f4+0)*68 + tok] = f2tf32(kv.x);
            Ks[(f4+1)*68 + tok] = f2tf32(kv.y);
            Ks[(f4+2)*68 + tok] = f2tf32(kv.z);
            Ks[(f4+3)*68 + tok] = f2tf32(kv.w);
            float4 vv = *(const float4*)(kvb + 1024);
            Vs[tok*68 + f4+0] = f2tf32(vv.x);
            Vs[tok*68 + f4+1] = f2tf32(vv.y);
            Vs[tok*68 + f4+2] = f2tf32(vv.z);
            Vs[tok*68 + f4+3] = f2tf32(vv.w);
        }
        __syncthreads();

        float acc_s[4][2][4];
#pragma unroll
        for (int a = 0; a < 4; a++)
#pragma unroll
            for (int b = 0; b < 2; b++)
#pragma unroll
                for (int q = 0; q < 4; q++) acc_s[a][b][q] = 0.f;

#pragma unroll
        for (int ks = 0; ks < 8; ks++) {
            uint32_t af[4][4], bfr[2][2];
#pragma unroll
            for (int mi = 0; mi < 4; mi++) {
                int r0 = wy*64 + mi*16;
                af[mi][0] = qs[(ks*8+tg  )*133 + r0 + g];
                af[mi][1] = qs[(ks*8+tg  )*133 + r0 + g + 8];
                af[mi][2] = qs[(ks*8+tg+4)*133 + r0 + g];
                af[mi][3] = qs[(ks*8+tg+4)*133 + r0 + g + 8];
            }
#pragma unroll
            for (int ni = 0; ni < 2; ni++) {
                int cw = wx*16 + ni*8;
                bfr[ni][0] = Ks[(ks*8+tg  )*68 + cw + g];
                bfr[ni][1] = Ks[(ks*8+tg+4)*68 + cw + g];
            }
#pragma unroll
            for (int mi = 0; mi < 4; mi++)
#pragma unroll
                for (int ni = 0; ni < 2; ni++)
                    mma_tf32(acc_s[mi][ni], af[mi], bfr[ni]);
        }

#pragma unroll
        for (int mi = 0; mi < 4; mi++)
#pragma unroll
            for (int half = 0; half < 2; half++) {
                int rl = wy*64 + mi*16 + half*8 + g;
                float ra = 0.f;
#pragma unroll
                for (int ni = 0; ni < 2; ni++) {
                    int cc = wx*16 + ni*8 + 2*tg;
                    float v0 = __expf(acc_s[mi][ni][half*2+0]);
                    float v1 = __expf(acc_s[mi][ni][half*2+1]);
                    Ps[cc*133 + rl]     = f2tf32(v0);
                    Ps[(cc+1)*133 + rl] = f2tf32(v1);
                    ra += v0 + v1;
                }
                rs_loc[mi*2 + half] += ra;
            }
        __syncthreads();

#pragma unroll
        for (int ks = 0; ks < 8; ks++) {
            uint32_t af2[2][4], bf2[4][2];
#pragma unroll
            for (int mi2 = 0; mi2 < 2; mi2++) {
                int m0 = wy2*32 + mi2*16;
                af2[mi2][0] = Ps[(ks*8+tg  )*133 + m0 + g];
                af2[mi2][1] = Ps[(ks*8+tg  )*133 + m0 + g + 8];
                af2[mi2][2] = Ps[(ks*8+tg+4)*133 + m0 + g];
                af2[mi2][3] = Ps[(ks*8+tg+4)*133 + m0 + g + 8];
            }
#pragma unroll
            for (int ni2 = 0; ni2 < 4; ni2++) {
                int cw = wx2*32 + ni2*8;
                bf2[ni2][0] = Vs[(ks*8+tg  )*68 + cw + g];
                bf2[ni2][1] = Vs[(ks*8+tg+4)*68 + cw + g];
            }
#pragma unroll
            for (int mi2 = 0; mi2 < 2; mi2++)
#pragma unroll
                for (int ni2 = 0; ni2 < 4; ni2++)
                    mma_tf32(acc_o[mi2][ni2], af2[mi2], bf2[ni2]);
        }
        __syncthreads();
    }

#pragma unroll
    for (int j2 = 0; j2 < 8; j2++) {
        int rl = wy*64 + (j2>>1)*16 + (j2&1)*8 + g;
        atomicAdd(&rsm[rl], rs_loc[j2]);
    }
    __syncthreads();
    if (tid < 128) atomicAdd(d_rs + (size_t)z*ML + bm + tid, rsm[tid]);
#pragma unroll
    for (int mi2 = 0; mi2 < 2; mi2++)
#pragma unroll
        for (int half = 0; half < 2; half++) {
            int m = wy2*32 + mi2*16 + half*8 + g;
#pragma unroll
            for (int ni2 = 0; ni2 < 4; ni2++) {
                int cc = wx2*32 + ni2*8 + 2*tg;
                float* dst = d_a3v + ((size_t)(z*ML + bm + m))*DH + cc;
                atomicAdd(dst,     acc_o[mi2][ni2][half*2+0]);
                atomicAdd(dst + 1, acc_o[mi2][ni2][half*2+1]);
            }
        }
}

// a1 path: 128 tokens vs 4 chunks of 64 landmarks: out = (exp(0.125 q@kl^T) @ w2)/rowsum.
__global__ __launch_bounds__(256) void a1_fused_k() {
    extern __shared__ uint32_t sm[];
    uint32_t* qs = sm + SMW_QS;
    uint32_t* Ks = sm + SMW_KS;
    uint32_t* Vs = sm + SMW_VS;
    uint32_t* Ps = sm + SMW_PS;
    float* rsm = (float*)(sm + SMW_RS);

    int bm = blockIdx.x * 128;    // token base
    int z = blockIdx.y; int zb = z / NH, zh = z % NH;
    int tid = threadIdx.x;
    int wid = tid >> 5, lane = tid & 31;
    int wy = wid >> 2, wx = wid & 3;
    int wy2 = wid >> 1, wx2 = wid & 1;
    int g = lane >> 2, tg = lane & 3;

    if (tid < 128) rsm[tid] = 0.f;

    for (int i = tid; i < 128*16; i += 256) {
        int row = i >> 4, f4 = (i & 15) << 2;
        float4 v = *(const float4*)(d_qkv + ((size_t)(zb*NP + bm + row))*1536 + zh*64 + f4);
        qs[(f4+0)*133 + row] = f2tf32(v.x * 0.125f);
        qs[(f4+1)*133 + row] = f2tf32(v.y * 0.125f);
        qs[(f4+2)*133 + row] = f2tf32(v.z * 0.125f);
        qs[(f4+3)*133 + row] = f2tf32(v.w * 0.125f);
    }

    float acc_o[2][4][4];
#pragma unroll
    for (int a = 0; a < 2; a++)
#pragma unroll
        for (int b = 0; b < 4; b++)
#pragma unroll
            for (int q = 0; q < 4; q++) acc_o[a][b][q] = 0.f;
    float rs_loc[8];
#pragma unroll
    for (int a = 0; a < 8; a++) rs_loc[a] = 0.f;

    for (int lc = 0; lc < 4; lc++) {
        int base = lc*64;
        for (int i = tid; i < 64*16; i += 256) {
            int lm = i >> 4, f4 = (i & 15) << 2;
            float4 kv = *(const float4*)(d_kl + ((size_t)(z*ML + base + lm))*DH + f4);
            Ks[(f4+0)*68 + lm] = f2tf32(kv.x);
            Ks[(f4+1)*68 + lm] = f2tf32(kv.y);
            Ks[(f4+2)*68 + lm] = f2tf32(kv.z);
            Ks[(f4+3)*68 + lm] = f2tf32(kv.w);
            float4 wv = *(const float4*)(d_w2 + ((size_t)(z*ML + base + lm))*DH + f4);
            Vs[lm*68 + f4+0] = f2tf32(wv.x);
            Vs[lm*68 + f4+1] = f2tf32(wv.y);
            Vs[lm*68 + f4+2] = f2tf32(wv.z);
            Vs[lm*68 + f4+3] = f2tf32(wv.w);
        }
        __syncthreads();

        float acc_s[4][2][4];
#pragma unroll
        for (int a = 0; a < 4; a++)
#pragma unroll
            for (int b = 0; b < 2; b++)
#pragma unroll
                for (int q = 0; q < 4; q++) acc_s[a][b][q] = 0.f;

#pragma unroll
        for (int ks = 0; ks < 8; ks++) {
            uint32_t af[4][4], bfr[2][2];
#pragma unroll
            for (int mi = 0; mi < 4; mi++) {
                int r0 = wy*64 + mi*16;
                af[mi][0] = qs[(ks*8+tg  )*133 + r0 + g];
                af[mi][1] = qs[(ks*8+tg  )*133 + r0 + g + 8];
                af[mi][2] = qs[(ks*8+tg+4)*133 + r0 + g];
                af[mi][3] = qs[(ks*8+tg+4)*133 + r0 + g + 8];
            }
#pragma unroll
            for (int ni = 0; ni < 2; ni++) {
                int cw = wx*16 + ni*8;
                bfr[ni][0] = Ks[(ks*8+tg  )*68 + cw + g];
                bfr[ni][1] = Ks[(ks*8+tg+4)*68 + cw + g];
            }
#pragma unroll
            for (int mi = 0; mi < 4; mi++)
#pragma unroll
                for (int ni = 0; ni < 2; ni++)
                    mma_tf32(acc_s[mi][ni], af[mi], bfr[ni]);
        }

#pragma unroll
        for (int mi = 0; mi < 4; mi++)
#pragma unroll
            for (int half = 0; half < 2; half++) {
                int rl = wy*64 + mi*16 + half*8 + g;
                float ra = 0.f;
#pragma unroll
                for (int ni = 0; ni < 2; ni++) {
                    int cc = wx*16 + ni*8 + 2*tg;
                    float v0 = __expf(acc_s[mi][ni][half*2+0]);
                    float v1 = __expf(acc_s[mi][ni][half*2+1]);
                    Ps[cc*133 + rl]     = f2tf32(v0);
                    Ps[(cc+1)*133 + rl] = f2tf32(v1);
                    ra += v0 + v1;
                }
                rs_loc[mi*2 + half] += ra;
            }
        __syncthreads();

#pragma unroll
        for (int ks = 0; ks < 8; ks++) {
            uint32_t af2[2][4], bf2[4][2];
#pragma unroll
            for (int mi2 = 0; mi2 < 2; mi2++) {
                int m0 = wy2*32 + mi2*16;
                af2[mi2][0] = Ps[(ks*8+tg  )*133 + m0 + g];
                af2[mi2][1] = Ps[(ks*8+tg  )*133 + m0 + g + 8];
                af2[mi2][2] = Ps[(ks*8+tg+4)*133 + m0 + g];
                af2[mi2][3] = Ps[(ks*8+tg+4)*133 + m0 + g + 8];
            }
#pragma unroll
            for (int ni2 = 0; ni2 < 4; ni2++) {
                int cw = wx2*32 + ni2*8;
                bf2[ni2][0] = Vs[(ks*8+tg  )*68 + cw + g];
                bf2[ni2][1] = Vs[(ks*8+tg+4)*68 + cw + g];
            }
#pragma unroll
            for (int mi2 = 0; mi2 < 2; mi2++)
#pragma unroll
                for (int ni2 = 0; ni2 < 4; ni2++)
                    mma_tf32(acc_o[mi2][ni2], af2[mi2], bf2[ni2]);
        }
        __syncthreads();
    }

#pragma unroll
    for (int j2 = 0; j2 < 8; j2++) {
        int rl = wy*64 + (j2>>1)*16 + (j2&1)*8 + g;
        atomicAdd(&rsm[rl], rs_loc[j2]);
    }
    __syncthreads();
#pragma unroll
    for (int mi2 = 0; mi2 < 2; mi2++)
#pragma unroll
        for (int half = 0; half < 2; half++) {
            int m = wy2*32 + mi2*16 + half*8 + g;
            float inv = 1.f / rsm[m];
#pragma unroll
            for (int ni2 = 0; ni2 < 4; ni2++) {
                int cc = wx2*32 + ni2*8 + 2*tg;
                *(float2*)(d_attn + ((size_t)(zb*NP + bm + m))*EMBD + zh*64 + cc) =
                    make_float2(acc_o[mi2][ni2][half*2+0]*inv, acc_o[mi2][ni2][half*2+1]*inv);
            }
        }
}

// -------------------- small 64-tile batched GEMM (fp32) with optional B row-scale --------------------
__global__ __launch_bounds__(256) void bgemm_epi(
    const float* __restrict__ A, const float* __restrict__ Bm, float* __restrict__ C,
    int Md, int Nd, int Kd, float cI, float eB, float s, const float* __restrict__ rsc)
{
    __shared__ float As[16][64];
    __shared__ float Bs[16][64];
    A  += (size_t)blockIdx.z * Md * Kd;
    Bm += (size_t)blockIdx.z * Kd * Nd;
    C  += (size_t)blockIdx.z * Md * Nd;
    const float* rscz = rsc ? rsc + (size_t)blockIdx.z * Kd : nullptr;
    int bm = blockIdx.y * 64, bn = blockIdx.x * 64;
    int tid = threadIdx.x;
    int la_r = tid >> 2, la_c = (tid & 3) << 2;
    int lb_r = tid >> 4, lb_c = (tid & 15) << 2;
    int ty = tid >> 4, tx = tid & 15;
    float acc[4][4];
#pragma unroll
    for (int i = 0; i < 4; i++)
#pragma unroll
        for (int j = 0; j < 4; j++) acc[i][j] = 0.f;

    for (int k0 = 0; k0 < Kd; k0 += 16) {
        float4 av = *(const float4*)(A + (size_t)(bm + la_r)*Kd + k0 + la_c);
        As[la_c  ][la_r] = av.x;
        As[la_c+1][la_r] = av.y;
        As[la_c+2][la_r] = av.z;
        As[la_c+3][la_r] = av.w;
        int kr = k0 + lb_r;
        float4 bv = *(const float4*)(Bm + (size_t)kr*Nd + bn + lb_c);
        float rsv = rscz ? (1.f / rscz[kr]) : 1.f;
        float e0 = eB*rsv*bv.x, e1 = eB*rsv*bv.y, e2 = eB*rsv*bv.z, e3 = eB*rsv*bv.w;
        int c0 = bn + lb_c;
        if (kr == c0    ) e0 += cI;
        if (kr == c0 + 1) e1 += cI;
        if (kr == c0 + 2) e2 += cI;
        if (kr == c0 + 3) e3 += cI;
        Bs[lb_r][lb_c  ] = e0;
        Bs[lb_r][lb_c+1] = e1;
        Bs[lb_r][lb_c+2] = e2;
        Bs[lb_r][lb_c+3] = e3;
        __syncthreads();
#pragma unroll
        for (int kk = 0; kk < 16; kk++) {
            float a0 = As[kk][ty*4+0], a1 = As[kk][ty*4+1], a2 = As[kk][ty*4+2], a3 = As[kk][ty*4+3];
            float b0 = Bs[kk][tx*4+0], b1 = Bs[kk][tx*4+1], b2 = Bs[kk][tx*4+2], b3 = Bs[kk][tx*4+3];
            acc[0][0]+=a0*b0; acc[0][1]+=a0*b1; acc[0][2]+=a0*b2; acc[0][3]+=a0*b3;
            acc[1][0]+=a1*b0; acc[1][1]+=a1*b1; acc[1][2]+=a1*b2; acc[1][3]+=a1*b3;
            acc[2][0]+=a2*b0; acc[2][1]+=a2*b1; acc[2][2]+=a2*b2; acc[2][3]+=a2*b3;
            acc[3][0]+=a3*b0; acc[3][1]+=a3*b1; acc[3][2]+=a3*b2; acc[3][3]+=a3*b3;
        }
        __syncthreads();
    }
#pragma unroll
    for (int i = 0; i < 4; i++) {
        int r = bm + ty*4 + i;
#pragma unroll
        for (int j = 0; j < 4; j++) {
            int c = bn + tx*4 + j;
            C[(size_t)r*Nd + c] = s * acc[i][j];
        }
    }
}

// -------------------- misc small kernels --------------------
__global__ void fill_cls_k(const float* __restrict__ cls) {
    int i = blockIdx.x*256 + threadIdx.x;
    if (i < BB*EMBD) d_h[(size_t)(i/EMBD)*NT*EMBD + (i % EMBD)] = cls[i % EMBD];
}

__global__ void fill_wrap_k() {
    int i = blockIdx.x*256 + threadIdx.x;
    if (i >= BB*ADDW*EMBD) return;
    int c = i % EMBD; int r = i / EMBD; int j = r % ADDW; int b = r / ADDW;
    d_h[((size_t)(b*NT + 1 + N0 + j))*EMBD + c] = d_h[((size_t)(b*NT + 1 + j))*EMBD + c];
}

__global__ __launch_bounds__(256) void ln_pad_k(const float* __restrict__ g, const float* __restrict__ bp) {
    int row = blockIdx.x; int b = row / NP; int t = row % NP;
    int tid = threadIdx.x;
    float* out = d_xn + (size_t)row*EMBD;
    if (t < PADT) { out[tid] = 0.f; out[tid+256] = 0.f; return; }
    const float* x = d_h + ((size_t)b*NT + (t - PADT))*EMBD;
    float v0 = x[tid], v1 = x[tid+256];
    __shared__ float red[256];
    red[tid] = v0 + v1; __syncthreads();
    for (int o = 128; o > 0; o >>= 1) { if (tid < o) red[tid] += red[tid+o]; __syncthreads(); }
    float mean = red[0] * (1.f/512.f); __syncthreads();
    float e0 = v0 - mean, e1 = v1 - mean;
    red[tid] = e0*e0 + e1*e1; __syncthreads();
    for (int o = 128; o > 0; o >>= 1) { if (tid < o) red[tid] += red[tid+o]; __syncthreads(); }
    float inv = rsqrtf(red[0] * (1.f/512.f) + 1e-5f);
    out[tid]     = e0*inv*g[tid]     + bp[tid];
    out[tid+256] = e1*inv*g[tid+256] + bp[tid+256];
}

__global__ void landmarks_k() {
    int blk = blockIdx.x; int bh = blk >> 8; int i = blk & 255;
    int d = threadIdx.x;  // 64 threads
    int b = bh / NH, h = bh % NH;
    const float* base = d_qkv + ((size_t)(b*NP) + (size_t)i*LWIN)*1536 + h*64 + d;
    float sq = 0.f, sk = 0.f;
#pragma unroll
    for (int j = 0; j < LWIN; j++) { sq += base[(size_t)j*1536]; sk += base[(size_t)j*1536 + 512]; }
    d_ql[((size_t)(bh*ML + i))*DH + d] = sq * (0.125f / LWIN);
    d_kl[((size_t)(bh*ML + i))*DH + d] = sk * (1.f   / LWIN);
}

__global__ __launch_bounds__(256) void a2_k() {
    int blk = blockIdx.x; int bh = blk >> 8; int i = blk & 255;
    int tid = threadIdx.x;
    __shared__ float sq[64];
    __shared__ float red[256];
    if (tid < 64) sq[tid] = d_ql[((size_t)(bh*ML + i))*DH + tid];
    __syncthreads();
    float s = dot64(sq, d_kl + ((size_t)(bh*ML + tid))*DH);
    red[tid] = s; __syncthreads();
    for (int o = 128; o > 0; o >>= 1) { if (tid < o) red[tid] = fmaxf(red[tid], red[tid+o]); __syncthreads(); }
    float m = red[0]; __syncthreads();
    float p = expf(s - m);
    red[tid] = p; __syncthreads();
    for (int o = 128; o > 0; o >>= 1) { if (tid < o) red[tid] += red[tid+o]; __syncthreads(); }
    float Z = red[0];
    d_a2[((size_t)bh << 16) + ((size_t)i << 8) + tid] = p / Z;
}

__global__ void reset_mx_k() { d_mx[0] = 0.f; d_mx[1] = 0.f; }

__global__ __launch_bounds__(256) void a2_stats_k() {
    int bh = blockIdx.x; int tid = threadIdx.x;
    const float* a = d_a2 + ((size_t)bh << 16);
    float cs = 0.f, rs = 0.f;
    for (int i = 0; i < ML; i++) cs += a[(size_t)i*ML + tid];
    for (int j = 0; j < ML; j++) rs += a[(size_t)tid*ML + j];
    __shared__ float red[256];
    red[tid] = cs; __syncthreads();
    for (int o = 128; o > 0; o >>= 1) { if (tid < o) red[tid] = fmaxf(red[tid], red[tid+o]); __syncthreads(); }
    if (tid == 0) atomicMax((int*)&d_mx[1], __float_as_int(red[0]));
    __syncthreads();
    red[tid] = rs; __syncthreads();
    for (int o = 128; o > 0; o >>= 1) { if (tid < o) red[tid] = fmaxf(red[tid], red[tid+o]); __syncthreads(); }
    if (tid == 0) atomicMax((int*)&d_mx[0], __float_as_int(red[0]));
}

__global__ void z_init_k() {
    size_t idx = (size_t)blockIdx.x*256 + threadIdx.x;
    if (idx >= (size_t)BH*ML*ML) return;
    size_t bh = idx >> 16; size_t r = (idx >> 8) & 255; size_t c = idx & 255;
    float denom = d_mx[0] * d_mx[1];
    d_z0[idx] = d_a2[(bh << 16) + (c << 8) + r] / denom;
}

// conv residual with smem tiling: block = (b, h, 128-token strip)
__global__ __launch_bounds__(256) void conv_res_k(const float* __restrict__ w) {
    __shared__ float vs[160*64];
    __shared__ float ws[33];
    int blk = blockIdx.x;
    int strip = blk % 48; int bh = blk / 48; int h = bh % NH; int b = bh / NH;
    int t0 = strip * 128;
    int tid = threadIdx.x;
    if (tid < 33) ws[tid] = w[h*33 + tid];
    for (int i = tid; i < 160*16; i += 256) {
        int row = i >> 4, f4 = (i & 15) << 2;
        int t = t0 - 16 + row;
        float4 v = make_float4(0.f,0.f,0.f,0.f);
        if (t >= 0 && t < NP)
            v = *(const float4*)(d_qkv + ((size_t)(b*NP + t))*1536 + 1024 + h*64 + f4);
        *(float4*)(vs + row*64 + f4) = v;
    }
    __syncthreads();
#pragma unroll
    for (int j = 0; j < 8; j++) {
        int o = tid + j*256;
        int row = o >> 4, f4 = (o & 15) << 2;
        float4 s = make_float4(0.f,0.f,0.f,0.f);
#pragma unroll
        for (int k = 0; k < 33; k++) {
            float4 v = *(const float4*)(vs + (row + k)*64 + f4);
            float wk = ws[k];
            s.x += v.x*wk; s.y += v.y*wk; s.z += v.z*wk; s.w += v.w*wk;
        }
        float4* dst = (float4*)(d_attn + ((size_t)(b*NP + t0 + row))*EMBD + h*64 + f4);
        float4 cur = *dst;
        cur.x += s.x; cur.y += s.y; cur.z += s.z; cur.w += s.w;
        *dst = cur;
    }
}

__global__ void add_res_k() {
    size_t idx = (size_t)blockIdx.x*256 + threadIdx.x;
    if (idx >= (size_t)BB*NT*EMBD) return;
    int c = idx % EMBD; size_t r = idx / EMBD; int t = r % NT; int b = (int)(r / NT);
    d_h[idx] += d_xn[((size_t)(b*NP + t + PADT))*EMBD + c];
}

// weight transpose for PPEG: [c][tap] -> [tap][c]
__global__ void wtrans_k(const float* __restrict__ w7, const float* __restrict__ w5,
                         const float* __restrict__ w3) {
    int i = blockIdx.x*256 + threadIdx.x;
    if (i < 49*EMBD) { int c = i / 49, t = i % 49; d_w7t[t*EMBD + c] = w7[i]; }
    if (i < 25*EMBD) { int c = i / 25, t = i % 25; d_w5t[t*EMBD + c] = w5[i]; }
    if (i < 9*EMBD)  { int c = i / 9,  t = i % 9;  d_w3t[t*EMBD + c] = w3[i]; }
}

__global__ __launch_bounds__(128) void ppeg2_k(
    const float* __restrict__ b7, const float* __restrict__ b5, const float* __restrict__ b3)
{
    int blk = blockIdx.x; int b = blk / NPIX; int pix = blk % NPIX;
    int i = pix / HW, j = pix % HW;
    int c = threadIdx.x << 2;
    const float* hbase = d_h + ((size_t)(b*NT + 1))*EMBD + c;
    float4 s = *(const float4*)(hbase + (size_t)pix*EMBD);
    {
        float4 x7 = *(const float4*)(b7 + c);
        float4 x5 = *(const float4*)(b5 + c);
        float4 x3 = *(const float4*)(b3 + c);
        s.x += x7.x + x5.x + x3.x; s.y += x7.y + x5.y + x3.y;
        s.z += x7.z + x5.z + x3.z; s.w += x7.w + x5.w + x3.w;
    }
#pragma unroll
    for (int a = 0; a < 7; a++) {
        int ii = i - 3 + a; if (ii < 0 || ii >= HW) continue;
#pragma unroll
        for (int q = 0; q < 7; q++) {
            int jj = j - 3 + q; if (jj < 0 || jj >= HW) continue;
            float4 x = *(const float4*)(hbase + (size_t)(ii*HW + jj)*EMBD);
            float4 w = *(const float4*)(d_w7t + (a*7 + q)*EMBD + c);
            s.x += x.x*w.x; s.y += x.y*w.y; s.z += x.z*w.z; s.w += x.w*w.w;
        }
    }
#pragma unroll
    for (int a = 0; a < 5; a++) {
        int ii = i - 2 + a; if (ii < 0 || ii >= HW) continue;
#pragma unroll
        for (int q = 0; q < 5; q++) {
            int jj = j - 2 + q; if (jj < 0 || jj >= HW) continue;
            float4 x = *(const float4*)(hbase + (size_t)(ii*HW + jj)*EMBD);
            float4 w = *(const float4*)(d_w5t + (a*5 + q)*EMBD + c);
            s.x += x.x*w.x; s.y += x.y*w.y; s.z += x.z*w.z; s.w += x.w*w.w;
        }
    }
#pragma unroll
    for (int a = 0; a < 3; a++) {
        int ii = i - 1 + a; if (ii < 0 || ii >= HW) continue;
#pragma unroll
        for (int q = 0; q < 3; q++) {
            int jj = j - 1 + q; if (jj < 0 || jj >= HW) continue;
            float4 x = *(const float4*)(hbase + (size_t)(ii*HW + jj)*EMBD);
            float4 w = *(const float4*)(d_w3t + (a*3 + q)*EMBD + c);
            s.x += x.x*w.x; s.y += x.y*w.y; s.z += x.z*w.z; s.w += x.w*w.w;
        }
    }
    *(float4*)(d_xn + ((size_t)(b*NPIX + pix))*EMBD + c) = s;
}

__global__ void ppeg_copy_k() {
    size_t idx = (size_t)blockIdx.x*256 + threadIdx.x;
    if (idx >= (size_t)BB*NPIX*EMBD) return;
    int c = idx % EMBD; size_t r = idx / EMBD; int pix = r % NPIX; int b = (int)(r / NPIX);
    d_h[((size_t)(b*NT + 1 + pix))*EMBD + c] = d_xn[idx];
}

__global__ __launch_bounds__(256) void head_k(
    const float* __restrict__ g, const float* __restrict__ bp,
    const float* __restrict__ w, const float* __restrict__ bias, float* __restrict__ out)
{
    int b = blockIdx.x; int tid = threadIdx.x;
    __shared__ float xs[512];
    __shared__ float red[256];
    __shared__ float lg[4];
    const float* x = d_h + (size_t)b*NT*EMBD;
    float v0 = x[tid], v1 = x[tid+256];
    red[tid] = v0 + v1; __syncthreads();
    for (int o = 128; o > 0; o >>= 1) { if (tid < o) red[tid] += red[tid+o]; __syncthreads(); }
    float mean = red[0] * (1.f/512.f); __syncthreads();
    float e0 = v0 - mean, e1 = v1 - mean;
    red[tid] = e0*e0 + e1*e1; __syncthreads();
    for (int o = 128; o > 0; o >>= 1) { if (tid < o) red[tid] += red[tid+o]; __syncthreads(); }
    float inv = rsqrtf(red[0] * (1.f/512.f) + 1e-5f);
    xs[tid]     = e0*inv*g[tid]     + bp[tid];
    xs[tid+256] = e1*inv*g[tid+256] + bp[tid+256];
    __syncthreads();
    if (tid < 4) {
        float s = bias[tid];
        for (int k = 0; k < 512; k++) s += xs[k]*w[k*4 + tid];
        lg[tid] = s;
    }
    __syncthreads();
    if (tid == 0) {
        int best = 0; float bv = lg[0];
        for (int k = 1; k < 4; k++) if (lg[k] > bv) { bv = lg[k]; best = k; }
        float S = 1.f;
        for (int k = 0; k < 4; k++) {
            float hz = 1.f / (1.f + expf(-lg[k]));
            out[b*4 + k] = hz;
            S *= (1.f - hz);
            out[16 + b*4 + k] = S;
        }
        out[32 + b] = (float)best;
    }
}

// -------------------- host orchestration --------------------
static float* symaddr(const void* sym) { void* p = nullptr; cudaGetSymbolAddress(&p, sym); return (float*)p; }

static void attn_layer(const float* lng, const float* lnb, const float* qkvw,
                       const float* outw, const float* outb, const float* resw)
{
    float* xnp   = symaddr(d_xn);
    float* qkvp  = symaddr(d_qkv);
    float* attnp = symaddr(d_attn);
    float* a2p   = symaddr(d_a2);
    float* z0p   = symaddr(d_z0);
    float* z1p   = symaddr(d_z1);
    float* t0p   = symaddr(d_t0);
    float* t1p   = symaddr(d_t1);
    float* t2p   = symaddr(d_t2);
    float* a3vp  = symaddr(d_a3v);
    float* w2p   = symaddr(d_w2);
    float* rsp   = symaddr(d_rs);

    ln_pad_k<<<BB*NP, 256>>>(lng, lnb);
    tf32gemm_k<<<dim3(1536/128, NP/128, BB), 256>>>(
        xnp, qkvw, nullptr, qkvp, NP, 1536, EMBD,
        (size_t)NP*EMBD, 0, (size_t)NP*1536, 0.f, 1.f, 1.f, 0);
    landmarks_k<<<BH*ML, 64>>>();
    a2_k<<<BH*ML, 256>>>();
    reset_mx_k<<<1, 1>>>();
    a2_stats_k<<<BH, 256>>>();
    z_init_k<<<(BH*ML*ML + 255)/256, 256>>>();

    const size_t SB = (size_t)ML*ML;
    float* zin = z0p; float* zout = z1p;
    for (int it = 0; it < 6; it++) {
        tf32gemm_k<<<dim3(2, 2, BH), 256>>>(a2p, zin, nullptr, t0p, 256, 256, 256, SB, SB, SB, 0.f,  1.f, 1.f,  0);
        tf32gemm_k<<<dim3(2, 2, BH), 256>>>(t0p, t0p, nullptr, t1p, 256, 256, 256, SB, SB, SB, 7.f, -1.f, 1.f,  0);
        tf32gemm_k<<<dim3(2, 2, BH), 256>>>(t0p, t1p, nullptr, t2p, 256, 256, 256, SB, SB, SB, 15.f,-1.f, 1.f,  0);
        tf32gemm_k<<<dim3(2, 2, BH), 256>>>(zin, t2p, nullptr, zout,256, 256, 256, SB, SB, SB, 13.f,-1.f, 0.25f,0);
        float* tmp = zin; zin = zout; zout = tmp;
    }
    // zin holds a2_inv (d_z0)

    // ---- a3 path fused ----
    cudaMemsetAsync(rsp, 0, (size_t)BH*ML*sizeof(float));
    cudaMemsetAsync(a3vp, 0, (size_t)BH*ML*DH*sizeof(float));
    a3_fused_k<<<dim3(8, 2, BH), 256, SMEM_FUSED_BYTES>>>();
    // w2 = a2_inv @ (a3v / rowsum)
    bgemm_epi<<<dim3(1, 4, BH), 256>>>(zin, a3vp, w2p, 256, 64, 256, 0.f, 1.f, 1.f, rsp);

    // ---- a1 path fused ----
    a1_fused_k<<<dim3(NP/128, BH), 256, SMEM_FUSED_BYTES>>>();

    conv_res_k<<<BB*NH*48, 256>>>(resw);
    tf32gemm_k<<<dim3(EMBD/128, NP/128, BB), 256>>>(
        attnp, outw, outb, xnp, NP, EMBD, EMBD,
        (size_t)NP*EMBD, 0, (size_t)NP*EMBD, 0.f, 1.f, 1.f, 0);
    add_res_k<<<(int)(((size_t)BB*NT*EMBD + 255)/256), 256>>>();
}

extern "C" void kernel_launch(void* const* d_in, const int* in_sizes, int n_in,
                              void* d_out, int out_size)
{
    (void)in_sizes; (void)n_in; (void)out_size;
    const float* x_path = (const float*)d_in[0];
    const float* fc1_w  = (const float*)d_in[1];
    const float* fc1_b  = (const float*)d_in[2];
    const float* cls    = (const float*)d_in[3];
    const float* ln1g   = (const float*)d_in[4];
    const float* ln1b   = (const float*)d_in[5];
    const float* qkv1w  = (const float*)d_in[6];
    const float* out1w  = (const float*)d_in[7];
    const float* out1b  = (const float*)d_in[8];
    const float* res1w  = (const float*)d_in[9];
    const float* ln2g   = (const float*)d_in[10];
    const float* ln2b   = (const float*)d_in[11];
    const float* qkv2w  = (const float*)d_in[12];
    const float* out2w  = (const float*)d_in[13];
    const float* out2b  = (const float*)d_in[14];
    const float* res2w  = (const float*)d_in[15];
    const float* c7w    = (const float*)d_in[16];
    const float* c7b    = (const float*)d_in[17];
    const float* c5w    = (const float*)d_in[18];
    const float* c5b    = (const float*)d_in[19];
    const float* c3w    = (const float*)d_in[20];
    const float* c3b    = (const float*)d_in[21];
    const float* ng     = (const float*)d_in[22];
    const float* nb     = (const float*)d_in[23];
    const float* fc2w   = (const float*)d_in[24];
    const float* fc2b   = (const float*)d_in[25];
    float* out = (float*)d_out;

    static int smem_cfg = 0;
    if (!smem_cfg) {
        cudaFuncSetAttribute(a3_fused_k, cudaFuncAttributeMaxDynamicSharedMemorySize, SMEM_FUSED_BYTES);
        cudaFuncSetAttribute(a1_fused_k, cudaFuncAttributeMaxDynamicSharedMemorySize, SMEM_FUSED_BYTES);
        smem_cfg = 1;
    }

    float* hp = symaddr(d_h);

    tf32gemm_k<<<dim3(EMBD/128, (N0 + 127)/128, BB), 256>>>(
        x_path, fc1_w, fc1_b, hp + EMBD, N0, EMBD, 1024,
        (size_t)N0*1024, 0, (size_t)NT*EMBD, 0.f, 1.f, 1.f, 1);
    fill_cls_k<<<(BB*EMBD + 255)/256, 256>>>(cls);
    fill_wrap_k<<<(BB*ADDW*EMBD + 255)/256, 256>>>();
    wtrans_k<<<(49*EMBD + 255)/256, 256>>>(c7w, c5w, c3w);

    attn_layer(ln1g, ln1b, qkv1w, out1w, out1b, res1w);

    ppeg2_k<<<BB*NPIX, 128>>>(c7b, c5b, c3b);
    ppeg_copy_k<<<(int)(((size_t)BB*NPIX*EMBD + 255)/256), 256>>>();

    attn_layer(ln2g, ln2b, qkv2w, out2w, out2b, res2w);

    head_k<<<BB, 256>>>(ng, nb, fc2w, fc2b, out);
}

// round 7
// speedup vs baseline: 7.7985x; 1.0721x over previous
#include <cuda_runtime.h>
#include <math.h>
#include <stdint.h>

#define BB   4
#define N0   6000
#define HW   78
#define NPIX (HW*HW)        // 6084
#define ADDW (NPIX - N0)    // 84
#define NT   (NPIX + 1)     // 6085
#define NP   6144
#define PADT (NP - NT)      // 59
#define EMBD 512
#define NH   8
#define DH   64
#define ML   256
#define LWIN (NP/ML)        // 24
#define BH   (BB*NH)        // 32

// -------------------- scratch (device globals, no allocation) --------------------
__device__ float d_h   [(size_t)BB*NT*EMBD];
__device__ float d_xn  [(size_t)BB*NP*EMBD];
__device__ float d_qkv [(size_t)BB*NP*3*EMBD];
__device__ float d_attn[(size_t)BB*NP*EMBD];
__device__ float d_ql  [BH*ML*DH];
__device__ float d_kl  [BH*ML*DH];
__device__ float d_a2  [BH*ML*ML];
__device__ float d_z0  [BH*ML*ML];
__device__ float d_z1  [BH*ML*ML];
__device__ float d_t0  [BH*ML*ML];
__device__ float d_t1  [BH*ML*ML];
__device__ float d_t2  [BH*ML*ML];
__device__ float d_a3v [BH*ML*DH];
__device__ float d_w2  [BH*ML*DH];
__device__ float d_rs  [BH*ML];
__device__ float d_mx  [2];
__device__ float d_w7t [49*EMBD];
__device__ float d_w5t [25*EMBD];
__device__ float d_w3t [9*EMBD];

__device__ __forceinline__ float dot64(const float* __restrict__ a, const float* __restrict__ kp) {
    float s = 0.f;
#pragma unroll
    for (int i = 0; i < 16; i++) {
        float4 x = *(const float4*)(kp + 4*i);
        s += a[4*i]*x.x + a[4*i+1]*x.y + a[4*i+2]*x.z + a[4*i+3]*x.w;
    }
    return s;
}

__device__ __forceinline__ uint32_t f2tf32(float f) {
    uint32_t r;
    asm("cvt.rna.tf32.f32 %0, %1;" : "=r"(r) : "f"(f));
    return r;
}

__device__ __forceinline__ uint32_t pkbf(float lo, float hi) {
    uint32_t r;
    asm("cvt.rn.bf16x2.f32 %0, %1, %2;" : "=r"(r) : "f"(hi), "f"(lo));
    return r;
}

__device__ __forceinline__ void mma_tf32(float* c, const uint32_t* a, const uint32_t* b) {
    asm volatile("mma.sync.aligned.m16n8k8.row.col.f32.tf32.tf32.f32 "
        "{%0,%1,%2,%3}, {%4,%5,%6,%7}, {%8,%9}, {%0,%1,%2,%3};"
        : "+f"(c[0]), "+f"(c[1]), "+f"(c[2]), "+f"(c[3])
        : "r"(a[0]), "r"(a[1]), "r"(a[2]), "r"(a[3]), "r"(b[0]), "r"(b[1]));
}

__device__ __forceinline__ void mma_bf16(float* c, const uint32_t* a, const uint32_t* b) {
    asm volatile("mma.sync.aligned.m16n8k16.row.col.f32.bf16.bf16.f32 "
        "{%0,%1,%2,%3}, {%4,%5,%6,%7}, {%8,%9}, {%0,%1,%2,%3};"
        : "+f"(c[0]), "+f"(c[1]), "+f"(c[2]), "+f"(c[3])
        : "r"(a[0]), "r"(a[1]), "r"(a[2]), "r"(a[3]), "r"(b[0]), "r"(b[1]));
}

// ==================== bf16 tensor-core GEMM, 128x128x16 double-buffered ====================
// C = A@B + bias, optional relu. A fp32 [M,K] row-major, B fp32 [K,N] row-major.
// N mult of 128, K mult of 16, M guarded.
__global__ __launch_bounds__(256) void bf16gemm_k(
    const float* __restrict__ A, const float* __restrict__ B,
    const float* __restrict__ bias, float* __restrict__ C,
    int M, int N, int K, size_t sA, size_t sC, int act)
{
    __shared__ uint32_t As[2][128][12];   // [row][kpair 8 + pad]
    __shared__ uint32_t Bs[2][128][12];   // [col][kpair 8 + pad]
    A += (size_t)blockIdx.z * sA;
    C += (size_t)blockIdx.z * sC;
    int bm = blockIdx.y * 128, bn = blockIdx.x * 128;
    int tid = threadIdx.x;
    int ar = tid >> 1, ak = (tid & 1) << 3;    // A: row, 8-float k offset
    int aw = (tid & 1) << 2;                   // word base in As row
    int bn0 = (tid & 31) << 2, bkp = tid >> 5; // B: 4 cols, kpair index 0..7
    int wid = tid >> 5, lane = tid & 31;
    int wy = wid >> 2, wx = wid & 3;
    int g = lane >> 2, tg = lane & 3;

    float acc[4][4][4];
#pragma unroll
    for (int mi = 0; mi < 4; mi++)
#pragma unroll
        for (int ni = 0; ni < 4; ni++)
#pragma unroll
            for (int q = 0; q < 4; q++) acc[mi][ni][q] = 0.f;

    int nk = K >> 4;

    // prologue: stage 0 -> buf 0
    {
        int r = bm + ar;
        float4 a0 = make_float4(0.f,0.f,0.f,0.f), a1 = a0;
        if (r < M) {
            a0 = *(const float4*)(A + (size_t)r*K + ak);
            a1 = *(const float4*)(A + (size_t)r*K + ak + 4);
        }
        As[0][ar][aw+0] = pkbf(a0.x, a0.y);
        As[0][ar][aw+1] = pkbf(a0.z, a0.w);
        As[0][ar][aw+2] = pkbf(a1.x, a1.y);
        As[0][ar][aw+3] = pkbf(a1.z, a1.w);
        float4 b0 = *(const float4*)(B + (size_t)(2*bkp  )*N + bn + bn0);
        float4 b1 = *(const float4*)(B + (size_t)(2*bkp+1)*N + bn + bn0);
        Bs[0][bn0+0][bkp] = pkbf(b0.x, b1.x);
        Bs[0][bn0+1][bkp] = pkbf(b0.y, b1.y);
        Bs[0][bn0+2][bkp] = pkbf(b0.z, b1.z);
        Bs[0][bn0+3][bkp] = pkbf(b0.w, b1.w);
    }
    __syncthreads();

    int buf = 0;
    for (int kt = 0; kt < nk; kt++) {
        float4 a0, a1, b0, b1;
        bool pf = (kt + 1 < nk);
        if (pf) {
            int k0 = (kt + 1) << 4;
            int r = bm + ar;
            a0 = make_float4(0.f,0.f,0.f,0.f); a1 = a0;
            if (r < M) {
                a0 = *(const float4*)(A + (size_t)r*K + k0 + ak);
                a1 = *(const float4*)(A + (size_t)r*K + k0 + ak + 4);
            }
            b0 = *(const float4*)(B + (size_t)(k0 + 2*bkp  )*N + bn + bn0);
            b1 = *(const float4*)(B + (size_t)(k0 + 2*bkp+1)*N + bn + bn0);
        }
        uint32_t af[4][4];
#pragma unroll
        for (int mi = 0; mi < 4; mi++) {
            int r0 = wy*64 + mi*16;
            af[mi][0] = As[buf][r0 + g    ][tg];
            af[mi][1] = As[buf][r0 + g + 8][tg];
            af[mi][2] = As[buf][r0 + g    ][tg + 4];
            af[mi][3] = As[buf][r0 + g + 8][tg + 4];
        }
        uint32_t bfr[4][2];
#pragma unroll
        for (int ni = 0; ni < 4; ni++) {
            int c0 = wx*32 + ni*8;
            bfr[ni][0] = Bs[buf][c0 + g][tg];
            bfr[ni][1] = Bs[buf][c0 + g][tg + 4];
        }
#pragma unroll
        for (int mi = 0; mi < 4; mi++)
#pragma unroll
            for (int ni = 0; ni < 4; ni++)
                mma_bf16(acc[mi][ni], af[mi], bfr[ni]);

        if (pf) {
            int nb = buf ^ 1;
            As[nb][ar][aw+0] = pkbf(a0.x, a0.y);
            As[nb][ar][aw+1] = pkbf(a0.z, a0.w);
            As[nb][ar][aw+2] = pkbf(a1.x, a1.y);
            As[nb][ar][aw+3] = pkbf(a1.z, a1.w);
            Bs[nb][bn0+0][bkp] = pkbf(b0.x, b1.x);
            Bs[nb][bn0+1][bkp] = pkbf(b0.y, b1.y);
            Bs[nb][bn0+2][bkp] = pkbf(b0.z, b1.z);
            Bs[nb][bn0+3][bkp] = pkbf(b0.w, b1.w);
        }
        __syncthreads();
        buf ^= 1;
    }

#pragma unroll
    for (int mi = 0; mi < 4; mi++) {
#pragma unroll
        for (int half = 0; half < 2; half++) {
            int r = bm + wy*64 + mi*16 + g + half*8;
            if (r >= M) continue;
#pragma unroll
            for (int ni = 0; ni < 4; ni++) {
                int c = bn + wx*32 + ni*8 + 2*tg;
                float v0 = acc[mi][ni][half*2+0] + (bias ? bias[c]   : 0.f);
                float v1 = acc[mi][ni][half*2+1] + (bias ? bias[c+1] : 0.f);
                if (act == 1) { v0 = fmaxf(v0, 0.f); v1 = fmaxf(v1, 0.f); }
                *(float2*)(C + (size_t)r*N + c) = make_float2(v0, v1);
            }
        }
    }
}

// ==================== tf32 tensor-core GEMM (pinv path), 128x128x8 ====================
__global__ __launch_bounds__(256) void tf32gemm_k(
    const float* __restrict__ A, const float* __restrict__ B,
    float* __restrict__ C, int Kd, size_t sAB,
    float cI, float eB, float sc)
{
    __shared__ uint32_t As[2][8][136];
    __shared__ uint32_t Bs[2][8][136];
    A += (size_t)blockIdx.z * sAB;
    B += (size_t)blockIdx.z * sAB;
    C += (size_t)blockIdx.z * sAB;
    const int N = 256;
    int bm = blockIdx.y * 128, bn = blockIdx.x * 128;
    int tid = threadIdx.x;
    int arow = tid >> 1, acol = (tid & 1) << 2;
    int brow = tid >> 5, bcol = (tid & 31) << 2;
    int wid = tid >> 5, lane = tid & 31;
    int wy = wid >> 2, wx = wid & 3;
    int g = lane >> 2, tg = lane & 3;

    float acc[4][4][4];
#pragma unroll
    for (int mi = 0; mi < 4; mi++)
#pragma unroll
        for (int ni = 0; ni < 4; ni++)
#pragma unroll
            for (int q = 0; q < 4; q++) acc[mi][ni][q] = 0.f;

    int nk = Kd >> 3;
    int col0 = bn + bcol;

    {
        float4 va = *(const float4*)(A + (size_t)(bm + arow)*Kd + acol);
        As[0][acol+0][arow] = f2tf32(va.x);
        As[0][acol+1][arow] = f2tf32(va.y);
        As[0][acol+2][arow] = f2tf32(va.z);
        As[0][acol+3][arow] = f2tf32(va.w);
        float4 vb = *(const float4*)(B + (size_t)brow*N + col0);
        float e0 = eB*vb.x, e1 = eB*vb.y, e2 = eB*vb.z, e3 = eB*vb.w;
        if (brow == col0    ) e0 += cI;
        if (brow == col0 + 1) e1 += cI;
        if (brow == col0 + 2) e2 += cI;
        if (brow == col0 + 3) e3 += cI;
        Bs[0][brow][bcol  ] = f2tf32(e0);
        Bs[0][brow][bcol+1] = f2tf32(e1);
        Bs[0][brow][bcol+2] = f2tf32(e2);
        Bs[0][brow][bcol+3] = f2tf32(e3);
    }
    __syncthreads();

    int buf = 0;
    for (int kt = 0; kt < nk; kt++) {
        float4 va, vb;
        bool pf = (kt + 1 < nk);
        if (pf) {
            int k0 = (kt + 1) << 3;
            va = *(const float4*)(A + (size_t)(bm + arow)*Kd + k0 + acol);
            vb = *(const float4*)(B + (size_t)(k0 + brow)*N + col0);
        }
        uint32_t af[4][4];
#pragma unroll
        for (int mi = 0; mi < 4; mi++) {
            int r0 = wy*64 + mi*16;
            af[mi][0] = As[buf][tg  ][r0 + g];
            af[mi][1] = As[buf][tg  ][r0 + g + 8];
            af[mi][2] = As[buf][tg+4][r0 + g];
            af[mi][3] = As[buf][tg+4][r0 + g + 8];
        }
        uint32_t bfr[4][2];
#pragma unroll
        for (int ni = 0; ni < 4; ni++) {
            int c0 = wx*32 + ni*8;
            bfr[ni][0] = Bs[buf][tg  ][c0 + g];
            bfr[ni][1] = Bs[buf][tg+4][c0 + g];
        }
#pragma unroll
        for (int mi = 0; mi < 4; mi++)
#pragma unroll
            for (int ni = 0; ni < 4; ni++)
                mma_tf32(acc[mi][ni], af[mi], bfr[ni]);

        if (pf) {
            int nb = buf ^ 1;
            int kr = ((kt + 1) << 3) + brow;
            As[nb][acol+0][arow] = f2tf32(va.x);
            As[nb][acol+1][arow] = f2tf32(va.y);
            As[nb][acol+2][arow] = f2tf32(va.z);
            As[nb][acol+3][arow] = f2tf32(va.w);
            float e0 = eB*vb.x, e1 = eB*vb.y, e2 = eB*vb.z, e3 = eB*vb.w;
            if (kr == col0    ) e0 += cI;
            if (kr == col0 + 1) e1 += cI;
            if (kr == col0 + 2) e2 += cI;
            if (kr == col0 + 3) e3 += cI;
            Bs[nb][brow][bcol  ] = f2tf32(e0);
            Bs[nb][brow][bcol+1] = f2tf32(e1);
            Bs[nb][brow][bcol+2] = f2tf32(e2);
            Bs[nb][brow][bcol+3] = f2tf32(e3);
        }
        __syncthreads();
        buf ^= 1;
    }

#pragma unroll
    for (int mi = 0; mi < 4; mi++) {
#pragma unroll
        for (int half = 0; half < 2; half++) {
            int r = bm + wy*64 + mi*16 + g + half*8;
#pragma unroll
            for (int ni = 0; ni < 4; ni++) {
                int c = bn + wx*32 + ni*8 + 2*tg;
                *(float2*)(C + (size_t)r*N + c) =
                    make_float2(sc*acc[mi][ni][half*2+0], sc*acc[mi][ni][half*2+1]);
            }
        }
    }
}

// ==================== fused attention (bf16), 64-wide chunks, ~56KB smem ====================
// words: qs[128][36] @0, Ks[64][36] @4608, Vs[64][36] @6912, Ps[128][36] @9216, rsm @13824
#define SW_QS 0
#define SW_KS 4608
#define SW_VS 6912
#define SW_PS 9216
#define SW_RS 13824
#define SM_FUSED_BYTES ((13824 + 4608 + 128)*4)

// a3: 128 ql rows vs streamed 64-token chunks: acc_o += exp(ql@K^T)@V, fp32 rowsum; atomics out.
__global__ __launch_bounds__(256) void a3_fused_k() {
    extern __shared__ uint32_t sm[];
    uint32_t* qs = sm + SW_QS;
    uint32_t* Ks = sm + SW_KS;
    uint32_t* Vs = sm + SW_VS;
    uint32_t* Ps = sm + SW_PS;
    float* rsm = (float*)(sm + SW_RS);

    int split = blockIdx.x;               // 0..7
    int bm = blockIdx.y * 128;            // ql base
    int z = blockIdx.z; int zb = z / NH, zh = z % NH;
    int tid = threadIdx.x;
    int wid = tid >> 5, lane = tid & 31;
    int wy = wid >> 2, wx = wid & 3;      // mma1 2x4: 64x16 warp tile
    int wy2 = wid >> 1, wx2 = wid & 1;    // mma2 4x2: 32x32 warp tile
    int g = lane >> 2, tg = lane & 3;

    if (tid < 128) rsm[tid] = 0.f;

    // qs[row][dpair]
    for (int i = tid; i < 128*16; i += 256) {
        int row = i >> 4, f4 = (i & 15) << 2;
        float4 v = *(const float4*)(d_ql + ((size_t)(z*ML + bm + row))*DH + f4);
        qs[row*36 + (f4>>1)    ] = pkbf(v.x, v.y);
        qs[row*36 + (f4>>1) + 1] = pkbf(v.z, v.w);
    }

    float acc_o[2][4][4];
#pragma unroll
    for (int a = 0; a < 2; a++)
#pragma unroll
        for (int b = 0; b < 4; b++)
#pragma unroll
            for (int q = 0; q < 4; q++) acc_o[a][b][q] = 0.f;
    float rs_loc[8];
#pragma unroll
    for (int a = 0; a < 8; a++) rs_loc[a] = 0.f;

    for (int ci = 0; ci < 12; ci++) {
        int c0 = split*768 + ci*64;
        // Ks[token][dpair]
        for (int i = tid; i < 64*16; i += 256) {
            int tok = i >> 4, f4 = (i & 15) << 2;
            float4 kv = *(const float4*)(d_qkv + ((size_t)(zb*NP + c0 + tok))*1536 + 512 + zh*64 + f4);
            Ks[tok*36 + (f4>>1)    ] = pkbf(kv.x, kv.y);
            Ks[tok*36 + (f4>>1) + 1] = pkbf(kv.z, kv.w);
        }
        // Vs[d][tokenpair] (transpose-pack)
        for (int i = tid; i < 32*16; i += 256) {
            int tp = i >> 4, f4 = (i & 15) << 2;
            const float* vb0 = d_qkv + ((size_t)(zb*NP + c0 + 2*tp))*1536 + 1024 + zh*64 + f4;
            float4 v0 = *(const float4*)vb0;
            float4 v1 = *(const float4*)(vb0 + 1536);
            Vs[(f4+0)*36 + tp] = pkbf(v0.x, v1.x);
            Vs[(f4+1)*36 + tp] = pkbf(v0.y, v1.y);
            Vs[(f4+2)*36 + tp] = pkbf(v0.z, v1.z);
            Vs[(f4+3)*36 + tp] = pkbf(v0.w, v1.w);
        }
        __syncthreads();

        float acc_s[4][2][4];
#pragma unroll
        for (int a = 0; a < 4; a++)
#pragma unroll
            for (int b = 0; b < 2; b++)
#pragma unroll
                for (int q = 0; q < 4; q++) acc_s[a][b][q] = 0.f;

#pragma unroll
        for (int kk = 0; kk < 4; kk++) {       // d = 64 = 4 x k16
            uint32_t af[4][4], bfr[2][2];
#pragma unroll
            for (int mi = 0; mi < 4; mi++) {
                int r0 = wy*64 + mi*16;
                af[mi][0] = qs[(r0 + g    )*36 + kk*8 + tg];
                af[mi][1] = qs[(r0 + g + 8)*36 + kk*8 + tg];
                af[mi][2] = qs[(r0 + g    )*36 + kk*8 + tg + 4];
                af[mi][3] = qs[(r0 + g + 8)*36 + kk*8 + tg + 4];
            }
#pragma unroll
            for (int ni = 0; ni < 2; ni++) {
                int cw = wx*16 + ni*8;
                bfr[ni][0] = Ks[(cw + g)*36 + kk*8 + tg];
                bfr[ni][1] = Ks[(cw + g)*36 + kk*8 + tg + 4];
            }
#pragma unroll
            for (int mi = 0; mi < 4; mi++)
#pragma unroll
                for (int ni = 0; ni < 2; ni++)
                    mma_bf16(acc_s[mi][ni], af[mi], bfr[ni]);
        }

        // exp epilogue -> Ps[row][tokenpair] (c0,c1 are adjacent cols -> one packed word)
#pragma unroll
        for (int mi = 0; mi < 4; mi++)
#pragma unroll
            for (int half = 0; half < 2; half++) {
                int rl = wy*64 + mi*16 + half*8 + g;
                float ra = 0.f;
#pragma unroll
                for (int ni = 0; ni < 2; ni++) {
                    int cp = wx*8 + ni*4 + tg;     // column pair index
                    float v0 = __expf(acc_s[mi][ni][half*2+0]);
                    float v1 = __expf(acc_s[mi][ni][half*2+1]);
                    Ps[rl*36 + cp] = pkbf(v0, v1);
                    ra += v0 + v1;
                }
                rs_loc[mi*2 + half] += ra;
            }
        __syncthreads();

        // mma2: P(128x64) @ V(64x64)
#pragma unroll
        for (int kk = 0; kk < 4; kk++) {
            uint32_t af2[2][4], bf2[4][2];
#pragma unroll
            for (int mi2 = 0; mi2 < 2; mi2++) {
                int m0 = wy2*32 + mi2*16;
                af2[mi2][0] = Ps[(m0 + g    )*36 + kk*8 + tg];
                af2[mi2][1] = Ps[(m0 + g + 8)*36 + kk*8 + tg];
                af2[mi2][2] = Ps[(m0 + g    )*36 + kk*8 + tg + 4];
                af2[mi2][3] = Ps[(m0 + g + 8)*36 + kk*8 + tg + 4];
            }
#pragma unroll
            for (int ni2 = 0; ni2 < 4; ni2++) {
                int cw = wx2*32 + ni2*8;
                bf2[ni2][0] = Vs[(cw + g)*36 + kk*8 + tg];
                bf2[ni2][1] = Vs[(cw + g)*36 + kk*8 + tg + 4];
            }
#pragma unroll
            for (int mi2 = 0; mi2 < 2; mi2++)
#pragma unroll
                for (int ni2 = 0; ni2 < 4; ni2++)
                    mma_bf16(acc_o[mi2][ni2], af2[mi2], bf2[ni2]);
        }
        __syncthreads();
    }

#pragma unroll
    for (int j2 = 0; j2 < 8; j2++) {
        int rl = wy*64 + (j2>>1)*16 + (j2&1)*8 + g;
        atomicAdd(&rsm[rl], rs_loc[j2]);
    }
    __syncthreads();
    if (tid < 128) atomicAdd(d_rs + (size_t)z*ML + bm + tid, rsm[tid]);
#pragma unroll
    for (int mi2 = 0; mi2 < 2; mi2++)
#pragma unroll
        for (int half = 0; half < 2; half++) {
            int m = wy2*32 + mi2*16 + half*8 + g;
#pragma unroll
            for (int ni2 = 0; ni2 < 4; ni2++) {
                int cc = wx2*32 + ni2*8 + 2*tg;
                float* dst = d_a3v + ((size_t)(z*ML + bm + m))*DH + cc;
                atomicAdd(dst,     acc_o[mi2][ni2][half*2+0]);
                atomicAdd(dst + 1, acc_o[mi2][ni2][half*2+1]);
            }
        }
}

// a1: 128 tokens vs 4 chunks of 64 landmarks: out = (exp(0.125 q@kl^T) @ w2)/rowsum.
__global__ __launch_bounds__(256) void a1_fused_k() {
    extern __shared__ uint32_t sm[];
    uint32_t* qs = sm + SW_QS;
    uint32_t* Ks = sm + SW_KS;
    uint32_t* Vs = sm + SW_VS;
    uint32_t* Ps = sm + SW_PS;
    float* rsm = (float*)(sm + SW_RS);

    int bm = blockIdx.x * 128;    // token base
    int z = blockIdx.y; int zb = z / NH, zh = z % NH;
    int tid = threadIdx.x;
    int wid = tid >> 5, lane = tid & 31;
    int wy = wid >> 2, wx = wid & 3;
    int wy2 = wid >> 1, wx2 = wid & 1;
    int g = lane >> 2, tg = lane & 3;

    if (tid < 128) rsm[tid] = 0.f;

    for (int i = tid; i < 128*16; i += 256) {
        int row = i >> 4, f4 = (i & 15) << 2;
        float4 v = *(const float4*)(d_qkv + ((size_t)(zb*NP + bm + row))*1536 + zh*64 + f4);
        qs[row*36 + (f4>>1)    ] = pkbf(v.x*0.125f, v.y*0.125f);
        qs[row*36 + (f4>>1) + 1] = pkbf(v.z*0.125f, v.w*0.125f);
    }

    float acc_o[2][4][4];
#pragma unroll
    for (int a = 0; a < 2; a++)
#pragma unroll
        for (int b = 0; b < 4; b++)
#pragma unroll
            for (int q = 0; q < 4; q++) acc_o[a][b][q] = 0.f;
    float rs_loc[8];
#pragma unroll
    for (int a = 0; a < 8; a++) rs_loc[a] = 0.f;

    for (int lc = 0; lc < 4; lc++) {
        int base = lc*64;
        for (int i = tid; i < 64*16; i += 256) {
            int lm = i >> 4, f4 = (i & 15) << 2;
            float4 kv = *(const float4*)(d_kl + ((size_t)(z*ML + base + lm))*DH + f4);
            Ks[lm*36 + (f4>>1)    ] = pkbf(kv.x, kv.y);
            Ks[lm*36 + (f4>>1) + 1] = pkbf(kv.z, kv.w);
        }
        for (int i = tid; i < 32*16; i += 256) {
            int lp = i >> 4, f4 = (i & 15) << 2;
            const float* wb0 = d_w2 + ((size_t)(z*ML + base + 2*lp))*DH + f4;
            float4 w0 = *(const float4*)wb0;
            float4 w1 = *(const float4*)(wb0 + DH);
            Vs[(f4+0)*36 + lp] = pkbf(w0.x, w1.x);
            Vs[(f4+1)*36 + lp] = pkbf(w0.y, w1.y);
            Vs[(f4+2)*36 + lp] = pkbf(w0.z, w1.z);
            Vs[(f4+3)*36 + lp] = pkbf(w0.w, w1.w);
        }
        __syncthreads();

        float acc_s[4][2][4];
#pragma unroll
        for (int a = 0; a < 4; a++)
#pragma unroll
            for (int b = 0; b < 2; b++)
#pragma unroll
                for (int q = 0; q < 4; q++) acc_s[a][b][q] = 0.f;

#pragma unroll
        for (int kk = 0; kk < 4; kk++) {
            uint32_t af[4][4], bfr[2][2];
#pragma unroll
            for (int mi = 0; mi < 4; mi++) {
                int r0 = wy*64 + mi*16;
                af[mi][0] = qs[(r0 + g    )*36 + kk*8 + tg];
                af[mi][1] = qs[(r0 + g + 8)*36 + kk*8 + tg];
                af[mi][2] = qs[(r0 + g    )*36 + kk*8 + tg + 4];
                af[mi][3] = qs[(r0 + g + 8)*36 + kk*8 + tg + 4];
            }
#pragma unroll
            for (int ni = 0; ni < 2; ni++) {
                int cw = wx*16 + ni*8;
                bfr[ni][0] = Ks[(cw + g)*36 + kk*8 + tg];
                bfr[ni][1] = Ks[(cw + g)*36 + kk*8 + tg + 4];
            }
#pragma unroll
            for (int mi = 0; mi < 4; mi++)
#pragma unroll
                for (int ni = 0; ni < 2; ni++)
                    mma_bf16(acc_s[mi][ni], af[mi], bfr[ni]);
        }

#pragma unroll
        for (int mi = 0; mi < 4; mi++)
#pragma unroll
            for (int half = 0; half < 2; half++) {
                int rl = wy*64 + mi*16 + half*8 + g;
                float ra = 0.f;
#pragma unroll
                for (int ni = 0; ni < 2; ni++) {
                    int cp = wx*8 + ni*4 + tg;
                    float v0 = __expf(acc_s[mi][ni][half*2+0]);
                    float v1 = __expf(acc_s[mi][ni][half*2+1]);
                    Ps[rl*36 + cp] = pkbf(v0, v1);
                    ra += v0 + v1;
                }
                rs_loc[mi*2 + half] += ra;
            }
        __syncthreads();

#pragma unroll
        for (int kk = 0; kk < 4; kk++) {
            uint32_t af2[2][4], bf2[4][2];
#pragma unroll
            for (int mi2 = 0; mi2 < 2; mi2++) {
                int m0 = wy2*32 + mi2*16;
                af2[mi2][0] = Ps[(m0 + g    )*36 + kk*8 + tg];
                af2[mi2][1] = Ps[(m0 + g + 8)*36 + kk*8 + tg];
                af2[mi2][2] = Ps[(m0 + g    )*36 + kk*8 + tg + 4];
                af2[mi2][3] = Ps[(m0 + g + 8)*36 + kk*8 + tg + 4];
            }
#pragma unroll
            for (int ni2 = 0; ni2 < 4; ni2++) {
                int cw = wx2*32 + ni2*8;
                bf2[ni2][0] = Vs[(cw + g)*36 + kk*8 + tg];
                bf2[ni2][1] = Vs[(cw + g)*36 + kk*8 + tg + 4];
            }
#pragma unroll
            for (int mi2 = 0; mi2 < 2; mi2++)
#pragma unroll
                for (int ni2 = 0; ni2 < 4; ni2++)
                    mma_bf16(acc_o[mi2][ni2], af2[mi2], bf2[ni2]);
        }
        __syncthreads();
    }

#pragma unroll
    for (int j2 = 0; j2 < 8; j2++) {
        int rl = wy*64 + (j2>>1)*16 + (j2&1)*8 + g;
        atomicAdd(&rsm[rl], rs_loc[j2]);
    }
    __syncthreads();
#pragma unroll
    for (int mi2 = 0; mi2 < 2; mi2++)
#pragma unroll
        for (int half = 0; half < 2; half++) {
            int m = wy2*32 + mi2*16 + half*8 + g;
            float inv = 1.f / rsm[m];
#pragma unroll
            for (int ni2 = 0; ni2 < 4; ni2++) {
                int cc = wx2*32 + ni2*8 + 2*tg;
                *(float2*)(d_attn + ((size_t)(zb*NP + bm + m))*EMBD + zh*64 + cc) =
                    make_float2(acc_o[mi2][ni2][half*2+0]*inv, acc_o[mi2][ni2][half*2+1]*inv);
            }
        }
}

// -------------------- small 64-tile batched GEMM (fp32) with optional B row-scale --------------------
__global__ __launch_bounds__(256) void bgemm_epi(
    const float* __restrict__ A, const float* __restrict__ Bm, float* __restrict__ C,
    int Md, int Nd, int Kd, float cI, float eB, float s, const float* __restrict__ rsc)
{
    __shared__ float As[16][64];
    __shared__ float Bs[16][64];
    A  += (size_t)blockIdx.z * Md * Kd;
    Bm += (size_t)blockIdx.z * Kd * Nd;
    C  += (size_t)blockIdx.z * Md * Nd;
    const float* rscz = rsc ? rsc + (size_t)blockIdx.z * Kd : nullptr;
    int bm = blockIdx.y * 64, bn = blockIdx.x * 64;
    int tid = threadIdx.x;
    int la_r = tid >> 2, la_c = (tid & 3) << 2;
    int lb_r = tid >> 4, lb_c = (tid & 15) << 2;
    int ty = tid >> 4, tx = tid & 15;
    float acc[4][4];
#pragma unroll
    for (int i = 0; i < 4; i++)
#pragma unroll
        for (int j = 0; j < 4; j++) acc[i][j] = 0.f;

    for (int k0 = 0; k0 < Kd; k0 += 16) {
        float4 av = *(const float4*)(A + (size_t)(bm + la_r)*Kd + k0 + la_c);
        As[la_c  ][la_r] = av.x;
        As[la_c+1][la_r] = av.y;
        As[la_c+2][la_r] = av.z;
        As[la_c+3][la_r] = av.w;
        int kr = k0 + lb_r;
        float4 bv = *(const float4*)(Bm + (size_t)kr*Nd + bn + lb_c);
        float rsv = rscz ? (1.f / rscz[kr]) : 1.f;
        float e0 = eB*rsv*bv.x, e1 = eB*rsv*bv.y, e2 = eB*rsv*bv.z, e3 = eB*rsv*bv.w;
        int c0 = bn + lb_c;
        if (kr == c0    ) e0 += cI;
        if (kr == c0 + 1) e1 += cI;
        if (kr == c0 + 2) e2 += cI;
        if (kr == c0 + 3) e3 += cI;
        Bs[lb_r][lb_c  ] = e0;
        Bs[lb_r][lb_c+1] = e1;
        Bs[lb_r][lb_c+2] = e2;
        Bs[lb_r][lb_c+3] = e3;
        __syncthreads();
#pragma unroll
        for (int kk = 0; kk < 16; kk++) {
            float a0 = As[kk][ty*4+0], a1 = As[kk][ty*4+1], a2 = As[kk][ty*4+2], a3 = As[kk][ty*4+3];
            float b0 = Bs[kk][tx*4+0], b1 = Bs[kk][tx*4+1], b2 = Bs[kk][tx*4+2], b3 = Bs[kk][tx*4+3];
            acc[0][0]+=a0*b0; acc[0][1]+=a0*b1; acc[0][2]+=a0*b2; acc[0][3]+=a0*b3;
            acc[1][0]+=a1*b0; acc[1][1]+=a1*b1; acc[1][2]+=a1*b2; acc[1][3]+=a1*b3;
            acc[2][0]+=a2*b0; acc[2][1]+=a2*b1; acc[2][2]+=a2*b2; acc[2][3]+=a2*b3;
            acc[3][0]+=a3*b0; acc[3][1]+=a3*b1; acc[3][2]+=a3*b2; acc[3][3]+=a3*b3;
        }
        __syncthreads();
    }
#pragma unroll
    for (int i = 0; i < 4; i++) {
        int r = bm + ty*4 + i;
#pragma unroll
        for (int j = 0; j < 4; j++) {
            int c = bn + tx*4 + j;
            C[(size_t)r*Nd + c] = s * acc[i][j];
        }
    }
}

// -------------------- misc small kernels --------------------
__global__ void fill_cls_k(const float* __restrict__ cls) {
    int i = blockIdx.x*256 + threadIdx.x;
    if (i < BB*EMBD) d_h[(size_t)(i/EMBD)*NT*EMBD + (i % EMBD)] = cls[i % EMBD];
}

__global__ void fill_wrap_k() {
    int i = blockIdx.x*256 + threadIdx.x;
    if (i >= BB*ADDW*EMBD) return;
    int c = i % EMBD; int r = i / EMBD; int j = r % ADDW; int b = r / ADDW;
    d_h[((size_t)(b*NT + 1 + N0 + j))*EMBD + c] = d_h[((size_t)(b*NT + 1 + j))*EMBD + c];
}

__global__ __launch_bounds__(256) void ln_pad_k(const float* __restrict__ g, const float* __restrict__ bp) {
    int row = blockIdx.x; int b = row / NP; int t = row % NP;
    int tid = threadIdx.x;
    float* out = d_xn + (size_t)row*EMBD;
    if (t < PADT) { out[tid] = 0.f; out[tid+256] = 0.f; return; }
    const float* x = d_h + ((size_t)b*NT + (t - PADT))*EMBD;
    float v0 = x[tid], v1 = x[tid+256];
    __shared__ float red[256];
    red[tid] = v0 + v1; __syncthreads();
    for (int o = 128; o > 0; o >>= 1) { if (tid < o) red[tid] += red[tid+o]; __syncthreads(); }
    float mean = red[0] * (1.f/512.f); __syncthreads();
    float e0 = v0 - mean, e1 = v1 - mean;
    red[tid] = e0*e0 + e1*e1; __syncthreads();
    for (int o = 128; o > 0; o >>= 1) { if (tid < o) red[tid] += red[tid+o]; __syncthreads(); }
    float inv = rsqrtf(red[0] * (1.f/512.f) + 1e-5f);
    out[tid]     = e0*inv*g[tid]     + bp[tid];
    out[tid+256] = e1*inv*g[tid+256] + bp[tid+256];
}

__global__ void landmarks_k() {
    int blk = blockIdx.x; int bh = blk >> 8; int i = blk & 255;
    int d = threadIdx.x;  // 64 threads
    int b = bh / NH, h = bh % NH;
    const float* base = d_qkv + ((size_t)(b*NP) + (size_t)i*LWIN)*1536 + h*64 + d;
    float sq = 0.f, sk = 0.f;
#pragma unroll
    for (int j = 0; j < LWIN; j++) { sq += base[(size_t)j*1536]; sk += base[(size_t)j*1536 + 512]; }
    d_ql[((size_t)(bh*ML + i))*DH + d] = sq * (0.125f / LWIN);
    d_kl[((size_t)(bh*ML + i))*DH + d] = sk * (1.f   / LWIN);
}

__global__ __launch_bounds__(256) void a2_k() {
    int blk = blockIdx.x; int bh = blk >> 8; int i = blk & 255;
    int tid = threadIdx.x;
    __shared__ float sq[64];
    __shared__ float red[256];
    if (tid < 64) sq[tid] = d_ql[((size_t)(bh*ML + i))*DH + tid];
    __syncthreads();
    float s = dot64(sq, d_kl + ((size_t)(bh*ML + tid))*DH);
    red[tid] = s; __syncthreads();
    for (int o = 128; o > 0; o >>= 1) { if (tid < o) red[tid] = fmaxf(red[tid], red[tid+o]); __syncthreads(); }
    float m = red[0]; __syncthreads();
    float p = expf(s - m);
    red[tid] = p; __syncthreads();
    for (int o = 128; o > 0; o >>= 1) { if (tid < o) red[tid] += red[tid+o]; __syncthreads(); }
    float Z = red[0];
    d_a2[((size_t)bh << 16) + ((size_t)i << 8) + tid] = p / Z;
}

__global__ void reset_mx_k() { d_mx[0] = 0.f; d_mx[1] = 0.f; }

__global__ __launch_bounds__(256) void a2_stats_k() {
    int bh = blockIdx.x; int tid = threadIdx.x;
    const float* a = d_a2 + ((size_t)bh << 16);
    float cs = 0.f, rs = 0.f;
    for (int i = 0; i < ML; i++) cs += a[(size_t)i*ML + tid];
    for (int j = 0; j < ML; j++) rs += a[(size_t)tid*ML + j];
    __shared__ float red[256];
    red[tid] = cs; __syncthreads();
    for (int o = 128; o > 0; o >>= 1) { if (tid < o) red[tid] = fmaxf(red[tid], red[tid+o]); __syncthreads(); }
    if (tid == 0) atomicMax((int*)&d_mx[1], __float_as_int(red[0]));
    __syncthreads();
    red[tid] = rs; __syncthreads();
    for (int o = 128; o > 0; o >>= 1) { if (tid < o) red[tid] = fmaxf(red[tid], red[tid+o]); __syncthreads(); }
    if (tid == 0) atomicMax((int*)&d_mx[0], __float_as_int(red[0]));
}

__global__ void z_init_k() {
    size_t idx = (size_t)blockIdx.x*256 + threadIdx.x;
    if (idx >= (size_t)BH*ML*ML) return;
    size_t bh = idx >> 16; size_t r = (idx >> 8) & 255; size_t c = idx & 255;
    float denom = d_mx[0] * d_mx[1];
    d_z0[idx] = d_a2[(bh << 16) + (c << 8) + r] / denom;
}

// conv residual with smem tiling: block = (b, h, 128-token strip)
__global__ __launch_bounds__(256) void conv_res_k(const float* __restrict__ w) {
    __shared__ float vs[160*64];
    __shared__ float ws[33];
    int blk = blockIdx.x;
    int strip = blk % 48; int bh = blk / 48; int h = bh % NH; int b = bh / NH;
    int t0 = strip * 128;
    int tid = threadIdx.x;
    if (tid < 33) ws[tid] = w[h*33 + tid];
    for (int i = tid; i < 160*16; i += 256) {
        int row = i >> 4, f4 = (i & 15) << 2;
        int t = t0 - 16 + row;
        float4 v = make_float4(0.f,0.f,0.f,0.f);
        if (t >= 0 && t < NP)
            v = *(const float4*)(d_qkv + ((size_t)(b*NP + t))*1536 + 1024 + h*64 + f4);
        *(float4*)(vs + row*64 + f4) = v;
    }
    __syncthreads();
#pragma unroll
    for (int j = 0; j < 8; j++) {
        int o = tid + j*256;
        int row = o >> 4, f4 = (o & 15) << 2;
        float4 s = make_float4(0.f,0.f,0.f,0.f);
#pragma unroll
        for (int k = 0; k < 33; k++) {
            float4 v = *(const float4*)(vs + (row + k)*64 + f4);
            float wk = ws[k];
            s.x += v.x*wk; s.y += v.y*wk; s.z += v.z*wk; s.w += v.w*wk;
        }
        float4* dst = (float4*)(d_attn + ((size_t)(b*NP + t0 + row))*EMBD + h*64 + f4);
        float4 cur = *dst;
        cur.x += s.x; cur.y += s.y; cur.z += s.z; cur.w += s.w;
        *dst = cur;
    }
}

__global__ void add_res_k() {
    size_t idx = (size_t)blockIdx.x*256 + threadIdx.x;
    if (idx >= (size_t)BB*NT*EMBD) return;
    int c = idx % EMBD; size_t r = idx / EMBD; int t = r % NT; int b = (int)(r / NT);
    d_h[idx] += d_xn[((size_t)(b*NP + t + PADT))*EMBD + c];
}

// weight transpose for PPEG: [c][tap] -> [tap][c]
__global__ void wtrans_k(const float* __restrict__ w7, const float* __restrict__ w5,
                         const float* __restrict__ w3) {
    int i = blockIdx.x*256 + threadIdx.x;
    if (i < 49*EMBD) { int c = i / 49, t = i % 49; d_w7t[t*EMBD + c] = w7[i]; }
    if (i < 25*EMBD) { int c = i / 25, t = i % 25; d_w5t[t*EMBD + c] = w5[i]; }
    if (i < 9*EMBD)  { int c = i / 9,  t = i % 9;  d_w3t[t*EMBD + c] = w3[i]; }
}

__global__ __launch_bounds__(128) void ppeg2_k(
    const float* __restrict__ b7, const float* __restrict__ b5, const float* __restrict__ b3)
{
    int blk = blockIdx.x; int b = blk / NPIX; int pix = blk % NPIX;
    int i = pix / HW, j = pix % HW;
    int c = threadIdx.x << 2;
    const float* hbase = d_h + ((size_t)(b*NT + 1))*EMBD + c;
    float4 s = *(const float4*)(hbase + (size_t)pix*EMBD);
    {
        float4 x7 = *(const float4*)(b7 + c);
        float4 x5 = *(const float4*)(b5 + c);
        float4 x3 = *(const float4*)(b3 + c);
        s.x += x7.x + x5.x + x3.x; s.y += x7.y + x5.y + x3.y;
        s.z += x7.z + x5.z + x3.z; s.w += x7.w + x5.w + x3.w;
    }
#pragma unroll
    for (int a = 0; a < 7; a++) {
        int ii = i - 3 + a; if (ii < 0 || ii >= HW) continue;
#pragma unroll
        for (int q = 0; q < 7; q++) {
            int jj = j - 3 + q; if (jj < 0 || jj >= HW) continue;
            float4 x = *(const float4*)(hbase + (size_t)(ii*HW + jj)*EMBD);
            float4 w = *(const float4*)(d_w7t + (a*7 + q)*EMBD + c);
            s.x += x.x*w.x; s.y += x.y*w.y; s.z += x.z*w.z; s.w += x.w*w.w;
        }
    }
#pragma unroll
    for (int a = 0; a < 5; a++) {
        int ii = i - 2 + a; if (ii < 0 || ii >= HW) continue;
#pragma unroll
        for (int q = 0; q < 5; q++) {
            int jj = j - 2 + q; if (jj < 0 || jj >= HW) continue;
            float4 x = *(const float4*)(hbase + (size_t)(ii*HW + jj)*EMBD);
            float4 w = *(const float4*)(d_w5t + (a*5 + q)*EMBD + c);
            s.x += x.x*w.x; s.y += x.y*w.y; s.z += x.z*w.z; s.w += x.w*w.w;
        }
    }
#pragma unroll
    for (int a = 0; a < 3; a++) {
        int ii = i - 1 + a; if (ii < 0 || ii >= HW) continue;
#pragma unroll
        for (int q = 0; q < 3; q++) {
            int jj = j - 1 + q; if (jj < 0 || jj >= HW) continue;
            float4 x = *(const float4*)(hbase + (size_t)(ii*HW + jj)*EMBD);
            float4 w = *(const float4*)(d_w3t + (a*3 + q)*EMBD + c);
            s.x += x.x*w.x; s.y += x.y*w.y; s.z += x.z*w.z; s.w += x.w*w.w;
        }
    }
    *(float4*)(d_xn + ((size_t)(b*NPIX + pix))*EMBD + c) = s;
}

__global__ void ppeg_copy_k() {
    size_t idx = (size_t)blockIdx.x*256 + threadIdx.x;
    if (idx >= (size_t)BB*NPIX*EMBD) return;
    int c = idx % EMBD; size_t r = idx / EMBD; int pix = r % NPIX; int b = (int)(r / NPIX);
    d_h[((size_t)(b*NT + 1 + pix))*EMBD + c] = d_xn[idx];
}

__global__ __launch_bounds__(256) void head_k(
    const float* __restrict__ g, const float* __restrict__ bp,
    const float* __restrict__ w, const float* __restrict__ bias, float* __restrict__ out)
{
    int b = blockIdx.x; int tid = threadIdx.x;
    __shared__ float xs[512];
    __shared__ float red[256];
    __shared__ float lg[4];
    const float* x = d_h + (size_t)b*NT*EMBD;
    float v0 = x[tid], v1 = x[tid+256];
    red[tid] = v0 + v1; __syncthreads();
    for (int o = 128; o > 0; o >>= 1) { if (tid < o) red[tid] += red[tid+o]; __syncthreads(); }
    float mean = red[0] * (1.f/512.f); __syncthreads();
    float e0 = v0 - mean, e1 = v1 - mean;
    red[tid] = e0*e0 + e1*e1; __syncthreads();
    for (int o = 128; o > 0; o >>= 1) { if (tid < o) red[tid] += red[tid+o]; __syncthreads(); }
    float inv = rsqrtf(red[0] * (1.f/512.f) + 1e-5f);
    xs[tid]     = e0*inv*g[tid]     + bp[tid];
    xs[tid+256] = e1*inv*g[tid+256] + bp[tid+256];
    __syncthreads();
    if (tid < 4) {
        float s = bias[tid];
        for (int k = 0; k < 512; k++) s += xs[k]*w[k*4 + tid];
        lg[tid] = s;
    }
    __syncthreads();
    if (tid == 0) {
        int best = 0; float bv = lg[0];
        for (int k = 1; k < 4; k++) if (lg[k] > bv) { bv = lg[k]; best = k; }
        float S = 1.f;
        for (int k = 0; k < 4; k++) {
            float hz = 1.f / (1.f + expf(-lg[k]));
            out[b*4 + k] = hz;
            S *= (1.f - hz);
            out[16 + b*4 + k] = S;
        }
        out[32 + b] = (float)best;
    }
}

// -------------------- host orchestration --------------------
static float* symaddr(const void* sym) { void* p = nullptr; cudaGetSymbolAddress(&p, sym); return (float*)p; }

static void attn_layer(const float* lng, const float* lnb, const float* qkvw,
                       const float* outw, const float* outb, const float* resw)
{
    float* xnp   = symaddr(d_xn);
    float* qkvp  = symaddr(d_qkv);
    float* attnp = symaddr(d_attn);
    float* a2p   = symaddr(d_a2);
    float* z0p   = symaddr(d_z0);
    float* z1p   = symaddr(d_z1);
    float* t0p   = symaddr(d_t0);
    float* t1p   = symaddr(d_t1);
    float* t2p   = symaddr(d_t2);
    float* a3vp  = symaddr(d_a3v);
    float* w2p   = symaddr(d_w2);
    float* rsp   = symaddr(d_rs);

    ln_pad_k<<<BB*NP, 256>>>(lng, lnb);
    bf16gemm_k<<<dim3(1536/128, NP/128, BB), 256>>>(
        xnp, qkvw, nullptr, qkvp, NP, 1536, EMBD,
        (size_t)NP*EMBD, (size_t)NP*1536, 0);
    landmarks_k<<<BH*ML, 64>>>();
    a2_k<<<BH*ML, 256>>>();
    reset_mx_k<<<1, 1>>>();
    a2_stats_k<<<BH, 256>>>();
    z_init_k<<<(BH*ML*ML + 255)/256, 256>>>();

    const size_t SB = (size_t)ML*ML;
    float* zin = z0p; float* zout = z1p;
    for (int it = 0; it < 6; it++) {
        tf32gemm_k<<<dim3(2, 2, BH), 256>>>(a2p, zin, t0p, 256, SB, 0.f,  1.f, 1.f);
        tf32gemm_k<<<dim3(2, 2, BH), 256>>>(t0p, t0p, t1p, 256, SB, 7.f, -1.f, 1.f);
        tf32gemm_k<<<dim3(2, 2, BH), 256>>>(t0p, t1p, t2p, 256, SB, 15.f,-1.f, 1.f);
        tf32gemm_k<<<dim3(2, 2, BH), 256>>>(zin, t2p, zout,256, SB, 13.f,-1.f, 0.25f);
        float* tmp = zin; zin = zout; zout = tmp;
    }
    // zin holds a2_inv (d_z0)

    // ---- a3 path fused (bf16) ----
    cudaMemsetAsync(rsp, 0, (size_t)BH*ML*sizeof(float));
    cudaMemsetAsync(a3vp, 0, (size_t)BH*ML*DH*sizeof(float));
    a3_fused_k<<<dim3(8, 2, BH), 256, SM_FUSED_BYTES>>>();
    // w2 = a2_inv @ (a3v / rowsum)   (fp32)
    bgemm_epi<<<dim3(1, 4, BH), 256>>>(zin, a3vp, w2p, 256, 64, 256, 0.f, 1.f, 1.f, rsp);

    // ---- a1 path fused (bf16) ----
    a1_fused_k<<<dim3(NP/128, BH), 256, SM_FUSED_BYTES>>>();

    conv_res_k<<<BB*NH*48, 256>>>(resw);
    bf16gemm_k<<<dim3(EMBD/128, NP/128, BB), 256>>>(
        attnp, outw, outb, xnp, NP, EMBD, EMBD,
        (size_t)NP*EMBD, (size_t)NP*EMBD, 0);
    add_res_k<<<(int)(((size_t)BB*NT*EMBD + 255)/256), 256>>>();
}

extern "C" void kernel_launch(void* const* d_in, const int* in_sizes, int n_in,
                              void* d_out, int out_size)
{
    (void)in_sizes; (void)n_in; (void)out_size;
    const float* x_path = (const float*)d_in[0];
    const float* fc1_w  = (const float*)d_in[1];
    const float* fc1_b  = (const float*)d_in[2];
    const float* cls    = (const float*)d_in[3];
    const float* ln1g   = (const float*)d_in[4];
    const float* ln1b   = (const float*)d_in[5];
    const float* qkv1w  = (const float*)d_in[6];
    const float* out1w  = (const float*)d_in[7];
    const float* out1b  = (const float*)d_in[8];
    const float* res1w  = (const float*)d_in[9];
    const float* ln2g   = (const float*)d_in[10];
    const float* ln2b   = (const float*)d_in[11];
    const float* qkv2w  = (const float*)d_in[12];
    const float* out2w  = (const float*)d_in[13];
    const float* out2b  = (const float*)d_in[14];
    const float* res2w  = (const float*)d_in[15];
    const float* c7w    = (const float*)d_in[16];
    const float* c7b    = (const float*)d_in[17];
    const float* c5w    = (const float*)d_in[18];
    const float* c5b    = (const float*)d_in[19];
    const float* c3w    = (const float*)d_in[20];
    const float* c3b    = (const float*)d_in[21];
    const float* ng     = (const float*)d_in[22];
    const float* nb     = (const float*)d_in[23];
    const float* fc2w   = (const float*)d_in[24];
    const float* fc2b   = (const float*)d_in[25];
    float* out = (float*)d_out;

    static int smem_cfg = 0;
    if (!smem_cfg) {
        cudaFuncSetAttribute(a3_fused_k, cudaFuncAttributeMaxDynamicSharedMemorySize, SM_FUSED_BYTES);
        cudaFuncSetAttribute(a1_fused_k, cudaFuncAttributeMaxDynamicSharedMemorySize, SM_FUSED_BYTES);
        smem_cfg = 1;
    }

    float* hp = symaddr(d_h);

    bf16gemm_k<<<dim3(EMBD/128, (N0 + 127)/128, BB), 256>>>(
        x_path, fc1_w, fc1_b, hp + EMBD, N0, EMBD, 1024,
        (size_t)N0*1024, (size_t)NT*EMBD, 1);
    fill_cls_k<<<(BB*EMBD + 255)/256, 256>>>(cls);
    fill_wrap_k<<<(BB*ADDW*EMBD + 255)/256, 256>>>();
    wtrans_k<<<(49*EMBD + 255)/256, 256>>>(c7w, c5w, c3w);

    attn_layer(ln1g, ln1b, qkv1w, out1w, out1b, res1w);

    ppeg2_k<<<BB*NPIX, 128>>>(c7b, c5b, c3b);
    ppeg_copy_k<<<(int)(((size_t)BB*NPIX*EMBD + 255)/256), 256>>>();

    attn_layer(ln2g, ln2b, qkv2w, out2w, out2b, res2w);

    head_k<<<BB, 256>>>(ng, nb, fc2w, fc2b, out);
}